// round 11
// baseline (speedup 1.0000x reference)
#include <cuda_runtime.h>
#include <math.h>

#define NROW 131072            /* B*T*H*W */
#define BSTR 6291456           /* T*H*W*C */
#define TSTR 393216            /* H*W*C   */

__device__ float g_buf0[NROW * 96];
__device__ float g_buf1[NROW * 96];
__device__ float g_buf2[NROW * 96];
__device__ float g_buf3[NROW * 96];
__device__ float g_A [65536 * 96];
__device__ float g_Bc[65536 * 96];
__device__ float g_c64 [4096];     // [n][x]
__device__ float g_c64T[4096];     // [x][n]
__device__ float g_c16 [256];      // [n][x]
__device__ float g_c16T[256];      // [x][n]
__device__ float g_lwT[96 * 192];
__device__ float g_twT[96 * 96];
__device__ float g_vwT[96 * 96];
__device__ float g_owT[96 * 96];

// packed dual-fp32 FMA (FFMA2) — 2 FMAs per issue slot, exact fp32 rounding
__device__ __forceinline__ float2 ffma2(float2 a, float2 b, float2 c) {
    float2 d;
    asm("fma.rn.f32x2 %0, %1, %2, %3;"
        : "=l"(reinterpret_cast<unsigned long long&>(d))
        : "l"(reinterpret_cast<unsigned long long&>(a)),
          "l"(reinterpret_cast<unsigned long long&>(b)),
          "l"(reinterpret_cast<unsigned long long&>(c)));
    return d;
}

// ---------------- cosine basis init (idempotent) -----------------------------
__global__ void __launch_bounds__(256) k_cosinit() {
    int tid = threadIdx.x;
    const float PI = 3.14159265358979323846f;
    for (int i = tid; i < 4096; i += 256) {
        int n = i >> 6, xx = i & 63;
        float v = cosf((float)n * ((float)xx + 0.5f) * (PI / 64.0f)) * 0.17677669529663687f;
        if (n == 0) v *= 0.70710678118654752f;
        g_c64[n * 64 + xx] = v;
        g_c64T[xx * 64 + n] = v;
    }
    for (int i = tid; i < 256; i += 256) {
        int n = i >> 4, xx = i & 15;
        float v = cosf((float)n * ((float)xx + 0.5f) * (PI / 16.0f)) * 0.35355339059327373f;
        if (n == 0) v *= 0.70710678118654752f;
        g_c16[n * 16 + xx] = v;
        g_c16T[xx * 16 + n] = v;
    }
}

// ---------------- weight pre-transpose to k-major ----------------------------
__global__ void __launch_bounds__(256) k_prepw(const float* __restrict__ lw,
                                               const float* __restrict__ tw,
                                               const float* __restrict__ vw,
                                               const float* __restrict__ ow) {
    int i = blockIdx.x * 256 + threadIdx.x;
    if (i < 18432) {
        int cc = i / 96, k = i - cc * 96;
        g_lwT[k * 192 + cc] = lw[i];
    } else if (i < 27648) {
        int j = i - 18432; int cc = j / 96, k = j - cc * 96;
        g_twT[k * 96 + cc] = tw[j];
    } else if (i < 36864) {
        int j = i - 27648; int cc = j / 96, k = j - cc * 96;
        g_vwT[k * 96 + cc] = vw[j];
    } else if (i < 46080) {
        int j = i - 36864; int cc = j / 96, k = j - cc * 96;
        g_owT[k * 96 + cc] = ow[j];
    }
}

// ------ depthwise 3x3x3 conv, 4 t-planes per block: x -> buf0[B,C,T,H,W] ----
__global__ void __launch_bounds__(256) k_conv(const float* __restrict__ x,
                                              const float* __restrict__ wt,
                                              const float* __restrict__ bs) {
    extern __shared__ float xs[];          // [6][34][66] = 13464
    int htile = blockIdx.x, tg = blockIdx.y, bc = blockIdx.z;
    int c = bc % 96;
    int tid = threadIdx.x;
    int h0 = htile * 32;
    for (int i = tid; i < 6 * 34 * 66; i += 256) {
        int p = i / 2244, rem = i - p * 2244;
        int hh = rem / 66, ww = rem - hh * 66;
        int th = tg * 4 - 1 + p, gh = h0 + hh - 1, gw = ww - 1;
        float v = 0.f;
        if ((unsigned)th < 16u && (unsigned)gh < 64u && (unsigned)gw < 64u)
            v = x[(bc * 16 + th) * 4096 + gh * 64 + gw];
        xs[i] = v;
    }
    float wr[27];
#pragma unroll
    for (int j = 0; j < 27; j++) wr[j] = wt[c * 27 + j];
    float bv = bs[c];
    __syncthreads();
    int wd = tid & 63, ht = tid >> 6;
#pragma unroll
    for (int tt = 0; tt < 4; tt++) {
#pragma unroll
        for (int j = 0; j < 8; j++) {
            int l = ht + j * 4;
            float acc = bv;
#pragma unroll
            for (int dt = 0; dt < 3; dt++)
#pragma unroll
                for (int dh = 0; dh < 3; dh++)
#pragma unroll
                    for (int dw = 0; dw < 3; dw++)
                        acc += wr[dt * 9 + dh * 3 + dw] *
                               xs[(tt + dt) * 2244 + (l + dh) * 66 + wd + dw];
            g_buf0[(bc * 16 + tg * 4 + tt) * 4096 + (h0 + l) * 64 + wd] = acc;
        }
    }
}

// ---- fused linear: z->silu->buf2, xg->bias->DCT_W(sym)->buf1 ---------------
__global__ void __launch_bounds__(512, 2) k_lin(const float* __restrict__ lb) {
    extern __shared__ float sm[];
    float* xs = sm;              // [96][132]=12672; phase3 reused as yx[128][98]
    float* ws = sm + 12672;      // [96][98] = 9408; phase3 reused as cfk[32][68]
    int tid = threadIdx.x;
    int r0 = blockIdx.x * 128;
    int b = r0 >> 16, thw0 = r0 & 65535;
    for (int i = tid; i < 12288; i += 512) {
        int k = i >> 7, r = i & 127;
        xs[k * 132 + r] = g_buf0[(b * 96 + k) * 65536 + thw0 + r];
    }
    for (int i = tid; i < 9216; i += 512) {
        int k = i / 96, cc = i - k * 96;
        ws[k * 98 + cc] = g_lwT[k * 192 + 96 + cc];   // z half first
    }
    __syncthreads();
    int ct = tid & 15, rt = tid >> 4;        // rt 0..31
    int rr0 = rt * 4, cc0 = 2 * ct;
    // ---- phase 1: z GEMM + silu ----
    {
        float2 bv[3];
#pragma unroll
        for (int j = 0; j < 3; j++) bv[j] = *(const float2*)&lb[96 + cc0 + 32 * j];
        float2 acc[4][3];
#pragma unroll
        for (int i = 0; i < 4; i++)
#pragma unroll
            for (int j = 0; j < 3; j++) acc[i][j] = make_float2(0.f, 0.f);
#pragma unroll 4
        for (int k = 0; k < 96; k++) {
            float2 wv[3];
#pragma unroll
            for (int j = 0; j < 3; j++) wv[j] = *(const float2*)&ws[k * 98 + cc0 + 32 * j];
            float4 xq = *(const float4*)&xs[k * 132 + rr0];
            float xr[4] = {xq.x, xq.y, xq.z, xq.w};
#pragma unroll
            for (int i = 0; i < 4; i++) {
                float2 xv = make_float2(xr[i], xr[i]);
#pragma unroll
                for (int j = 0; j < 3; j++) acc[i][j] = ffma2(xv, wv[j], acc[i][j]);
            }
        }
#pragma unroll
        for (int i = 0; i < 4; i++)
#pragma unroll
            for (int j = 0; j < 3; j++) {
                float2 v = acc[i][j];
                v.x += bv[j].x; v.y += bv[j].y;
                float2 o;
                o.x = v.x / (1.f + expf(-v.x));
                o.y = v.y / (1.f + expf(-v.y));
                *(float2*)&g_buf2[(long)(r0 + rr0 + i) * 96 + cc0 + 32 * j] = o;
            }
    }
    __syncthreads();          // all phase-1 ws reads done
    for (int i = tid; i < 9216; i += 512) {
        int k = i / 96, cc = i - k * 96;
        ws[k * 98 + cc] = g_lwT[k * 192 + cc];        // xg half
    }
    __syncthreads();
    // ---- phase 2: xg GEMM + bias ----
    float2 acc[4][3];
#pragma unroll
    for (int i = 0; i < 4; i++)
#pragma unroll
        for (int j = 0; j < 3; j++) acc[i][j] = make_float2(0.f, 0.f);
#pragma unroll 4
    for (int k = 0; k < 96; k++) {
        float2 wv[3];
#pragma unroll
        for (int j = 0; j < 3; j++) wv[j] = *(const float2*)&ws[k * 98 + cc0 + 32 * j];
        float4 xq = *(const float4*)&xs[k * 132 + rr0];
        float xr[4] = {xq.x, xq.y, xq.z, xq.w};
#pragma unroll
        for (int i = 0; i < 4; i++) {
            float2 xv = make_float2(xr[i], xr[i]);
#pragma unroll
            for (int j = 0; j < 3; j++) acc[i][j] = ffma2(xv, wv[j], acc[i][j]);
        }
    }
    {
        float2 bv[3];
#pragma unroll
        for (int j = 0; j < 3; j++) bv[j] = *(const float2*)&lb[cc0 + 32 * j];
#pragma unroll
        for (int i = 0; i < 4; i++)
#pragma unroll
            for (int j = 0; j < 3; j++) {
                acc[i][j].x += bv[j].x; acc[i][j].y += bv[j].y;
            }
    }
    __syncthreads();          // xs fully read; reuse as yx[row][98]
#pragma unroll
    for (int i = 0; i < 4; i++)
#pragma unroll
        for (int j = 0; j < 3; j++)
            *(float2*)&xs[(rr0 + i) * 98 + cc0 + 32 * j] = acc[i][j];
    for (int i = tid; i < 2048; i += 512)
        ws[(i >> 6) * 68 + (i & 63)] = g_c64T[i];     // cfk[w][n], w<32
    __syncthreads();
    // e/o pre-pass in place: row w := y[w]+y[63-w]; row 63-w := y[w]-y[63-w]
    for (int i = tid; i < 6144; i += 512) {
        int line = i / 3072, rem = i - line * 3072;
        int w = rem / 96, c = rem - w * 96;           // w < 32
        float* p1 = &xs[(line * 64 + w) * 98 + c];
        float* p2 = &xs[(line * 64 + 63 - w) * 98 + c];
        float y1 = *p1, y2 = *p2;
        *p1 = y1 + y2; *p2 = y1 - y2;
    }
    __syncthreads();
    // ---- phase 3: DCT along W (symmetric, 32-long inner loop) ----
    int line = rt >> 4, wl = (rt & 15) * 4;
    float2 a2[4][3];
#pragma unroll
    for (int i = 0; i < 4; i++)
#pragma unroll
        for (int j = 0; j < 3; j++) a2[i][j] = make_float2(0.f, 0.f);
#pragma unroll 4
    for (int w = 0; w < 32; w++) {
        float2 ev[3], ov[3];
#pragma unroll
        for (int j = 0; j < 3; j++) {
            ev[j] = *(const float2*)&xs[(line * 64 + w) * 98 + cc0 + 32 * j];
            ov[j] = *(const float2*)&xs[(line * 64 + 63 - w) * 98 + cc0 + 32 * j];
        }
        float4 q = *(const float4*)&ws[w * 68 + wl];
        float2 c0v = make_float2(q.x, q.x), c1v = make_float2(q.y, q.y);
        float2 c2v = make_float2(q.z, q.z), c3v = make_float2(q.w, q.w);
#pragma unroll
        for (int j = 0; j < 3; j++) {
            a2[0][j] = ffma2(c0v, ev[j], a2[0][j]);   // n=wl   even
            a2[1][j] = ffma2(c1v, ov[j], a2[1][j]);   // n=wl+1 odd
            a2[2][j] = ffma2(c2v, ev[j], a2[2][j]);
            a2[3][j] = ffma2(c3v, ov[j], a2[3][j]);
        }
    }
#pragma unroll
    for (int i = 0; i < 4; i++)
#pragma unroll
        for (int j = 0; j < 3; j++)
            *(float2*)&g_buf1[(long)(r0 + line * 64 + wl + i) * 96 + cc0 + 32 * j] = a2[i][j];
}

// ------- tau field: A, B coefficient fields [THW,96] (128 rows, 4x6) --------
__global__ void __launch_bounds__(512, 2) k_tau(const float* __restrict__ fe,
                                                const float* __restrict__ tb,
                                                const float* __restrict__ cp,
                                                const float* __restrict__ ap) {
    extern __shared__ float sm[];
    float* xs = sm;               // [96][132]
    float* ws = sm + 12672;       // [96][96]
    int tid = threadIdx.x;
    int r0 = blockIdx.x * 128;
    for (int i = tid; i < 12288; i += 512) {
        int r = i / 96, k = i - r * 96;
        xs[k * 132 + r] = fe[(long)(r0 + r) * 96 + k];
    }
    for (int i = tid; i < 9216; i += 512) ws[i] = g_twT[i];
    __syncthreads();
    float c0 = cp[0], al = ap[0];
    int ct = tid & 15, rt = tid >> 4;
    int rr0 = rt * 4, cc0 = 2 * ct;
    float2 acc[4][3];
#pragma unroll
    for (int i = 0; i < 4; i++)
#pragma unroll
        for (int j = 0; j < 3; j++) acc[i][j] = make_float2(0.f, 0.f);
#pragma unroll 4
    for (int k = 0; k < 96; k++) {
        float2 wv[3];
#pragma unroll
        for (int j = 0; j < 3; j++) wv[j] = *(const float2*)&ws[k * 96 + cc0 + 32 * j];
        float4 q0 = *(const float4*)&xs[k * 132 + rr0];
        float xr[4] = {q0.x, q0.y, q0.z, q0.w};
#pragma unroll
        for (int i = 0; i < 4; i++) {
            float2 xv = make_float2(xr[i], xr[i]);
#pragma unroll
            for (int j = 0; j < 3; j++) acc[i][j] = ffma2(xv, wv[j], acc[i][j]);
        }
    }
#pragma unroll
    for (int i = 0; i < 4; i++) {
#pragma unroll
        for (int j = 0; j < 3; j++) {
            int cc = cc0 + 32 * j;
            float2 v = acc[i][j];
            v.x += tb[cc]; v.y += tb[cc + 1];
            float2 Av, Bv;
            {
                float g = 0.5f * v.x * (1.f + erff(v.x * 0.70710678118654752f));
                float si, co; sincosf(c0 * g, &si, &co);
                float damp = expf(-0.5f * al * g);
                float so = si / (c0 + 1e-8f);
                Av.x = damp * (co + so * al * 0.5f); Bv.x = damp * so;
            }
            {
                float g = 0.5f * v.y * (1.f + erff(v.y * 0.70710678118654752f));
                float si, co; sincosf(c0 * g, &si, &co);
                float damp = expf(-0.5f * al * g);
                float so = si / (c0 + 1e-8f);
                Av.y = damp * (co + so * al * 0.5f); Bv.y = damp * so;
            }
            long idx = (long)(r0 + rr0 + i) * 96 + cc;
            *(float2*)&g_A[idx]  = Av;
            *(float2*)&g_Bc[idx] = Bv;
        }
    }
}

// ---------- forward DCT along H (symmetric): 512 thr, 2 W-cols, 4x6 ---------
__global__ void __launch_bounds__(512, 2) k_dctHf(const float* __restrict__ in,
                                                  float* __restrict__ out) {
    extern __shared__ float sm[];
    float* xs  = sm;             // [2][64][98] = 12544
    float* cfk = sm + 12544;     // [32][68]: cfk[w][n] = c64[n][w], w<32
    int tid = threadIdx.x;
    for (int i = tid; i < 2048; i += 512) cfk[(i >> 6) * 68 + (i & 63)] = g_c64T[i];
    int outer = blockIdx.x >> 5;
    int wpair = blockIdx.x & 31;
    long obase = (long)outer * TSTR;
    for (int i = tid; i < 6144; i += 512) {
        int s = i / 3072, rem = i - s * 3072;
        int k = rem / 48, c2 = rem - k * 48;
        float2 v = *(const float2*)&in[obase + (wpair * 2 + s) * 96 + k * 6144 + c2 * 2];
        *(float2*)&xs[(s * 64 + k) * 98 + c2 * 2] = v;
    }
    __syncthreads();
    // e/o pre-pass in place
    for (int i = tid; i < 6144; i += 512) {
        int s = i / 3072, rem = i - s * 3072;
        int w = rem / 96, c = rem - w * 96;          // w < 32
        float* p1 = &xs[(s * 64 + w) * 98 + c];
        float* p2 = &xs[(s * 64 + 63 - w) * 98 + c];
        float y1 = *p1, y2 = *p2;
        *p1 = y1 + y2; *p2 = y1 - y2;
    }
    __syncthreads();
    int ct = tid & 15, rt = tid >> 4;        // rt 0..31
    int cc0 = 2 * ct;
    int slab = rt >> 4, n0 = (rt & 15) * 4;
    float2 acc[4][3];
#pragma unroll
    for (int i = 0; i < 4; i++)
#pragma unroll
        for (int j = 0; j < 3; j++) acc[i][j] = make_float2(0.f, 0.f);
#pragma unroll 4
    for (int k = 0; k < 32; k++) {
        float2 ev[3], ov[3];
#pragma unroll
        for (int j = 0; j < 3; j++) {
            ev[j] = *(const float2*)&xs[(slab * 64 + k) * 98 + cc0 + 32 * j];
            ov[j] = *(const float2*)&xs[(slab * 64 + 63 - k) * 98 + cc0 + 32 * j];
        }
        float4 q0 = *(const float4*)&cfk[k * 68 + n0];
        float cr[4] = {q0.x, q0.y, q0.z, q0.w};
#pragma unroll
        for (int i = 0; i < 4; i++) {
            float2 cv = make_float2(cr[i], cr[i]);
            float2* src = (i & 1) ? ov : ev;         // n0 mult of 4 -> parity = i&1
#pragma unroll
            for (int j = 0; j < 3; j++) acc[i][j] = ffma2(cv, src[j], acc[i][j]);
        }
    }
    long sbase = obase + (wpair * 2 + slab) * 96;
#pragma unroll
    for (int i = 0; i < 4; i++)
#pragma unroll
        for (int j = 0; j < 3; j++)
            *(float2*)&out[sbase + (n0 + i) * 6144 + cc0 + 32 * j] = acc[i][j];
}

// ---------- inverse DCT along H (parity accum): 512 thr, 2 W-cols -----------
__global__ void __launch_bounds__(512, 2) k_dctHi(const float* __restrict__ in,
                                                  float* __restrict__ out) {
    extern __shared__ float sm[];
    float* xs  = sm;             // [2][64][98] = 12544
    float* cik = sm + 12544;     // [64][36]: cik[n][w] = c64[n][w], w<32
    int tid = threadIdx.x;
    for (int i = tid; i < 2048; i += 512) {
        int n = i >> 5, w = i & 31;
        cik[n * 36 + w] = g_c64[n * 64 + w];
    }
    int outer = blockIdx.x >> 5;
    int wpair = blockIdx.x & 31;
    long obase = (long)outer * TSTR;
    for (int i = tid; i < 6144; i += 512) {
        int s = i / 3072, rem = i - s * 3072;
        int k = rem / 48, c2 = rem - k * 48;
        float2 v = *(const float2*)&in[obase + (wpair * 2 + s) * 96 + k * 6144 + c2 * 2];
        *(float2*)&xs[(s * 64 + k) * 98 + c2 * 2] = v;
    }
    __syncthreads();
    int ct = tid & 15, rt = tid >> 4;        // rt 0..31
    int cc0 = 2 * ct;
    int slab = rt >> 4, wu0 = (rt & 15) * 2;         // 2 w-units -> 4 outputs
    float2 E[2][3], O[2][3];
#pragma unroll
    for (int i = 0; i < 2; i++)
#pragma unroll
        for (int j = 0; j < 3; j++) { E[i][j] = make_float2(0.f, 0.f); O[i][j] = make_float2(0.f, 0.f); }
#pragma unroll 2
    for (int m = 0; m < 32; m++) {
        float2 se[3], so[3];
#pragma unroll
        for (int j = 0; j < 3; j++) {
            se[j] = *(const float2*)&xs[(slab * 64 + 2 * m) * 98 + cc0 + 32 * j];
            so[j] = *(const float2*)&xs[(slab * 64 + 2 * m + 1) * 98 + cc0 + 32 * j];
        }
        float2 qe = *(const float2*)&cik[(2 * m) * 36 + wu0];
        float2 qo = *(const float2*)&cik[(2 * m + 1) * 36 + wu0];
        float ce[2] = {qe.x, qe.y};
        float co[2] = {qo.x, qo.y};
#pragma unroll
        for (int i = 0; i < 2; i++) {
            float2 cev = make_float2(ce[i], ce[i]);
            float2 cov = make_float2(co[i], co[i]);
#pragma unroll
            for (int j = 0; j < 3; j++) {
                E[i][j] = ffma2(cev, se[j], E[i][j]);
                O[i][j] = ffma2(cov, so[j], O[i][j]);
            }
        }
    }
    long sbase = obase + (wpair * 2 + slab) * 96;
#pragma unroll
    for (int i = 0; i < 2; i++) {
        int w = wu0 + i;
#pragma unroll
        for (int j = 0; j < 3; j++) {
            float2 a, bq;
            a.x = E[i][j].x + O[i][j].x; a.y = E[i][j].y + O[i][j].y;
            bq.x = E[i][j].x - O[i][j].x; bq.y = E[i][j].y - O[i][j].y;
            *(float2*)&out[sbase + w * 6144 + cc0 + 32 * j] = a;
            *(float2*)&out[sbase + (63 - w) * 6144 + cc0 + 32 * j] = bq;
        }
    }
}

// ---- fused: DCT_T + v0 mix + spectral combine + IDCT_T, 512 thr, 4 hw ------
__global__ void __launch_bounds__(512, 2) k_fusedT(const float* __restrict__ in,
                                                   float* __restrict__ out,
                                                   const float* __restrict__ vb) {
    extern __shared__ float sm[];
    float* wsm = sm;             // [96][96] = 9216
    float* x16 = sm + 9216;      // [4][16][96] = 6144 (reused as vs)
    float* u0  = x16 + 6144;     // [64][100] = 6400
    float* cA  = u0 + 6400;      // [16][16]: cA[t][n] = c16[n][t]  (fwd)
    float* cC  = cA + 256;       // [16][16]: cC[n][t] = c16[n][t]  (inv)
    int tid = threadIdx.x;
    int b = blockIdx.x >> 10, hw0 = (blockIdx.x & 1023) * 4;
    for (int i = tid; i < 9216; i += 512) wsm[i] = g_vwT[i];
    if (tid < 256) cA[tid] = g_c16T[tid];
    else cC[tid - 256] = g_c16[tid - 256];
    for (int i = tid; i < 6144; i += 512) {
        int s = i / 1536, rem = i - s * 1536;
        int t = rem / 96, c = rem - t * 96;
        x16[i] = in[(long)b * BSTR + (hw0 + s) * 96 + t * TSTR + c];
    }
    __syncthreads();
    int ct = tid & 15, rt = tid >> 4;        // rt 0..31
    int cc0 = 2 * ct;
    int slab = rt >> 3, q2 = (rt & 7) * 2;   // 2 rows per thread
    int hw = hw0 + slab;
    // ---- phase A: forward DCT along T (2 freq rows x 6 ch) ----
    {
        float2 a[2][3];
#pragma unroll
        for (int i = 0; i < 2; i++)
#pragma unroll
            for (int j = 0; j < 3; j++) a[i][j] = make_float2(0.f, 0.f);
#pragma unroll
        for (int t = 0; t < 16; t++) {
            float2 xv[3];
#pragma unroll
            for (int j = 0; j < 3; j++)
                xv[j] = *(const float2*)&x16[(slab * 16 + t) * 96 + cc0 + 32 * j];
            float2 q = *(const float2*)&cA[t * 16 + q2];
            float cr[2] = {q.x, q.y};
#pragma unroll
            for (int i = 0; i < 2; i++) {
                float2 cv = make_float2(cr[i], cr[i]);
#pragma unroll
                for (int j = 0; j < 3; j++) a[i][j] = ffma2(cv, xv[j], a[i][j]);
            }
        }
#pragma unroll
        for (int i = 0; i < 2; i++)
#pragma unroll
            for (int j = 0; j < 3; j++)
                *(float2*)&u0[(slab * 16 + q2 + i) * 100 + cc0 + 32 * j] = a[i][j];
    }
    __syncthreads();
    // ---- phase B: v0 mix + spectral combine -> vs (x16 region) ----
    {
        float2 Av[2][3], Bv[2][3];
#pragma unroll
        for (int i = 0; i < 2; i++)
#pragma unroll
            for (int j = 0; j < 3; j++) {
                long gi = ((long)(q2 + i) * 4096 + hw) * 96 + cc0 + 32 * j;
                Av[i][j] = *(const float2*)&g_A[gi];
                Bv[i][j] = *(const float2*)&g_Bc[gi];
            }
        float2 v[2][3];
#pragma unroll
        for (int i = 0; i < 2; i++)
#pragma unroll
            for (int j = 0; j < 3; j++) v[i][j] = make_float2(0.f, 0.f);
#pragma unroll 4
        for (int k = 0; k < 96; k++) {
            float2 wv[3];
#pragma unroll
            for (int j = 0; j < 3; j++) wv[j] = *(const float2*)&wsm[k * 96 + cc0 + 32 * j];
#pragma unroll
            for (int i = 0; i < 2; i++) {
                float u1 = u0[(slab * 16 + q2 + i) * 100 + k];
                float2 uv = make_float2(u1, u1);
#pragma unroll
                for (int j = 0; j < 3; j++) v[i][j] = ffma2(uv, wv[j], v[i][j]);
            }
        }
        if (hw0 == 0 && rt == 0) {   // DC (t=0,h=0,w=0) of constant v0_b field
#pragma unroll
            for (int j = 0; j < 3; j++) {
                v[0][j].x += 256.f * vb[cc0 + 32 * j];
                v[0][j].y += 256.f * vb[cc0 + 32 * j + 1];
            }
        }
        __syncthreads();   // u0 reads done by all; x16 region becomes vs
#pragma unroll
        for (int i = 0; i < 2; i++)
#pragma unroll
            for (int j = 0; j < 3; j++) {
                float2 uu = *(const float2*)&u0[(slab * 16 + q2 + i) * 100 + cc0 + 32 * j];
                float2 r;
                r.x = Av[i][j].x * uu.x + Bv[i][j].x * v[i][j].x;
                r.y = Av[i][j].y * uu.y + Bv[i][j].y * v[i][j].y;
                *(float2*)&x16[(slab * 16 + q2 + i) * 96 + cc0 + 32 * j] = r;
            }
    }
    __syncthreads();
    // ---- phase C: inverse DCT along T (2 time rows x 6 ch) ----
    {
        float2 y[2][3];
#pragma unroll
        for (int i = 0; i < 2; i++)
#pragma unroll
            for (int j = 0; j < 3; j++) y[i][j] = make_float2(0.f, 0.f);
#pragma unroll
        for (int n = 0; n < 16; n++) {
            float2 sv[3];
#pragma unroll
            for (int j = 0; j < 3; j++)
                sv[j] = *(const float2*)&x16[(slab * 16 + n) * 96 + cc0 + 32 * j];
            float2 q = *(const float2*)&cC[n * 16 + q2];
            float cr[2] = {q.x, q.y};
#pragma unroll
            for (int i = 0; i < 2; i++) {
                float2 cv = make_float2(cr[i], cr[i]);
#pragma unroll
                for (int j = 0; j < 3; j++) y[i][j] = ffma2(cv, sv[j], y[i][j]);
            }
        }
#pragma unroll
        for (int i = 0; i < 2; i++)
#pragma unroll
            for (int j = 0; j < 3; j++)
                *(float2*)&out[(long)b * BSTR + hw * 96 + (q2 + i) * TSTR + cc0 + 32 * j] = y[i][j];
    }
}

// ---- final: IDCT_W(sym) + LN + gate + out GEMM + transpose store -----------
__global__ void __launch_bounds__(256) k_final(const float* __restrict__ lg,
                                               const float* __restrict__ lbt,
                                               const float* __restrict__ ob,
                                               float* __restrict__ outp) {
    extern __shared__ float sm[];
    float* s   = sm;             // [128][98] = 12544 (freq -> spatial/LN'd -> os)
    float* cik = sm + 12544;     // [64][36]: cik[n][w] = c64[n][w], w<32
    float* ws  = cik + 2304;     // [96][96] = 9216
    float* os  = sm;             // reuse s: [96][130] = 12480
    int tid = threadIdx.x;
    int r0 = blockIdx.x * 128;
    int b = r0 >> 16, thw0 = r0 & 65535;
    for (int i = tid; i < 12288; i += 256) {
        int n = i / 96, c = i - n * 96;
        s[n * 98 + c] = g_buf3[(long)r0 * 96 + i];
    }
    for (int i = tid; i < 2048; i += 256) {
        int n = i >> 5, w = i & 31;
        cik[n * 36 + w] = g_c64[n * 64 + w];
    }
    for (int i = tid; i < 9216; i += 256) ws[i] = g_owT[i];
    __syncthreads();
    int ct = tid & 15, rt = tid >> 4;
    int cc0 = 2 * ct;
    int line = rt >> 3, wu0 = (rt & 7) * 4;
    // IDCT along W (parity accumulation): x[w]=E+O, x[63-w]=E-O
    float2 E[4][3], O[4][3];
#pragma unroll
    for (int i = 0; i < 4; i++)
#pragma unroll
        for (int j = 0; j < 3; j++) { E[i][j] = make_float2(0.f, 0.f); O[i][j] = make_float2(0.f, 0.f); }
#pragma unroll 2
    for (int m = 0; m < 32; m++) {
        float2 se[3], so[3];
#pragma unroll
        for (int j = 0; j < 3; j++) {
            se[j] = *(const float2*)&s[(line * 64 + 2 * m) * 98 + cc0 + 32 * j];
            so[j] = *(const float2*)&s[(line * 64 + 2 * m + 1) * 98 + cc0 + 32 * j];
        }
        float4 qe = *(const float4*)&cik[(2 * m) * 36 + wu0];
        float4 qo = *(const float4*)&cik[(2 * m + 1) * 36 + wu0];
        float ce[4] = {qe.x, qe.y, qe.z, qe.w};
        float co[4] = {qo.x, qo.y, qo.z, qo.w};
#pragma unroll
        for (int i = 0; i < 4; i++) {
            float2 cev = make_float2(ce[i], ce[i]);
            float2 cov = make_float2(co[i], co[i]);
#pragma unroll
            for (int j = 0; j < 3; j++) {
                E[i][j] = ffma2(cev, se[j], E[i][j]);
                O[i][j] = ffma2(cov, so[j], O[i][j]);
            }
        }
    }
    __syncthreads();
#pragma unroll
    for (int i = 0; i < 4; i++) {
        int w = wu0 + i;
#pragma unroll
        for (int j = 0; j < 3; j++) {
            float2 a, bq;
            a.x = E[i][j].x + O[i][j].x; a.y = E[i][j].y + O[i][j].y;
            bq.x = E[i][j].x - O[i][j].x; bq.y = E[i][j].y - O[i][j].y;
            *(float2*)&s[(line * 64 + w) * 98 + cc0 + 32 * j] = a;
            *(float2*)&s[(line * 64 + 63 - w) * 98 + cc0 + 32 * j] = bq;
        }
    }
    __syncthreads();
    // LayerNorm + gate in place; 8 warps x 16 rows
    {
        int wp = tid >> 5, lane = tid & 31;
        float g0 = lg[lane], g1 = lg[lane + 32], g2 = lg[lane + 64];
        float b0 = lbt[lane], b1 = lbt[lane + 32], b2 = lbt[lane + 64];
#pragma unroll
        for (int rr = 0; rr < 16; rr++) {
            int w = wp * 16 + rr;
            float x0 = s[w * 98 + lane], x1 = s[w * 98 + lane + 32], x2 = s[w * 98 + lane + 64];
            float sum = x0 + x1 + x2, q = x0 * x0 + x1 * x1 + x2 * x2;
#pragma unroll
            for (int o = 16; o > 0; o >>= 1) {
                sum += __shfl_xor_sync(0xffffffffu, sum, o);
                q   += __shfl_xor_sync(0xffffffffu, q, o);
            }
            float mean = sum * (1.f / 96.f);
            float var = q * (1.f / 96.f) - mean * mean;
            float rstd = rsqrtf(var + 1e-5f);
            long gr = (long)(r0 + w) * 96;
            s[w * 98 + lane]      = ((x0 - mean) * rstd * g0 + b0) * g_buf2[gr + lane];
            s[w * 98 + lane + 32] = ((x1 - mean) * rstd * g1 + b1) * g_buf2[gr + lane + 32];
            s[w * 98 + lane + 64] = ((x2 - mean) * rstd * g2 + b2) * g_buf2[gr + lane + 64];
        }
    }
    __syncthreads();
    // out GEMM: 8 rows x 6 cols per thread (scalar broadcast row loads)
    int rr0 = rt * 8;
    float2 acc[8][3];
#pragma unroll
    for (int i = 0; i < 8; i++)
#pragma unroll
        for (int j = 0; j < 3; j++) acc[i][j] = make_float2(0.f, 0.f);
#pragma unroll 4
    for (int k = 0; k < 96; k++) {
        float2 wv[3];
#pragma unroll
        for (int j = 0; j < 3; j++) wv[j] = *(const float2*)&ws[k * 96 + cc0 + 32 * j];
#pragma unroll
        for (int i = 0; i < 8; i++) {
            float x1 = s[(rr0 + i) * 98 + k];
            float2 xv = make_float2(x1, x1);
#pragma unroll
            for (int j = 0; j < 3; j++) acc[i][j] = ffma2(xv, wv[j], acc[i][j]);
        }
    }
    float2 obv[3];
#pragma unroll
    for (int j = 0; j < 3; j++) obv[j] = *(const float2*)&ob[cc0 + 32 * j];
    __syncthreads();           // GEMM reads of s done; reuse as os
#pragma unroll
    for (int i = 0; i < 8; i++)
#pragma unroll
        for (int j = 0; j < 3; j++) {
            int cc = cc0 + 32 * j;
            os[cc * 130 + rr0 + i]       = acc[i][j].x + obv[j].x;
            os[(cc + 1) * 130 + rr0 + i] = acc[i][j].y + obv[j].y;
        }
    __syncthreads();
    for (int i = tid; i < 12288; i += 256) {
        int cc = i >> 7, w = i & 127;
        outp[(long)b * BSTR + cc * 65536 + thw0 + w] = os[cc * 130 + w];
    }
}

extern "C" void kernel_launch(void* const* d_in, const int* in_sizes, int n_in,
                              void* d_out, int out_size) {
    const float* x   = (const float*)d_in[0];
    const float* fe  = (const float*)d_in[1];
    const float* dww = (const float*)d_in[2];
    const float* dwb = (const float*)d_in[3];
    const float* lw  = (const float*)d_in[4];
    const float* lb  = (const float*)d_in[5];
    const float* vw  = (const float*)d_in[6];
    const float* vb  = (const float*)d_in[7];
    const float* tw  = (const float*)d_in[8];
    const float* tb  = (const float*)d_in[9];
    const float* cc  = (const float*)d_in[10];
    const float* al  = (const float*)d_in[11];
    const float* lg  = (const float*)d_in[12];
    const float* lbt = (const float*)d_in[13];
    const float* ow  = (const float*)d_in[14];
    const float* ob  = (const float*)d_in[15];
    float* outp = (float*)d_out;

    size_t smCnv = (size_t)(6 * 34 * 66) * 4;           //  53856
    size_t smLin = (size_t)(12672 + 9408) * 4;          //  88320
    size_t smTau = (size_t)(12672 + 9216) * 4;          //  87552
    size_t smHf  = (size_t)(12544 + 2176) * 4;          //  58880
    size_t smHi  = (size_t)(12544 + 2304) * 4;          //  59392
    size_t smFus = (size_t)(9216 + 6144 + 6400 + 512) * 4; // 89088
    size_t smFin = (size_t)(12544 + 2304 + 9216) * 4;   //  96256
    cudaFuncSetAttribute(k_conv,   cudaFuncAttributeMaxDynamicSharedMemorySize, (int)smCnv);
    cudaFuncSetAttribute(k_lin,    cudaFuncAttributeMaxDynamicSharedMemorySize, (int)smLin);
    cudaFuncSetAttribute(k_tau,    cudaFuncAttributeMaxDynamicSharedMemorySize, (int)smTau);
    cudaFuncSetAttribute(k_dctHf,  cudaFuncAttributeMaxDynamicSharedMemorySize, (int)smHf);
    cudaFuncSetAttribute(k_dctHi,  cudaFuncAttributeMaxDynamicSharedMemorySize, (int)smHi);
    cudaFuncSetAttribute(k_fusedT, cudaFuncAttributeMaxDynamicSharedMemorySize, (int)smFus);
    cudaFuncSetAttribute(k_final,  cudaFuncAttributeMaxDynamicSharedMemorySize, (int)smFin);

    float *b1, *b3;
    cudaGetSymbolAddress((void**)&b1, g_buf1);
    cudaGetSymbolAddress((void**)&b3, g_buf3);

    k_cosinit<<<1, 256>>>();
    k_prepw<<<180, 256>>>(lw, tw, vw, ow);
    k_conv<<<dim3(2, 4, 192), 256, smCnv>>>(x, dww, dwb);
    k_lin<<<1024, 512, smLin>>>(lb);                   // z+silu -> buf2; xg+DCT_W -> buf1
    k_tau<<<512, 512, smTau>>>(fe, tb, cc, al);
    k_dctHf<<<1024, 512, smHf>>>(b1, b3);              // DCT along H -> buf3
    k_fusedT<<<2048, 512, smFus>>>(b3, b1, vb);        // DCT_T + mix + IDCT_T -> buf1
    k_dctHi<<<1024, 512, smHi>>>(b1, b3);              // IDCT along H -> buf3
    k_final<<<1024, 256, smFin>>>(lg, lbt, ob, outp);  // IDCT_W + LN + gate + GEMM
}

// round 12
// speedup vs baseline: 1.1101x; 1.1101x over previous
#include <cuda_runtime.h>
#include <math.h>

#define NROW 131072            /* B*T*H*W */
#define BSTR 6291456           /* T*H*W*C */
#define TSTR 393216            /* H*W*C   */

__device__ float g_buf0[NROW * 96];
__device__ float g_buf1[NROW * 96];
__device__ float g_buf2[NROW * 96];
__device__ float g_buf3[NROW * 96];
__device__ float g_A [65536 * 96];
__device__ float g_Bc[65536 * 96];
__device__ float g_c64 [4096];     // [n][x]
__device__ float g_c64T[4096];     // [x][n]
__device__ float g_c16 [256];      // [n][x]
__device__ float g_c16T[256];      // [x][n]
__device__ float g_lwT[96 * 192];
__device__ float g_twT[96 * 96];
__device__ float g_vwT[96 * 96];
__device__ float g_owT[96 * 96];

// packed dual-fp32 FMA (FFMA2) — 2 FMAs per issue slot, exact fp32 rounding
__device__ __forceinline__ float2 ffma2(float2 a, float2 b, float2 c) {
    float2 d;
    asm("fma.rn.f32x2 %0, %1, %2, %3;"
        : "=l"(reinterpret_cast<unsigned long long&>(d))
        : "l"(reinterpret_cast<unsigned long long&>(a)),
          "l"(reinterpret_cast<unsigned long long&>(b)),
          "l"(reinterpret_cast<unsigned long long&>(c)));
    return d;
}

// ---------------- cosine basis init (idempotent) -----------------------------
__global__ void __launch_bounds__(256) k_cosinit() {
    int tid = threadIdx.x;
    const float PI = 3.14159265358979323846f;
    for (int i = tid; i < 4096; i += 256) {
        int n = i >> 6, xx = i & 63;
        float v = cosf((float)n * ((float)xx + 0.5f) * (PI / 64.0f)) * 0.17677669529663687f;
        if (n == 0) v *= 0.70710678118654752f;
        g_c64[n * 64 + xx] = v;
        g_c64T[xx * 64 + n] = v;
    }
    for (int i = tid; i < 256; i += 256) {
        int n = i >> 4, xx = i & 15;
        float v = cosf((float)n * ((float)xx + 0.5f) * (PI / 16.0f)) * 0.35355339059327373f;
        if (n == 0) v *= 0.70710678118654752f;
        g_c16[n * 16 + xx] = v;
        g_c16T[xx * 16 + n] = v;
    }
}

// ---------------- weight pre-transpose to k-major ----------------------------
__global__ void __launch_bounds__(256) k_prepw(const float* __restrict__ lw,
                                               const float* __restrict__ tw,
                                               const float* __restrict__ vw,
                                               const float* __restrict__ ow) {
    int i = blockIdx.x * 256 + threadIdx.x;
    if (i < 18432) {
        int cc = i / 96, k = i - cc * 96;
        g_lwT[k * 192 + cc] = lw[i];
    } else if (i < 27648) {
        int j = i - 18432; int cc = j / 96, k = j - cc * 96;
        g_twT[k * 96 + cc] = tw[j];
    } else if (i < 36864) {
        int j = i - 27648; int cc = j / 96, k = j - cc * 96;
        g_vwT[k * 96 + cc] = vw[j];
    } else if (i < 46080) {
        int j = i - 36864; int cc = j / 96, k = j - cc * 96;
        g_owT[k * 96 + cc] = ow[j];
    }
}

// ------ depthwise 3x3x3 conv, 4 t-planes per block: x -> buf0[B,C,T,H,W] ----
__global__ void __launch_bounds__(256) k_conv(const float* __restrict__ x,
                                              const float* __restrict__ wt,
                                              const float* __restrict__ bs) {
    extern __shared__ float xs[];          // [6][34][66] = 13464
    int htile = blockIdx.x, tg = blockIdx.y, bc = blockIdx.z;
    int c = bc % 96;
    int tid = threadIdx.x;
    int h0 = htile * 32;
    for (int i = tid; i < 6 * 34 * 66; i += 256) {
        int p = i / 2244, rem = i - p * 2244;
        int hh = rem / 66, ww = rem - hh * 66;
        int th = tg * 4 - 1 + p, gh = h0 + hh - 1, gw = ww - 1;
        float v = 0.f;
        if ((unsigned)th < 16u && (unsigned)gh < 64u && (unsigned)gw < 64u)
            v = x[(bc * 16 + th) * 4096 + gh * 64 + gw];
        xs[i] = v;
    }
    float wr[27];
#pragma unroll
    for (int j = 0; j < 27; j++) wr[j] = wt[c * 27 + j];
    float bv = bs[c];
    __syncthreads();
    int wd = tid & 63, ht = tid >> 6;
#pragma unroll
    for (int tt = 0; tt < 4; tt++) {
#pragma unroll
        for (int j = 0; j < 8; j++) {
            int l = ht + j * 4;
            float acc = bv;
#pragma unroll
            for (int dt = 0; dt < 3; dt++)
#pragma unroll
                for (int dh = 0; dh < 3; dh++)
#pragma unroll
                    for (int dw = 0; dw < 3; dw++)
                        acc += wr[dt * 9 + dh * 3 + dw] *
                               xs[(tt + dt) * 2244 + (l + dh) * 66 + wd + dw];
            g_buf0[(bc * 16 + tg * 4 + tt) * 4096 + (h0 + l) * 64 + wd] = acc;
        }
    }
}

// ---- fused linear: z->silu->buf2, xg->bias->DCT_W(sym)->buf1 ---------------
__global__ void __launch_bounds__(512, 2) k_lin(const float* __restrict__ lb) {
    extern __shared__ float sm[];
    float* xs = sm;              // [96][132]=12672; phase3 reused as yx[128][98]
    float* ws = sm + 12672;      // [96][98] = 9408; phase3 reused as cfk[32][68]
    int tid = threadIdx.x;
    int r0 = blockIdx.x * 128;
    int b = r0 >> 16, thw0 = r0 & 65535;
    for (int i = tid; i < 12288; i += 512) {
        int k = i >> 7, r = i & 127;
        xs[k * 132 + r] = g_buf0[(b * 96 + k) * 65536 + thw0 + r];
    }
    for (int i = tid; i < 9216; i += 512) {
        int k = i / 96, cc = i - k * 96;
        ws[k * 98 + cc] = g_lwT[k * 192 + 96 + cc];   // z half first
    }
    __syncthreads();
    int ct = tid & 15, rt = tid >> 4;        // rt 0..31
    int rr0 = rt * 4, cc0 = 2 * ct;
    // ---- phase 1: z GEMM + silu ----
    {
        float2 bv[3];
#pragma unroll
        for (int j = 0; j < 3; j++) bv[j] = *(const float2*)&lb[96 + cc0 + 32 * j];
        float2 acc[4][3];
#pragma unroll
        for (int i = 0; i < 4; i++)
#pragma unroll
            for (int j = 0; j < 3; j++) acc[i][j] = make_float2(0.f, 0.f);
#pragma unroll 4
        for (int k = 0; k < 96; k++) {
            float2 wv[3];
#pragma unroll
            for (int j = 0; j < 3; j++) wv[j] = *(const float2*)&ws[k * 98 + cc0 + 32 * j];
            float4 xq = *(const float4*)&xs[k * 132 + rr0];
            float xr[4] = {xq.x, xq.y, xq.z, xq.w};
#pragma unroll
            for (int i = 0; i < 4; i++) {
                float2 xv = make_float2(xr[i], xr[i]);
#pragma unroll
                for (int j = 0; j < 3; j++) acc[i][j] = ffma2(xv, wv[j], acc[i][j]);
            }
        }
#pragma unroll
        for (int i = 0; i < 4; i++)
#pragma unroll
            for (int j = 0; j < 3; j++) {
                float2 v = acc[i][j];
                v.x += bv[j].x; v.y += bv[j].y;
                float2 o;
                o.x = v.x / (1.f + expf(-v.x));
                o.y = v.y / (1.f + expf(-v.y));
                *(float2*)&g_buf2[(long)(r0 + rr0 + i) * 96 + cc0 + 32 * j] = o;
            }
    }
    __syncthreads();          // all phase-1 ws reads done
    for (int i = tid; i < 9216; i += 512) {
        int k = i / 96, cc = i - k * 96;
        ws[k * 98 + cc] = g_lwT[k * 192 + cc];        // xg half
    }
    __syncthreads();
    // ---- phase 2: xg GEMM + bias ----
    float2 acc[4][3];
#pragma unroll
    for (int i = 0; i < 4; i++)
#pragma unroll
        for (int j = 0; j < 3; j++) acc[i][j] = make_float2(0.f, 0.f);
#pragma unroll 4
    for (int k = 0; k < 96; k++) {
        float2 wv[3];
#pragma unroll
        for (int j = 0; j < 3; j++) wv[j] = *(const float2*)&ws[k * 98 + cc0 + 32 * j];
        float4 xq = *(const float4*)&xs[k * 132 + rr0];
        float xr[4] = {xq.x, xq.y, xq.z, xq.w};
#pragma unroll
        for (int i = 0; i < 4; i++) {
            float2 xv = make_float2(xr[i], xr[i]);
#pragma unroll
            for (int j = 0; j < 3; j++) acc[i][j] = ffma2(xv, wv[j], acc[i][j]);
        }
    }
    {
        float2 bv[3];
#pragma unroll
        for (int j = 0; j < 3; j++) bv[j] = *(const float2*)&lb[cc0 + 32 * j];
#pragma unroll
        for (int i = 0; i < 4; i++)
#pragma unroll
            for (int j = 0; j < 3; j++) {
                acc[i][j].x += bv[j].x; acc[i][j].y += bv[j].y;
            }
    }
    __syncthreads();          // xs fully read; reuse as yx[row][98]
#pragma unroll
    for (int i = 0; i < 4; i++)
#pragma unroll
        for (int j = 0; j < 3; j++)
            *(float2*)&xs[(rr0 + i) * 98 + cc0 + 32 * j] = acc[i][j];
    for (int i = tid; i < 2048; i += 512)
        ws[(i >> 6) * 68 + (i & 63)] = g_c64T[i];     // cfk[w][n], w<32
    __syncthreads();
    // e/o pre-pass in place: row w := y[w]+y[63-w]; row 63-w := y[w]-y[63-w]
    for (int i = tid; i < 6144; i += 512) {
        int line = i / 3072, rem = i - line * 3072;
        int w = rem / 96, c = rem - w * 96;           // w < 32
        float* p1 = &xs[(line * 64 + w) * 98 + c];
        float* p2 = &xs[(line * 64 + 63 - w) * 98 + c];
        float y1 = *p1, y2 = *p2;
        *p1 = y1 + y2; *p2 = y1 - y2;
    }
    __syncthreads();
    // ---- phase 3: DCT along W (symmetric, 32-long inner loop) ----
    int line = rt >> 4, wl = (rt & 15) * 4;
    float2 a2[4][3];
#pragma unroll
    for (int i = 0; i < 4; i++)
#pragma unroll
        for (int j = 0; j < 3; j++) a2[i][j] = make_float2(0.f, 0.f);
#pragma unroll 4
    for (int w = 0; w < 32; w++) {
        float2 ev[3], ov[3];
#pragma unroll
        for (int j = 0; j < 3; j++) {
            ev[j] = *(const float2*)&xs[(line * 64 + w) * 98 + cc0 + 32 * j];
            ov[j] = *(const float2*)&xs[(line * 64 + 63 - w) * 98 + cc0 + 32 * j];
        }
        float4 q = *(const float4*)&ws[w * 68 + wl];
        float2 c0v = make_float2(q.x, q.x), c1v = make_float2(q.y, q.y);
        float2 c2v = make_float2(q.z, q.z), c3v = make_float2(q.w, q.w);
#pragma unroll
        for (int j = 0; j < 3; j++) {
            a2[0][j] = ffma2(c0v, ev[j], a2[0][j]);   // n=wl   even
            a2[1][j] = ffma2(c1v, ov[j], a2[1][j]);   // n=wl+1 odd
            a2[2][j] = ffma2(c2v, ev[j], a2[2][j]);
            a2[3][j] = ffma2(c3v, ov[j], a2[3][j]);
        }
    }
#pragma unroll
    for (int i = 0; i < 4; i++)
#pragma unroll
        for (int j = 0; j < 3; j++)
            *(float2*)&g_buf1[(long)(r0 + line * 64 + wl + i) * 96 + cc0 + 32 * j] = a2[i][j];
}

// ------- tau field: A, B coefficient fields [THW,96] (128 rows, 8x6) --------
__global__ void __launch_bounds__(256) k_tau(const float* __restrict__ fe,
                                             const float* __restrict__ tb,
                                             const float* __restrict__ cp,
                                             const float* __restrict__ ap) {
    extern __shared__ float sm[];
    float* xs = sm;               // [96][132]
    float* ws = sm + 12672;       // [96][96]
    int tid = threadIdx.x;
    int r0 = blockIdx.x * 128;
    for (int i = tid; i < 12288; i += 256) {
        int r = i / 96, k = i - r * 96;
        xs[k * 132 + r] = fe[(long)(r0 + r) * 96 + k];
    }
    for (int i = tid; i < 9216; i += 256) ws[i] = g_twT[i];
    __syncthreads();
    float c0 = cp[0], al = ap[0];
    int ct = tid & 15, rt = tid >> 4;
    int rr0 = rt * 8, cc0 = 2 * ct;
    float2 acc[8][3];
#pragma unroll
    for (int i = 0; i < 8; i++)
#pragma unroll
        for (int j = 0; j < 3; j++) acc[i][j] = make_float2(0.f, 0.f);
#pragma unroll 4
    for (int k = 0; k < 96; k++) {
        float2 wv[3];
#pragma unroll
        for (int j = 0; j < 3; j++) wv[j] = *(const float2*)&ws[k * 96 + cc0 + 32 * j];
        float4 q0 = *(const float4*)&xs[k * 132 + rr0];
        float4 q1 = *(const float4*)&xs[k * 132 + rr0 + 4];
        float xr[8] = {q0.x, q0.y, q0.z, q0.w, q1.x, q1.y, q1.z, q1.w};
#pragma unroll
        for (int i = 0; i < 8; i++) {
            float2 xv = make_float2(xr[i], xr[i]);
#pragma unroll
            for (int j = 0; j < 3; j++) acc[i][j] = ffma2(xv, wv[j], acc[i][j]);
        }
    }
#pragma unroll
    for (int i = 0; i < 8; i++) {
#pragma unroll
        for (int j = 0; j < 3; j++) {
            int cc = cc0 + 32 * j;
            float2 v = acc[i][j];
            v.x += tb[cc]; v.y += tb[cc + 1];
            float2 Av, Bv;
            {
                float g = 0.5f * v.x * (1.f + erff(v.x * 0.70710678118654752f));
                float si, co; sincosf(c0 * g, &si, &co);
                float damp = expf(-0.5f * al * g);
                float so = si / (c0 + 1e-8f);
                Av.x = damp * (co + so * al * 0.5f); Bv.x = damp * so;
            }
            {
                float g = 0.5f * v.y * (1.f + erff(v.y * 0.70710678118654752f));
                float si, co; sincosf(c0 * g, &si, &co);
                float damp = expf(-0.5f * al * g);
                float so = si / (c0 + 1e-8f);
                Av.y = damp * (co + so * al * 0.5f); Bv.y = damp * so;
            }
            long idx = (long)(r0 + rr0 + i) * 96 + cc;
            *(float2*)&g_A[idx]  = Av;
            *(float2*)&g_Bc[idx] = Bv;
        }
    }
}

// ---------- forward DCT along H (symmetric): 2 W-columns per block ----------
// e/o butterfly fused into the global->smem staging loop.
__global__ void __launch_bounds__(256) k_dctHf(const float* __restrict__ in,
                                               float* __restrict__ out) {
    extern __shared__ float sm[];
    float* xs  = sm;             // [2][64][98] = 12544 (holds e/o halves)
    float* cfk = sm + 12544;     // [32][68]: cfk[w][n] = c64[n][w], w<32
    int tid = threadIdx.x;
    for (int i = tid; i < 2048; i += 256) cfk[(i >> 6) * 68 + (i & 63)] = g_c64T[i];
    int outer = blockIdx.x >> 5;
    int wpair = blockIdx.x & 31;
    long obase = (long)outer * TSTR;
    for (int i = tid; i < 3072; i += 256) {
        int s = i / 1536, rem = i - s * 1536;
        int k = rem / 48, c2 = rem - k * 48;         // k < 32
        long rb = obase + (wpair * 2 + s) * 96 + c2 * 2;
        float2 v1 = *(const float2*)&in[rb + k * 6144];
        float2 v2 = *(const float2*)&in[rb + (63 - k) * 6144];
        float2 e, o;
        e.x = v1.x + v2.x; e.y = v1.y + v2.y;
        o.x = v1.x - v2.x; o.y = v1.y - v2.y;
        *(float2*)&xs[(s * 64 + k) * 98 + c2 * 2] = e;
        *(float2*)&xs[(s * 64 + 63 - k) * 98 + c2 * 2] = o;
    }
    __syncthreads();
    int ct = tid & 15, rt = tid >> 4;
    int cc0 = 2 * ct;
    int slab = rt >> 3, n0 = (rt & 7) * 8;
    float2 acc[8][3];
#pragma unroll
    for (int i = 0; i < 8; i++)
#pragma unroll
        for (int j = 0; j < 3; j++) acc[i][j] = make_float2(0.f, 0.f);
#pragma unroll 4
    for (int k = 0; k < 32; k++) {
        float2 ev[3], ov[3];
#pragma unroll
        for (int j = 0; j < 3; j++) {
            ev[j] = *(const float2*)&xs[(slab * 64 + k) * 98 + cc0 + 32 * j];
            ov[j] = *(const float2*)&xs[(slab * 64 + 63 - k) * 98 + cc0 + 32 * j];
        }
        float4 q0 = *(const float4*)&cfk[k * 68 + n0];
        float4 q1 = *(const float4*)&cfk[k * 68 + n0 + 4];
        float cr[8] = {q0.x, q0.y, q0.z, q0.w, q1.x, q1.y, q1.z, q1.w};
#pragma unroll
        for (int i = 0; i < 8; i++) {
            float2 cv = make_float2(cr[i], cr[i]);
            float2* src = (i & 1) ? ov : ev;         // parity of n0+i = parity of i
#pragma unroll
            for (int j = 0; j < 3; j++) acc[i][j] = ffma2(cv, src[j], acc[i][j]);
        }
    }
    long sbase = obase + (wpair * 2 + slab) * 96;
#pragma unroll
    for (int i = 0; i < 8; i++)
#pragma unroll
        for (int j = 0; j < 3; j++)
            *(float2*)&out[sbase + (n0 + i) * 6144 + cc0 + 32 * j] = acc[i][j];
}

// ---------- inverse DCT along H (parity accum): 2 W-columns per block -------
__global__ void __launch_bounds__(256) k_dctHi(const float* __restrict__ in,
                                               float* __restrict__ out) {
    extern __shared__ float sm[];
    float* xs  = sm;             // [2][64][98] = 12544
    float* cik = sm + 12544;     // [64][36]: cik[n][w] = c64[n][w], w<32
    int tid = threadIdx.x;
    for (int i = tid; i < 2048; i += 256) {
        int n = i >> 5, w = i & 31;
        cik[n * 36 + w] = g_c64[n * 64 + w];
    }
    int outer = blockIdx.x >> 5;
    int wpair = blockIdx.x & 31;
    long obase = (long)outer * TSTR;
    for (int i = tid; i < 6144; i += 256) {
        int s = i / 3072, rem = i - s * 3072;
        int k = rem / 48, c2 = rem - k * 48;
        float2 v = *(const float2*)&in[obase + (wpair * 2 + s) * 96 + k * 6144 + c2 * 2];
        *(float2*)&xs[(s * 64 + k) * 98 + c2 * 2] = v;
    }
    __syncthreads();
    int ct = tid & 15, rt = tid >> 4;
    int cc0 = 2 * ct;
    int slab = rt >> 3, wu0 = (rt & 7) * 4;          // 4 w-units -> 8 outputs
    float2 E[4][3], O[4][3];
#pragma unroll
    for (int i = 0; i < 4; i++)
#pragma unroll
        for (int j = 0; j < 3; j++) { E[i][j] = make_float2(0.f, 0.f); O[i][j] = make_float2(0.f, 0.f); }
#pragma unroll 2
    for (int m = 0; m < 32; m++) {
        float2 se[3], so[3];
#pragma unroll
        for (int j = 0; j < 3; j++) {
            se[j] = *(const float2*)&xs[(slab * 64 + 2 * m) * 98 + cc0 + 32 * j];
            so[j] = *(const float2*)&xs[(slab * 64 + 2 * m + 1) * 98 + cc0 + 32 * j];
        }
        float4 qe = *(const float4*)&cik[(2 * m) * 36 + wu0];
        float4 qo = *(const float4*)&cik[(2 * m + 1) * 36 + wu0];
        float ce[4] = {qe.x, qe.y, qe.z, qe.w};
        float co[4] = {qo.x, qo.y, qo.z, qo.w};
#pragma unroll
        for (int i = 0; i < 4; i++) {
            float2 cev = make_float2(ce[i], ce[i]);
            float2 cov = make_float2(co[i], co[i]);
#pragma unroll
            for (int j = 0; j < 3; j++) {
                E[i][j] = ffma2(cev, se[j], E[i][j]);
                O[i][j] = ffma2(cov, so[j], O[i][j]);
            }
        }
    }
    long sbase = obase + (wpair * 2 + slab) * 96;
#pragma unroll
    for (int i = 0; i < 4; i++) {
        int w = wu0 + i;
#pragma unroll
        for (int j = 0; j < 3; j++) {
            float2 a, bq;
            a.x = E[i][j].x + O[i][j].x; a.y = E[i][j].y + O[i][j].y;
            bq.x = E[i][j].x - O[i][j].x; bq.y = E[i][j].y - O[i][j].y;
            *(float2*)&out[sbase + w * 6144 + cc0 + 32 * j] = a;
            *(float2*)&out[sbase + (63 - w) * 6144 + cc0 + 32 * j] = bq;
        }
    }
}

// ---- fused: DCT_T + v0 mix + spectral combine + IDCT_T, 4 hw/block ---------
__global__ void __launch_bounds__(256) k_fusedT(const float* __restrict__ in,
                                                float* __restrict__ out,
                                                const float* __restrict__ vb) {
    extern __shared__ float sm[];
    float* wsm = sm;             // [96][96] = 9216
    float* x16 = sm + 9216;      // [4][16][96] = 6144 (reused as vs)
    float* u0  = x16 + 6144;     // [64][100] = 6400
    float* cA  = u0 + 6400;      // [16][16]: cA[t][n] = c16[n][t]  (fwd)
    float* cC  = cA + 256;       // [16][16]: cC[n][t] = c16[n][t]  (inv)
    int tid = threadIdx.x;
    int b = blockIdx.x >> 10, hw0 = (blockIdx.x & 1023) * 4;
    for (int i = tid; i < 9216; i += 256) wsm[i] = g_vwT[i];
    cA[tid] = g_c16T[tid];
    cC[tid] = g_c16[tid];
    for (int i = tid; i < 6144; i += 256) {
        int s = i / 1536, rem = i - s * 1536;
        int t = rem / 96, c = rem - t * 96;
        x16[i] = in[(long)b * BSTR + (hw0 + s) * 96 + t * TSTR + c];
    }
    __syncthreads();
    int ct = tid & 15, rt = tid >> 4;
    int cc0 = 2 * ct;
    int slab = rt >> 2, q4 = (rt & 3) * 4;   // rows within slab
    int hw = hw0 + slab;
    // ---- phase A: forward DCT along T (4 freq rows x 6 ch) ----
    {
        float2 a[4][3];
#pragma unroll
        for (int i = 0; i < 4; i++)
#pragma unroll
            for (int j = 0; j < 3; j++) a[i][j] = make_float2(0.f, 0.f);
#pragma unroll
        for (int t = 0; t < 16; t++) {
            float2 xv[3];
#pragma unroll
            for (int j = 0; j < 3; j++)
                xv[j] = *(const float2*)&x16[(slab * 16 + t) * 96 + cc0 + 32 * j];
            float4 q = *(const float4*)&cA[t * 16 + q4];
            float cr[4] = {q.x, q.y, q.z, q.w};
#pragma unroll
            for (int i = 0; i < 4; i++) {
                float2 cv = make_float2(cr[i], cr[i]);
#pragma unroll
                for (int j = 0; j < 3; j++) a[i][j] = ffma2(cv, xv[j], a[i][j]);
            }
        }
#pragma unroll
        for (int i = 0; i < 4; i++)
#pragma unroll
            for (int j = 0; j < 3; j++)
                *(float2*)&u0[(slab * 16 + q4 + i) * 100 + cc0 + 32 * j] = a[i][j];
    }
    __syncthreads();
    // ---- phase B: v0 mix + spectral combine -> vs (x16 region) ----
    {
        float2 Av[4][3], Bv[4][3];
#pragma unroll
        for (int i = 0; i < 4; i++)
#pragma unroll
            for (int j = 0; j < 3; j++) {
                long gi = ((long)(q4 + i) * 4096 + hw) * 96 + cc0 + 32 * j;
                Av[i][j] = *(const float2*)&g_A[gi];
                Bv[i][j] = *(const float2*)&g_Bc[gi];
            }
        float2 v[4][3];
#pragma unroll
        for (int i = 0; i < 4; i++)
#pragma unroll
            for (int j = 0; j < 3; j++) v[i][j] = make_float2(0.f, 0.f);
#pragma unroll 4
        for (int k = 0; k < 96; k++) {
            float2 wv[3];
#pragma unroll
            for (int j = 0; j < 3; j++) wv[j] = *(const float2*)&wsm[k * 96 + cc0 + 32 * j];
#pragma unroll
            for (int i = 0; i < 4; i++) {
                float u1 = u0[(slab * 16 + q4 + i) * 100 + k];
                float2 uv = make_float2(u1, u1);
#pragma unroll
                for (int j = 0; j < 3; j++) v[i][j] = ffma2(uv, wv[j], v[i][j]);
            }
        }
        if (hw0 == 0 && rt == 0) {   // DC (t=0,h=0,w=0) of constant v0_b field
#pragma unroll
            for (int j = 0; j < 3; j++) {
                v[0][j].x += 256.f * vb[cc0 + 32 * j];
                v[0][j].y += 256.f * vb[cc0 + 32 * j + 1];
            }
        }
        __syncthreads();   // u0 reads done by all; x16 region becomes vs
#pragma unroll
        for (int i = 0; i < 4; i++)
#pragma unroll
            for (int j = 0; j < 3; j++) {
                float2 uu = *(const float2*)&u0[(slab * 16 + q4 + i) * 100 + cc0 + 32 * j];
                float2 r;
                r.x = Av[i][j].x * uu.x + Bv[i][j].x * v[i][j].x;
                r.y = Av[i][j].y * uu.y + Bv[i][j].y * v[i][j].y;
                *(float2*)&x16[(slab * 16 + q4 + i) * 96 + cc0 + 32 * j] = r;
            }
    }
    __syncthreads();
    // ---- phase C: inverse DCT along T (4 time rows x 6 ch) ----
    {
        float2 y[4][3];
#pragma unroll
        for (int i = 0; i < 4; i++)
#pragma unroll
            for (int j = 0; j < 3; j++) y[i][j] = make_float2(0.f, 0.f);
#pragma unroll
        for (int n = 0; n < 16; n++) {
            float2 sv[3];
#pragma unroll
            for (int j = 0; j < 3; j++)
                sv[j] = *(const float2*)&x16[(slab * 16 + n) * 96 + cc0 + 32 * j];
            float4 q = *(const float4*)&cC[n * 16 + q4];
            float cr[4] = {q.x, q.y, q.z, q.w};
#pragma unroll
            for (int i = 0; i < 4; i++) {
                float2 cv = make_float2(cr[i], cr[i]);
#pragma unroll
                for (int j = 0; j < 3; j++) y[i][j] = ffma2(cv, sv[j], y[i][j]);
            }
        }
#pragma unroll
        for (int i = 0; i < 4; i++)
#pragma unroll
            for (int j = 0; j < 3; j++)
                *(float2*)&out[(long)b * BSTR + hw * 96 + (q4 + i) * TSTR + cc0 + 32 * j] = y[i][j];
    }
}

// ---- final: IDCT_W(sym) + LN + gate + out GEMM + transpose store -----------
__global__ void __launch_bounds__(256) k_final(const float* __restrict__ lg,
                                               const float* __restrict__ lbt,
                                               const float* __restrict__ ob,
                                               float* __restrict__ outp) {
    extern __shared__ float sm[];
    float* s   = sm;             // [128][98] = 12544 (freq -> spatial/LN'd -> os)
    float* cik = sm + 12544;     // [64][36]: cik[n][w] = c64[n][w], w<32
    float* ws  = cik + 2304;     // [96][96] = 9216
    float* os  = sm;             // reuse s: [96][130] = 12480
    int tid = threadIdx.x;
    int r0 = blockIdx.x * 128;
    int b = r0 >> 16, thw0 = r0 & 65535;
    for (int i = tid; i < 12288; i += 256) {
        int n = i / 96, c = i - n * 96;
        s[n * 98 + c] = g_buf3[(long)r0 * 96 + i];
    }
    for (int i = tid; i < 2048; i += 256) {
        int n = i >> 5, w = i & 31;
        cik[n * 36 + w] = g_c64[n * 64 + w];
    }
    for (int i = tid; i < 9216; i += 256) ws[i] = g_owT[i];
    __syncthreads();
    int ct = tid & 15, rt = tid >> 4;
    int cc0 = 2 * ct;
    int line = rt >> 3, wu0 = (rt & 7) * 4;
    // IDCT along W (parity accumulation): x[w]=E+O, x[63-w]=E-O
    float2 E[4][3], O[4][3];
#pragma unroll
    for (int i = 0; i < 4; i++)
#pragma unroll
        for (int j = 0; j < 3; j++) { E[i][j] = make_float2(0.f, 0.f); O[i][j] = make_float2(0.f, 0.f); }
#pragma unroll 2
    for (int m = 0; m < 32; m++) {
        float2 se[3], so[3];
#pragma unroll
        for (int j = 0; j < 3; j++) {
            se[j] = *(const float2*)&s[(line * 64 + 2 * m) * 98 + cc0 + 32 * j];
            so[j] = *(const float2*)&s[(line * 64 + 2 * m + 1) * 98 + cc0 + 32 * j];
        }
        float4 qe = *(const float4*)&cik[(2 * m) * 36 + wu0];
        float4 qo = *(const float4*)&cik[(2 * m + 1) * 36 + wu0];
        float ce[4] = {qe.x, qe.y, qe.z, qe.w};
        float co[4] = {qo.x, qo.y, qo.z, qo.w};
#pragma unroll
        for (int i = 0; i < 4; i++) {
            float2 cev = make_float2(ce[i], ce[i]);
            float2 cov = make_float2(co[i], co[i]);
#pragma unroll
            for (int j = 0; j < 3; j++) {
                E[i][j] = ffma2(cev, se[j], E[i][j]);
                O[i][j] = ffma2(cov, so[j], O[i][j]);
            }
        }
    }
    __syncthreads();
#pragma unroll
    for (int i = 0; i < 4; i++) {
        int w = wu0 + i;
#pragma unroll
        for (int j = 0; j < 3; j++) {
            float2 a, bq;
            a.x = E[i][j].x + O[i][j].x; a.y = E[i][j].y + O[i][j].y;
            bq.x = E[i][j].x - O[i][j].x; bq.y = E[i][j].y - O[i][j].y;
            *(float2*)&s[(line * 64 + w) * 98 + cc0 + 32 * j] = a;
            *(float2*)&s[(line * 64 + 63 - w) * 98 + cc0 + 32 * j] = bq;
        }
    }
    __syncthreads();
    // LayerNorm + gate in place; 8 warps x 16 rows
    {
        int wp = tid >> 5, lane = tid & 31;
        float g0 = lg[lane], g1 = lg[lane + 32], g2 = lg[lane + 64];
        float b0 = lbt[lane], b1 = lbt[lane + 32], b2 = lbt[lane + 64];
#pragma unroll
        for (int rr = 0; rr < 16; rr++) {
            int w = wp * 16 + rr;
            float x0 = s[w * 98 + lane], x1 = s[w * 98 + lane + 32], x2 = s[w * 98 + lane + 64];
            float sum = x0 + x1 + x2, q = x0 * x0 + x1 * x1 + x2 * x2;
#pragma unroll
            for (int o = 16; o > 0; o >>= 1) {
                sum += __shfl_xor_sync(0xffffffffu, sum, o);
                q   += __shfl_xor_sync(0xffffffffu, q, o);
            }
            float mean = sum * (1.f / 96.f);
            float var = q * (1.f / 96.f) - mean * mean;
            float rstd = rsqrtf(var + 1e-5f);
            long gr = (long)(r0 + w) * 96;
            s[w * 98 + lane]      = ((x0 - mean) * rstd * g0 + b0) * g_buf2[gr + lane];
            s[w * 98 + lane + 32] = ((x1 - mean) * rstd * g1 + b1) * g_buf2[gr + lane + 32];
            s[w * 98 + lane + 64] = ((x2 - mean) * rstd * g2 + b2) * g_buf2[gr + lane + 64];
        }
    }
    __syncthreads();
    // out GEMM: 8 rows x 6 cols per thread (scalar broadcast row loads)
    int rr0 = rt * 8;
    float2 acc[8][3];
#pragma unroll
    for (int i = 0; i < 8; i++)
#pragma unroll
        for (int j = 0; j < 3; j++) acc[i][j] = make_float2(0.f, 0.f);
#pragma unroll 4
    for (int k = 0; k < 96; k++) {
        float2 wv[3];
#pragma unroll
        for (int j = 0; j < 3; j++) wv[j] = *(const float2*)&ws[k * 96 + cc0 + 32 * j];
#pragma unroll
        for (int i = 0; i < 8; i++) {
            float x1 = s[(rr0 + i) * 98 + k];
            float2 xv = make_float2(x1, x1);
#pragma unroll
            for (int j = 0; j < 3; j++) acc[i][j] = ffma2(xv, wv[j], acc[i][j]);
        }
    }
    float2 obv[3];
#pragma unroll
    for (int j = 0; j < 3; j++) obv[j] = *(const float2*)&ob[cc0 + 32 * j];
    __syncthreads();           // GEMM reads of s done; reuse as os
#pragma unroll
    for (int i = 0; i < 8; i++)
#pragma unroll
        for (int j = 0; j < 3; j++) {
            int cc = cc0 + 32 * j;
            os[cc * 130 + rr0 + i]       = acc[i][j].x + obv[j].x;
            os[(cc + 1) * 130 + rr0 + i] = acc[i][j].y + obv[j].y;
        }
    __syncthreads();
    for (int i = tid; i < 12288; i += 256) {
        int cc = i >> 7, w = i & 127;
        outp[(long)b * BSTR + cc * 65536 + thw0 + w] = os[cc * 130 + w];
    }
}

extern "C" void kernel_launch(void* const* d_in, const int* in_sizes, int n_in,
                              void* d_out, int out_size) {
    const float* x   = (const float*)d_in[0];
    const float* fe  = (const float*)d_in[1];
    const float* dww = (const float*)d_in[2];
    const float* dwb = (const float*)d_in[3];
    const float* lw  = (const float*)d_in[4];
    const float* lb  = (const float*)d_in[5];
    const float* vw  = (const float*)d_in[6];
    const float* vb  = (const float*)d_in[7];
    const float* tw  = (const float*)d_in[8];
    const float* tb  = (const float*)d_in[9];
    const float* cc  = (const float*)d_in[10];
    const float* al  = (const float*)d_in[11];
    const float* lg  = (const float*)d_in[12];
    const float* lbt = (const float*)d_in[13];
    const float* ow  = (const float*)d_in[14];
    const float* ob  = (const float*)d_in[15];
    float* outp = (float*)d_out;

    size_t smCnv = (size_t)(6 * 34 * 66) * 4;           //  53856
    size_t smLin = (size_t)(12672 + 9408) * 4;          //  88320
    size_t smTau = (size_t)(12672 + 9216) * 4;          //  87552
    size_t smHf  = (size_t)(12544 + 2176) * 4;          //  58880
    size_t smHi  = (size_t)(12544 + 2304) * 4;          //  59392
    size_t smFus = (size_t)(9216 + 6144 + 6400 + 512) * 4; // 89088
    size_t smFin = (size_t)(12544 + 2304 + 9216) * 4;   //  96256
    cudaFuncSetAttribute(k_conv,   cudaFuncAttributeMaxDynamicSharedMemorySize, (int)smCnv);
    cudaFuncSetAttribute(k_lin,    cudaFuncAttributeMaxDynamicSharedMemorySize, (int)smLin);
    cudaFuncSetAttribute(k_tau,    cudaFuncAttributeMaxDynamicSharedMemorySize, (int)smTau);
    cudaFuncSetAttribute(k_dctHf,  cudaFuncAttributeMaxDynamicSharedMemorySize, (int)smHf);
    cudaFuncSetAttribute(k_dctHi,  cudaFuncAttributeMaxDynamicSharedMemorySize, (int)smHi);
    cudaFuncSetAttribute(k_fusedT, cudaFuncAttributeMaxDynamicSharedMemorySize, (int)smFus);
    cudaFuncSetAttribute(k_final,  cudaFuncAttributeMaxDynamicSharedMemorySize, (int)smFin);

    float *b1, *b3;
    cudaGetSymbolAddress((void**)&b1, g_buf1);
    cudaGetSymbolAddress((void**)&b3, g_buf3);

    k_cosinit<<<1, 256>>>();
    k_prepw<<<180, 256>>>(lw, tw, vw, ow);
    k_conv<<<dim3(2, 4, 192), 256, smCnv>>>(x, dww, dwb);
    k_lin<<<1024, 512, smLin>>>(lb);                   // z+silu -> buf2; xg+DCT_W -> buf1
    k_tau<<<512, 256, smTau>>>(fe, tb, cc, al);
    k_dctHf<<<1024, 256, smHf>>>(b1, b3);              // DCT along H -> buf3
    k_fusedT<<<2048, 256, smFus>>>(b3, b1, vb);        // DCT_T + mix + IDCT_T -> buf1
    k_dctHi<<<1024, 256, smHi>>>(b1, b3);              // IDCT along H -> buf3
    k_final<<<1024, 256, smFin>>>(lg, lbt, ob, outp);  // IDCT_W + LN + gate + GEMM
}

// round 13
// speedup vs baseline: 1.1463x; 1.0326x over previous
#include <cuda_runtime.h>
#include <math.h>

#define NROW 131072            /* B*T*H*W */
#define BSTR 6291456           /* T*H*W*C */
#define TSTR 393216            /* H*W*C   */

__device__ float g_buf0[NROW * 96];
__device__ float g_buf1[NROW * 96];
__device__ float g_buf2[NROW * 96];
__device__ float g_buf3[NROW * 96];
__device__ float g_A [65536 * 96];
__device__ float g_Bc[65536 * 96];
__device__ float g_c64 [4096];     // [n][x]
__device__ float g_c64T[4096];     // [x][n]
__device__ float g_c16 [256];      // [n][x]
__device__ float g_c16T[256];      // [x][n]
__device__ float g_lwT[96 * 192];
__device__ float g_twT[96 * 96];
__device__ float g_vwT[96 * 96];
__device__ float g_owT[96 * 96];

// packed dual-fp32 FMA (FFMA2) — 2 FMAs per issue slot, exact fp32 rounding
__device__ __forceinline__ float2 ffma2(float2 a, float2 b, float2 c) {
    float2 d;
    asm("fma.rn.f32x2 %0, %1, %2, %3;"
        : "=l"(reinterpret_cast<unsigned long long&>(d))
        : "l"(reinterpret_cast<unsigned long long&>(a)),
          "l"(reinterpret_cast<unsigned long long&>(b)),
          "l"(reinterpret_cast<unsigned long long&>(c)));
    return d;
}

// ------------- merged init: weight transpose (blocks 0..179) + cos (180) ----
__global__ void __launch_bounds__(256) k_init(const float* __restrict__ lw,
                                              const float* __restrict__ tw,
                                              const float* __restrict__ vw,
                                              const float* __restrict__ ow) {
    int tid = threadIdx.x;
    if (blockIdx.x == 180) {
        const float PI = 3.14159265358979323846f;
        for (int i = tid; i < 4096; i += 256) {
            int n = i >> 6, xx = i & 63;
            float v = cosf((float)n * ((float)xx + 0.5f) * (PI / 64.0f)) * 0.17677669529663687f;
            if (n == 0) v *= 0.70710678118654752f;
            g_c64[n * 64 + xx] = v;
            g_c64T[xx * 64 + n] = v;
        }
        for (int i = tid; i < 256; i += 256) {
            int n = i >> 4, xx = i & 15;
            float v = cosf((float)n * ((float)xx + 0.5f) * (PI / 16.0f)) * 0.35355339059327373f;
            if (n == 0) v *= 0.70710678118654752f;
            g_c16[n * 16 + xx] = v;
            g_c16T[xx * 16 + n] = v;
        }
        return;
    }
    int i = blockIdx.x * 256 + tid;
    if (i < 18432) {
        int cc = i / 96, k = i - cc * 96;
        g_lwT[k * 192 + cc] = lw[i];
    } else if (i < 27648) {
        int j = i - 18432; int cc = j / 96, k = j - cc * 96;
        g_twT[k * 96 + cc] = tw[j];
    } else if (i < 36864) {
        int j = i - 27648; int cc = j / 96, k = j - cc * 96;
        g_vwT[k * 96 + cc] = vw[j];
    } else if (i < 46080) {
        int j = i - 36864; int cc = j / 96, k = j - cc * 96;
        g_owT[k * 96 + cc] = ow[j];
    }
}

// ------ depthwise 3x3x3 conv, 4 t-planes per block: x -> buf0[B,C,T,H,W] ----
__global__ void __launch_bounds__(256) k_conv(const float* __restrict__ x,
                                              const float* __restrict__ wt,
                                              const float* __restrict__ bs) {
    extern __shared__ float xs[];          // [6][34][66] = 13464
    int htile = blockIdx.x, tg = blockIdx.y, bc = blockIdx.z;
    int c = bc % 96;
    int tid = threadIdx.x;
    int h0 = htile * 32;
    for (int i = tid; i < 6 * 34 * 66; i += 256) {
        int p = i / 2244, rem = i - p * 2244;
        int hh = rem / 66, ww = rem - hh * 66;
        int th = tg * 4 - 1 + p, gh = h0 + hh - 1, gw = ww - 1;
        float v = 0.f;
        if ((unsigned)th < 16u && (unsigned)gh < 64u && (unsigned)gw < 64u)
            v = x[(bc * 16 + th) * 4096 + gh * 64 + gw];
        xs[i] = v;
    }
    float wr[27];
#pragma unroll
    for (int j = 0; j < 27; j++) wr[j] = wt[c * 27 + j];
    float bv = bs[c];
    __syncthreads();
    int wd = tid & 63, ht = tid >> 6;
#pragma unroll
    for (int tt = 0; tt < 4; tt++) {
#pragma unroll
        for (int j = 0; j < 8; j++) {
            int l = ht + j * 4;
            float acc = bv;
#pragma unroll
            for (int dt = 0; dt < 3; dt++)
#pragma unroll
                for (int dh = 0; dh < 3; dh++)
#pragma unroll
                    for (int dw = 0; dw < 3; dw++)
                        acc += wr[dt * 9 + dh * 3 + dw] *
                               xs[(tt + dt) * 2244 + (l + dh) * 66 + wd + dw];
            g_buf0[(bc * 16 + tg * 4 + tt) * 4096 + (h0 + l) * 64 + wd] = acc;
        }
    }
}

// ---- fused linear: z->silu->buf2, xg->bias->DCT_W(sym)->buf1 ---------------
__global__ void __launch_bounds__(512, 2) k_lin(const float* __restrict__ lb) {
    extern __shared__ float sm[];
    float* xs = sm;              // [96][132]=12672; phase3 reused as yx[128][98]
    float* ws = sm + 12672;      // [96][98] = 9408; phase3 reused as cfk[32][68]
    int tid = threadIdx.x;
    int r0 = blockIdx.x * 128;
    int b = r0 >> 16, thw0 = r0 & 65535;
    for (int i = tid; i < 3072; i += 512) {
        int k = i >> 5, r4 = i & 31;
        *(float4*)&xs[k * 132 + r4 * 4] =
            *(const float4*)&g_buf0[(long)(b * 96 + k) * 65536 + thw0 + r4 * 4];
    }
    for (int i = tid; i < 9216; i += 512) {
        int k = i / 96, cc = i - k * 96;
        ws[k * 98 + cc] = g_lwT[k * 192 + 96 + cc];   // z half first
    }
    __syncthreads();
    int ct = tid & 15, rt = tid >> 4;        // rt 0..31
    int rr0 = rt * 4, cc0 = 2 * ct;
    // ---- phase 1: z GEMM + silu ----
    {
        float2 bv[3];
#pragma unroll
        for (int j = 0; j < 3; j++) bv[j] = *(const float2*)&lb[96 + cc0 + 32 * j];
        float2 acc[4][3];
#pragma unroll
        for (int i = 0; i < 4; i++)
#pragma unroll
            for (int j = 0; j < 3; j++) acc[i][j] = make_float2(0.f, 0.f);
#pragma unroll 4
        for (int k = 0; k < 96; k++) {
            float2 wv[3];
#pragma unroll
            for (int j = 0; j < 3; j++) wv[j] = *(const float2*)&ws[k * 98 + cc0 + 32 * j];
            float4 xq = *(const float4*)&xs[k * 132 + rr0];
            float xr[4] = {xq.x, xq.y, xq.z, xq.w};
#pragma unroll
            for (int i = 0; i < 4; i++) {
                float2 xv = make_float2(xr[i], xr[i]);
#pragma unroll
                for (int j = 0; j < 3; j++) acc[i][j] = ffma2(xv, wv[j], acc[i][j]);
            }
        }
#pragma unroll
        for (int i = 0; i < 4; i++)
#pragma unroll
            for (int j = 0; j < 3; j++) {
                float2 v = acc[i][j];
                v.x += bv[j].x; v.y += bv[j].y;
                float2 o;
                o.x = v.x / (1.f + expf(-v.x));
                o.y = v.y / (1.f + expf(-v.y));
                *(float2*)&g_buf2[(long)(r0 + rr0 + i) * 96 + cc0 + 32 * j] = o;
            }
    }
    __syncthreads();          // all phase-1 ws reads done
    for (int i = tid; i < 9216; i += 512) {
        int k = i / 96, cc = i - k * 96;
        ws[k * 98 + cc] = g_lwT[k * 192 + cc];        // xg half
    }
    __syncthreads();
    // ---- phase 2: xg GEMM + bias ----
    float2 acc[4][3];
#pragma unroll
    for (int i = 0; i < 4; i++)
#pragma unroll
        for (int j = 0; j < 3; j++) acc[i][j] = make_float2(0.f, 0.f);
#pragma unroll 4
    for (int k = 0; k < 96; k++) {
        float2 wv[3];
#pragma unroll
        for (int j = 0; j < 3; j++) wv[j] = *(const float2*)&ws[k * 98 + cc0 + 32 * j];
        float4 xq = *(const float4*)&xs[k * 132 + rr0];
        float xr[4] = {xq.x, xq.y, xq.z, xq.w};
#pragma unroll
        for (int i = 0; i < 4; i++) {
            float2 xv = make_float2(xr[i], xr[i]);
#pragma unroll
            for (int j = 0; j < 3; j++) acc[i][j] = ffma2(xv, wv[j], acc[i][j]);
        }
    }
    {
        float2 bv[3];
#pragma unroll
        for (int j = 0; j < 3; j++) bv[j] = *(const float2*)&lb[cc0 + 32 * j];
#pragma unroll
        for (int i = 0; i < 4; i++)
#pragma unroll
            for (int j = 0; j < 3; j++) {
                acc[i][j].x += bv[j].x; acc[i][j].y += bv[j].y;
            }
    }
    __syncthreads();          // xs fully read; reuse as yx[row][98]
#pragma unroll
    for (int i = 0; i < 4; i++)
#pragma unroll
        for (int j = 0; j < 3; j++)
            *(float2*)&xs[(rr0 + i) * 98 + cc0 + 32 * j] = acc[i][j];
    for (int i = tid; i < 2048; i += 512)
        ws[(i >> 6) * 68 + (i & 63)] = g_c64T[i];     // cfk[w][n], w<32
    __syncthreads();
    // e/o pre-pass in place: row w := y[w]+y[63-w]; row 63-w := y[w]-y[63-w]
    for (int i = tid; i < 6144; i += 512) {
        int line = i / 3072, rem = i - line * 3072;
        int w = rem / 96, c = rem - w * 96;           // w < 32
        float* p1 = &xs[(line * 64 + w) * 98 + c];
        float* p2 = &xs[(line * 64 + 63 - w) * 98 + c];
        float y1 = *p1, y2 = *p2;
        *p1 = y1 + y2; *p2 = y1 - y2;
    }
    __syncthreads();
    // ---- phase 3: DCT along W (symmetric, 32-long inner loop) ----
    int line = rt >> 4, wl = (rt & 15) * 4;
    float2 a2[4][3];
#pragma unroll
    for (int i = 0; i < 4; i++)
#pragma unroll
        for (int j = 0; j < 3; j++) a2[i][j] = make_float2(0.f, 0.f);
#pragma unroll 4
    for (int w = 0; w < 32; w++) {
        float2 ev[3], ov[3];
#pragma unroll
        for (int j = 0; j < 3; j++) {
            ev[j] = *(const float2*)&xs[(line * 64 + w) * 98 + cc0 + 32 * j];
            ov[j] = *(const float2*)&xs[(line * 64 + 63 - w) * 98 + cc0 + 32 * j];
        }
        float4 q = *(const float4*)&ws[w * 68 + wl];
        float2 c0v = make_float2(q.x, q.x), c1v = make_float2(q.y, q.y);
        float2 c2v = make_float2(q.z, q.z), c3v = make_float2(q.w, q.w);
#pragma unroll
        for (int j = 0; j < 3; j++) {
            a2[0][j] = ffma2(c0v, ev[j], a2[0][j]);   // n=wl   even
            a2[1][j] = ffma2(c1v, ov[j], a2[1][j]);   // n=wl+1 odd
            a2[2][j] = ffma2(c2v, ev[j], a2[2][j]);
            a2[3][j] = ffma2(c3v, ov[j], a2[3][j]);
        }
    }
#pragma unroll
    for (int i = 0; i < 4; i++)
#pragma unroll
        for (int j = 0; j < 3; j++)
            *(float2*)&g_buf1[(long)(r0 + line * 64 + wl + i) * 96 + cc0 + 32 * j] = a2[i][j];
}

// ------- tau field: A, B coefficient fields [THW,96] (128 rows, 8x6) --------
__global__ void __launch_bounds__(256) k_tau(const float* __restrict__ fe,
                                             const float* __restrict__ tb,
                                             const float* __restrict__ cp,
                                             const float* __restrict__ ap) {
    extern __shared__ float sm[];
    float* xs = sm;               // [96][132]
    float* ws = sm + 12672;       // [96][96]
    int tid = threadIdx.x;
    int r0 = blockIdx.x * 128;
    for (int i = tid; i < 12288; i += 256) {
        int r = i / 96, k = i - r * 96;
        xs[k * 132 + r] = fe[(long)(r0 + r) * 96 + k];
    }
    for (int i = tid; i < 9216; i += 256) ws[i] = g_twT[i];
    __syncthreads();
    float c0 = cp[0], al = ap[0];
    int ct = tid & 15, rt = tid >> 4;
    int rr0 = rt * 8, cc0 = 2 * ct;
    float2 acc[8][3];
#pragma unroll
    for (int i = 0; i < 8; i++)
#pragma unroll
        for (int j = 0; j < 3; j++) acc[i][j] = make_float2(0.f, 0.f);
#pragma unroll 4
    for (int k = 0; k < 96; k++) {
        float2 wv[3];
#pragma unroll
        for (int j = 0; j < 3; j++) wv[j] = *(const float2*)&ws[k * 96 + cc0 + 32 * j];
        float4 q0 = *(const float4*)&xs[k * 132 + rr0];
        float4 q1 = *(const float4*)&xs[k * 132 + rr0 + 4];
        float xr[8] = {q0.x, q0.y, q0.z, q0.w, q1.x, q1.y, q1.z, q1.w};
#pragma unroll
        for (int i = 0; i < 8; i++) {
            float2 xv = make_float2(xr[i], xr[i]);
#pragma unroll
            for (int j = 0; j < 3; j++) acc[i][j] = ffma2(xv, wv[j], acc[i][j]);
        }
    }
#pragma unroll
    for (int i = 0; i < 8; i++) {
#pragma unroll
        for (int j = 0; j < 3; j++) {
            int cc = cc0 + 32 * j;
            float2 v = acc[i][j];
            v.x += tb[cc]; v.y += tb[cc + 1];
            float2 Av, Bv;
            {
                float g = 0.5f * v.x * (1.f + erff(v.x * 0.70710678118654752f));
                float si, co; sincosf(c0 * g, &si, &co);
                float damp = expf(-0.5f * al * g);
                float so = si / (c0 + 1e-8f);
                Av.x = damp * (co + so * al * 0.5f); Bv.x = damp * so;
            }
            {
                float g = 0.5f * v.y * (1.f + erff(v.y * 0.70710678118654752f));
                float si, co; sincosf(c0 * g, &si, &co);
                float damp = expf(-0.5f * al * g);
                float so = si / (c0 + 1e-8f);
                Av.y = damp * (co + so * al * 0.5f); Bv.y = damp * so;
            }
            long idx = (long)(r0 + rr0 + i) * 96 + cc;
            *(float2*)&g_A[idx]  = Av;
            *(float2*)&g_Bc[idx] = Bv;
        }
    }
}

// ---------- forward DCT along H (symmetric): 2 W-columns per block ----------
// e/o butterfly fused into float4 global->smem staging.
__global__ void __launch_bounds__(256) k_dctHf(const float* __restrict__ in,
                                               float* __restrict__ out) {
    extern __shared__ float sm[];
    float* xs  = sm;             // [2][64][100] = 12800 (e/o halves)
    float* cfk = sm + 12800;     // [32][68]: cfk[w][n] = c64[n][w], w<32
    int tid = threadIdx.x;
    for (int i = tid; i < 2048; i += 256) cfk[(i >> 6) * 68 + (i & 63)] = g_c64T[i];
    int outer = blockIdx.x >> 5;
    int wpair = blockIdx.x & 31;
    long obase = (long)outer * TSTR;
    for (int i = tid; i < 1536; i += 256) {
        int s = i / 768, rem = i - s * 768;
        int k = rem / 24, c4 = rem - k * 24;         // k < 32
        long rb = obase + (wpair * 2 + s) * 96 + c4 * 4;
        float4 v1 = *(const float4*)&in[rb + k * 6144];
        float4 v2 = *(const float4*)&in[rb + (63 - k) * 6144];
        float4 e, o;
        e.x = v1.x + v2.x; e.y = v1.y + v2.y; e.z = v1.z + v2.z; e.w = v1.w + v2.w;
        o.x = v1.x - v2.x; o.y = v1.y - v2.y; o.z = v1.z - v2.z; o.w = v1.w - v2.w;
        *(float4*)&xs[(s * 64 + k) * 100 + c4 * 4] = e;
        *(float4*)&xs[(s * 64 + 63 - k) * 100 + c4 * 4] = o;
    }
    __syncthreads();
    int ct = tid & 15, rt = tid >> 4;
    int cc0 = 2 * ct;
    int slab = rt >> 3, n0 = (rt & 7) * 8;
    float2 acc[8][3];
#pragma unroll
    for (int i = 0; i < 8; i++)
#pragma unroll
        for (int j = 0; j < 3; j++) acc[i][j] = make_float2(0.f, 0.f);
#pragma unroll 4
    for (int k = 0; k < 32; k++) {
        float2 ev[3], ov[3];
#pragma unroll
        for (int j = 0; j < 3; j++) {
            ev[j] = *(const float2*)&xs[(slab * 64 + k) * 100 + cc0 + 32 * j];
            ov[j] = *(const float2*)&xs[(slab * 64 + 63 - k) * 100 + cc0 + 32 * j];
        }
        float4 q0 = *(const float4*)&cfk[k * 68 + n0];
        float4 q1 = *(const float4*)&cfk[k * 68 + n0 + 4];
        float cr[8] = {q0.x, q0.y, q0.z, q0.w, q1.x, q1.y, q1.z, q1.w};
#pragma unroll
        for (int i = 0; i < 8; i++) {
            float2 cv = make_float2(cr[i], cr[i]);
            float2* src = (i & 1) ? ov : ev;         // parity of n0+i = parity of i
#pragma unroll
            for (int j = 0; j < 3; j++) acc[i][j] = ffma2(cv, src[j], acc[i][j]);
        }
    }
    long sbase = obase + (wpair * 2 + slab) * 96;
#pragma unroll
    for (int i = 0; i < 8; i++)
#pragma unroll
        for (int j = 0; j < 3; j++)
            *(float2*)&out[sbase + (n0 + i) * 6144 + cc0 + 32 * j] = acc[i][j];
}

// ---------- inverse DCT along H (parity accum): 2 W-columns per block -------
__global__ void __launch_bounds__(256) k_dctHi(const float* __restrict__ in,
                                               float* __restrict__ out) {
    extern __shared__ float sm[];
    float* xs  = sm;             // [2][64][100] = 12800
    float* cik = sm + 12800;     // [64][36]: cik[n][w] = c64[n][w], w<32
    int tid = threadIdx.x;
    for (int i = tid; i < 2048; i += 256) {
        int n = i >> 5, w = i & 31;
        cik[n * 36 + w] = g_c64[n * 64 + w];
    }
    int outer = blockIdx.x >> 5;
    int wpair = blockIdx.x & 31;
    long obase = (long)outer * TSTR;
    for (int i = tid; i < 3072; i += 256) {
        int s = i / 1536, rem = i - s * 1536;
        int k = rem / 24, c4 = rem - k * 24;
        float4 v = *(const float4*)&in[obase + (wpair * 2 + s) * 96 + k * 6144 + c4 * 4];
        *(float4*)&xs[(s * 64 + k) * 100 + c4 * 4] = v;
    }
    __syncthreads();
    int ct = tid & 15, rt = tid >> 4;
    int cc0 = 2 * ct;
    int slab = rt >> 3, wu0 = (rt & 7) * 4;          // 4 w-units -> 8 outputs
    float2 E[4][3], O[4][3];
#pragma unroll
    for (int i = 0; i < 4; i++)
#pragma unroll
        for (int j = 0; j < 3; j++) { E[i][j] = make_float2(0.f, 0.f); O[i][j] = make_float2(0.f, 0.f); }
#pragma unroll 2
    for (int m = 0; m < 32; m++) {
        float2 se[3], so[3];
#pragma unroll
        for (int j = 0; j < 3; j++) {
            se[j] = *(const float2*)&xs[(slab * 64 + 2 * m) * 100 + cc0 + 32 * j];
            so[j] = *(const float2*)&xs[(slab * 64 + 2 * m + 1) * 100 + cc0 + 32 * j];
        }
        float4 qe = *(const float4*)&cik[(2 * m) * 36 + wu0];
        float4 qo = *(const float4*)&cik[(2 * m + 1) * 36 + wu0];
        float ce[4] = {qe.x, qe.y, qe.z, qe.w};
        float co[4] = {qo.x, qo.y, qo.z, qo.w};
#pragma unroll
        for (int i = 0; i < 4; i++) {
            float2 cev = make_float2(ce[i], ce[i]);
            float2 cov = make_float2(co[i], co[i]);
#pragma unroll
            for (int j = 0; j < 3; j++) {
                E[i][j] = ffma2(cev, se[j], E[i][j]);
                O[i][j] = ffma2(cov, so[j], O[i][j]);
            }
        }
    }
    long sbase = obase + (wpair * 2 + slab) * 96;
#pragma unroll
    for (int i = 0; i < 4; i++) {
        int w = wu0 + i;
#pragma unroll
        for (int j = 0; j < 3; j++) {
            float2 a, bq;
            a.x = E[i][j].x + O[i][j].x; a.y = E[i][j].y + O[i][j].y;
            bq.x = E[i][j].x - O[i][j].x; bq.y = E[i][j].y - O[i][j].y;
            *(float2*)&out[sbase + w * 6144 + cc0 + 32 * j] = a;
            *(float2*)&out[sbase + (63 - w) * 6144 + cc0 + 32 * j] = bq;
        }
    }
}

// ---- fused: DCT_T + v0 mix + spectral combine + IDCT_T, 4 hw/block ---------
__global__ void __launch_bounds__(256) k_fusedT(const float* __restrict__ in,
                                                float* __restrict__ out,
                                                const float* __restrict__ vb) {
    extern __shared__ float sm[];
    float* wsm = sm;             // [96][96] = 9216
    float* x16 = sm + 9216;      // [4][16][96] = 6144 (reused as vs)
    float* u0  = x16 + 6144;     // [64][100] = 6400
    float* cA  = u0 + 6400;      // [16][16]: cA[t][n] = c16[n][t]  (fwd)
    float* cC  = cA + 256;       // [16][16]: cC[n][t] = c16[n][t]  (inv)
    int tid = threadIdx.x;
    int b = blockIdx.x >> 10, hw0 = (blockIdx.x & 1023) * 4;
    for (int i = tid; i < 9216; i += 256) wsm[i] = g_vwT[i];
    cA[tid] = g_c16T[tid];
    cC[tid] = g_c16[tid];
    for (int i = tid; i < 1536; i += 256) {
        int s = i / 384, rem = i - s * 384;
        int t = rem / 24, c4 = rem - t * 24;
        *(float4*)&x16[(s * 16 + t) * 96 + c4 * 4] =
            *(const float4*)&in[(long)b * BSTR + (hw0 + s) * 96 + t * TSTR + c4 * 4];
    }
    __syncthreads();
    int ct = tid & 15, rt = tid >> 4;
    int cc0 = 2 * ct;
    int slab = rt >> 2, q4 = (rt & 3) * 4;   // rows within slab
    int hw = hw0 + slab;
    // ---- phase A: forward DCT along T (4 freq rows x 6 ch) ----
    {
        float2 a[4][3];
#pragma unroll
        for (int i = 0; i < 4; i++)
#pragma unroll
            for (int j = 0; j < 3; j++) a[i][j] = make_float2(0.f, 0.f);
#pragma unroll
        for (int t = 0; t < 16; t++) {
            float2 xv[3];
#pragma unroll
            for (int j = 0; j < 3; j++)
                xv[j] = *(const float2*)&x16[(slab * 16 + t) * 96 + cc0 + 32 * j];
            float4 q = *(const float4*)&cA[t * 16 + q4];
            float cr[4] = {q.x, q.y, q.z, q.w};
#pragma unroll
            for (int i = 0; i < 4; i++) {
                float2 cv = make_float2(cr[i], cr[i]);
#pragma unroll
                for (int j = 0; j < 3; j++) a[i][j] = ffma2(cv, xv[j], a[i][j]);
            }
        }
#pragma unroll
        for (int i = 0; i < 4; i++)
#pragma unroll
            for (int j = 0; j < 3; j++)
                *(float2*)&u0[(slab * 16 + q4 + i) * 100 + cc0 + 32 * j] = a[i][j];
    }
    __syncthreads();
    // ---- phase B: v0 mix + spectral combine -> vs (x16 region) ----
    {
        float2 Av[4][3], Bv[4][3];
#pragma unroll
        for (int i = 0; i < 4; i++)
#pragma unroll
            for (int j = 0; j < 3; j++) {
                long gi = ((long)(q4 + i) * 4096 + hw) * 96 + cc0 + 32 * j;
                Av[i][j] = *(const float2*)&g_A[gi];
                Bv[i][j] = *(const float2*)&g_Bc[gi];
            }
        float2 v[4][3];
#pragma unroll
        for (int i = 0; i < 4; i++)
#pragma unroll
            for (int j = 0; j < 3; j++) v[i][j] = make_float2(0.f, 0.f);
#pragma unroll 4
        for (int k = 0; k < 96; k++) {
            float2 wv[3];
#pragma unroll
            for (int j = 0; j < 3; j++) wv[j] = *(const float2*)&wsm[k * 96 + cc0 + 32 * j];
#pragma unroll
            for (int i = 0; i < 4; i++) {
                float u1 = u0[(slab * 16 + q4 + i) * 100 + k];
                float2 uv = make_float2(u1, u1);
#pragma unroll
                for (int j = 0; j < 3; j++) v[i][j] = ffma2(uv, wv[j], v[i][j]);
            }
        }
        if (hw0 == 0 && rt == 0) {   // DC (t=0,h=0,w=0) of constant v0_b field
#pragma unroll
            for (int j = 0; j < 3; j++) {
                v[0][j].x += 256.f * vb[cc0 + 32 * j];
                v[0][j].y += 256.f * vb[cc0 + 32 * j + 1];
            }
        }
        __syncthreads();   // u0 reads done by all; x16 region becomes vs
#pragma unroll
        for (int i = 0; i < 4; i++)
#pragma unroll
            for (int j = 0; j < 3; j++) {
                float2 uu = *(const float2*)&u0[(slab * 16 + q4 + i) * 100 + cc0 + 32 * j];
                float2 r;
                r.x = Av[i][j].x * uu.x + Bv[i][j].x * v[i][j].x;
                r.y = Av[i][j].y * uu.y + Bv[i][j].y * v[i][j].y;
                *(float2*)&x16[(slab * 16 + q4 + i) * 96 + cc0 + 32 * j] = r;
            }
    }
    __syncthreads();
    // ---- phase C: inverse DCT along T (4 time rows x 6 ch) ----
    {
        float2 y[4][3];
#pragma unroll
        for (int i = 0; i < 4; i++)
#pragma unroll
            for (int j = 0; j < 3; j++) y[i][j] = make_float2(0.f, 0.f);
#pragma unroll
        for (int n = 0; n < 16; n++) {
            float2 sv[3];
#pragma unroll
            for (int j = 0; j < 3; j++)
                sv[j] = *(const float2*)&x16[(slab * 16 + n) * 96 + cc0 + 32 * j];
            float4 q = *(const float4*)&cC[n * 16 + q4];
            float cr[4] = {q.x, q.y, q.z, q.w};
#pragma unroll
            for (int i = 0; i < 4; i++) {
                float2 cv = make_float2(cr[i], cr[i]);
#pragma unroll
                for (int j = 0; j < 3; j++) y[i][j] = ffma2(cv, sv[j], y[i][j]);
            }
        }
#pragma unroll
        for (int i = 0; i < 4; i++)
#pragma unroll
            for (int j = 0; j < 3; j++)
                *(float2*)&out[(long)b * BSTR + hw * 96 + (q4 + i) * TSTR + cc0 + 32 * j] = y[i][j];
    }
}

// ---- final: IDCT_W(sym) + LN + gate + out GEMM + transpose store -----------
__global__ void __launch_bounds__(256) k_final(const float* __restrict__ lg,
                                               const float* __restrict__ lbt,
                                               const float* __restrict__ ob,
                                               float* __restrict__ outp) {
    extern __shared__ float sm[];
    float* s   = sm;             // [128][98] = 12544 (freq -> spatial/LN'd -> os)
    float* cik = sm + 12544;     // [64][36]: cik[n][w] = c64[n][w], w<32
    float* ws  = cik + 2304;     // [96][96] = 9216
    float* os  = sm;             // reuse s: [96][130] = 12480
    int tid = threadIdx.x;
    int r0 = blockIdx.x * 128;
    int b = r0 >> 16, thw0 = r0 & 65535;
    for (int i = tid; i < 12288; i += 256) {
        int n = i / 96, c = i - n * 96;
        s[n * 98 + c] = g_buf3[(long)r0 * 96 + i];
    }
    for (int i = tid; i < 2048; i += 256) {
        int n = i >> 5, w = i & 31;
        cik[n * 36 + w] = g_c64[n * 64 + w];
    }
    for (int i = tid; i < 9216; i += 256) ws[i] = g_owT[i];
    __syncthreads();
    int ct = tid & 15, rt = tid >> 4;
    int cc0 = 2 * ct;
    int line = rt >> 3, wu0 = (rt & 7) * 4;
    // IDCT along W (parity accumulation): x[w]=E+O, x[63-w]=E-O
    float2 E[4][3], O[4][3];
#pragma unroll
    for (int i = 0; i < 4; i++)
#pragma unroll
        for (int j = 0; j < 3; j++) { E[i][j] = make_float2(0.f, 0.f); O[i][j] = make_float2(0.f, 0.f); }
#pragma unroll 2
    for (int m = 0; m < 32; m++) {
        float2 se[3], so[3];
#pragma unroll
        for (int j = 0; j < 3; j++) {
            se[j] = *(const float2*)&s[(line * 64 + 2 * m) * 98 + cc0 + 32 * j];
            so[j] = *(const float2*)&s[(line * 64 + 2 * m + 1) * 98 + cc0 + 32 * j];
        }
        float4 qe = *(const float4*)&cik[(2 * m) * 36 + wu0];
        float4 qo = *(const float4*)&cik[(2 * m + 1) * 36 + wu0];
        float ce[4] = {qe.x, qe.y, qe.z, qe.w};
        float co[4] = {qo.x, qo.y, qo.z, qo.w};
#pragma unroll
        for (int i = 0; i < 4; i++) {
            float2 cev = make_float2(ce[i], ce[i]);
            float2 cov = make_float2(co[i], co[i]);
#pragma unroll
            for (int j = 0; j < 3; j++) {
                E[i][j] = ffma2(cev, se[j], E[i][j]);
                O[i][j] = ffma2(cov, so[j], O[i][j]);
            }
        }
    }
    __syncthreads();
#pragma unroll
    for (int i = 0; i < 4; i++) {
        int w = wu0 + i;
#pragma unroll
        for (int j = 0; j < 3; j++) {
            float2 a, bq;
            a.x = E[i][j].x + O[i][j].x; a.y = E[i][j].y + O[i][j].y;
            bq.x = E[i][j].x - O[i][j].x; bq.y = E[i][j].y - O[i][j].y;
            *(float2*)&s[(line * 64 + w) * 98 + cc0 + 32 * j] = a;
            *(float2*)&s[(line * 64 + 63 - w) * 98 + cc0 + 32 * j] = bq;
        }
    }
    __syncthreads();
    // LayerNorm + gate in place; 8 warps x 16 rows
    {
        int wp = tid >> 5, lane = tid & 31;
        float g0 = lg[lane], g1 = lg[lane + 32], g2 = lg[lane + 64];
        float b0 = lbt[lane], b1 = lbt[lane + 32], b2 = lbt[lane + 64];
#pragma unroll
        for (int rr = 0; rr < 16; rr++) {
            int w = wp * 16 + rr;
            float x0 = s[w * 98 + lane], x1 = s[w * 98 + lane + 32], x2 = s[w * 98 + lane + 64];
            float sum = x0 + x1 + x2, q = x0 * x0 + x1 * x1 + x2 * x2;
#pragma unroll
            for (int o = 16; o > 0; o >>= 1) {
                sum += __shfl_xor_sync(0xffffffffu, sum, o);
                q   += __shfl_xor_sync(0xffffffffu, q, o);
            }
            float mean = sum * (1.f / 96.f);
            float var = q * (1.f / 96.f) - mean * mean;
            float rstd = rsqrtf(var + 1e-5f);
            long gr = (long)(r0 + w) * 96;
            s[w * 98 + lane]      = ((x0 - mean) * rstd * g0 + b0) * g_buf2[gr + lane];
            s[w * 98 + lane + 32] = ((x1 - mean) * rstd * g1 + b1) * g_buf2[gr + lane + 32];
            s[w * 98 + lane + 64] = ((x2 - mean) * rstd * g2 + b2) * g_buf2[gr + lane + 64];
        }
    }
    __syncthreads();
    // out GEMM: 8 rows x 6 cols per thread (scalar broadcast row loads)
    int rr0 = rt * 8;
    float2 acc[8][3];
#pragma unroll
    for (int i = 0; i < 8; i++)
#pragma unroll
        for (int j = 0; j < 3; j++) acc[i][j] = make_float2(0.f, 0.f);
#pragma unroll 4
    for (int k = 0; k < 96; k++) {
        float2 wv[3];
#pragma unroll
        for (int j = 0; j < 3; j++) wv[j] = *(const float2*)&ws[k * 96 + cc0 + 32 * j];
#pragma unroll
        for (int i = 0; i < 8; i++) {
            float x1 = s[(rr0 + i) * 98 + k];
            float2 xv = make_float2(x1, x1);
#pragma unroll
            for (int j = 0; j < 3; j++) acc[i][j] = ffma2(xv, wv[j], acc[i][j]);
        }
    }
    float2 obv[3];
#pragma unroll
    for (int j = 0; j < 3; j++) obv[j] = *(const float2*)&ob[cc0 + 32 * j];
    __syncthreads();           // GEMM reads of s done; reuse as os
#pragma unroll
    for (int i = 0; i < 8; i++)
#pragma unroll
        for (int j = 0; j < 3; j++) {
            int cc = cc0 + 32 * j;
            os[cc * 130 + rr0 + i]       = acc[i][j].x + obv[j].x;
            os[(cc + 1) * 130 + rr0 + i] = acc[i][j].y + obv[j].y;
        }
    __syncthreads();
    for (int i = tid; i < 12288; i += 256) {
        int cc = i >> 7, w = i & 127;
        outp[(long)b * BSTR + cc * 65536 + thw0 + w] = os[cc * 130 + w];
    }
}

extern "C" void kernel_launch(void* const* d_in, const int* in_sizes, int n_in,
                              void* d_out, int out_size) {
    const float* x   = (const float*)d_in[0];
    const float* fe  = (const float*)d_in[1];
    const float* dww = (const float*)d_in[2];
    const float* dwb = (const float*)d_in[3];
    const float* lw  = (const float*)d_in[4];
    const float* lb  = (const float*)d_in[5];
    const float* vw  = (const float*)d_in[6];
    const float* vb  = (const float*)d_in[7];
    const float* tw  = (const float*)d_in[8];
    const float* tb  = (const float*)d_in[9];
    const float* cc  = (const float*)d_in[10];
    const float* al  = (const float*)d_in[11];
    const float* lg  = (const float*)d_in[12];
    const float* lbt = (const float*)d_in[13];
    const float* ow  = (const float*)d_in[14];
    const float* ob  = (const float*)d_in[15];
    float* outp = (float*)d_out;

    size_t smCnv = (size_t)(6 * 34 * 66) * 4;           //  53856
    size_t smLin = (size_t)(12672 + 9408) * 4;          //  88320
    size_t smTau = (size_t)(12672 + 9216) * 4;          //  87552
    size_t smHf  = (size_t)(12800 + 2176) * 4;          //  59904
    size_t smHi  = (size_t)(12800 + 2304) * 4;          //  60416
    size_t smFus = (size_t)(9216 + 6144 + 6400 + 512) * 4; // 89088
    size_t smFin = (size_t)(12544 + 2304 + 9216) * 4;   //  96256
    cudaFuncSetAttribute(k_conv,   cudaFuncAttributeMaxDynamicSharedMemorySize, (int)smCnv);
    cudaFuncSetAttribute(k_lin,    cudaFuncAttributeMaxDynamicSharedMemorySize, (int)smLin);
    cudaFuncSetAttribute(k_tau,    cudaFuncAttributeMaxDynamicSharedMemorySize, (int)smTau);
    cudaFuncSetAttribute(k_dctHf,  cudaFuncAttributeMaxDynamicSharedMemorySize, (int)smHf);
    cudaFuncSetAttribute(k_dctHi,  cudaFuncAttributeMaxDynamicSharedMemorySize, (int)smHi);
    cudaFuncSetAttribute(k_fusedT, cudaFuncAttributeMaxDynamicSharedMemorySize, (int)smFus);
    cudaFuncSetAttribute(k_final,  cudaFuncAttributeMaxDynamicSharedMemorySize, (int)smFin);

    float *b1, *b3;
    cudaGetSymbolAddress((void**)&b1, g_buf1);
    cudaGetSymbolAddress((void**)&b3, g_buf3);

    k_init<<<181, 256>>>(lw, tw, vw, ow);
    k_conv<<<dim3(2, 4, 192), 256, smCnv>>>(x, dww, dwb);
    k_lin<<<1024, 512, smLin>>>(lb);                   // z+silu -> buf2; xg+DCT_W -> buf1
    k_tau<<<512, 256, smTau>>>(fe, tb, cc, al);
    k_dctHf<<<1024, 256, smHf>>>(b1, b3);              // DCT along H -> buf3
    k_fusedT<<<2048, 256, smFus>>>(b3, b1, vb);        // DCT_T + mix + IDCT_T -> buf1
    k_dctHi<<<1024, 256, smHi>>>(b1, b3);              // IDCT along H -> buf3
    k_final<<<1024, 256, smFin>>>(lg, lbt, ob, outp);  // IDCT_W + LN + gate + GEMM
}

// round 14
// speedup vs baseline: 1.2007x; 1.0474x over previous
#include <cuda_runtime.h>
#include <math.h>

#define NROW 131072            /* B*T*H*W */
#define BSTR 6291456           /* T*H*W*C */
#define TSTR 393216            /* H*W*C   */

__device__ float g_buf0[NROW * 96];
__device__ float g_buf1[NROW * 96];
__device__ float g_buf2[NROW * 96];
__device__ float g_buf3[NROW * 96];
__device__ float g_A [65536 * 96];
__device__ float g_Bc[65536 * 96];
__device__ float g_c64 [4096];     // [n][x]
__device__ float g_c64T[4096];     // [x][n]
__device__ float g_c16 [256];      // [n][x]
__device__ float g_c16T[256];      // [x][n]
__device__ float g_lwT[96 * 192];
__device__ float g_twT[96 * 96];
__device__ float g_vwT[96 * 96];
__device__ float g_owT[96 * 96];

// packed dual-fp32 FMA (FFMA2) — 2 FMAs per issue slot, exact fp32 rounding
__device__ __forceinline__ float2 ffma2(float2 a, float2 b, float2 c) {
    float2 d;
    asm("fma.rn.f32x2 %0, %1, %2, %3;"
        : "=l"(reinterpret_cast<unsigned long long&>(d))
        : "l"(reinterpret_cast<unsigned long long&>(a)),
          "l"(reinterpret_cast<unsigned long long&>(b)),
          "l"(reinterpret_cast<unsigned long long&>(c)));
    return d;
}

// ------------- merged init: weight transpose (blocks 0..179) + cos (180) ----
__global__ void __launch_bounds__(256) k_init(const float* __restrict__ lw,
                                              const float* __restrict__ tw,
                                              const float* __restrict__ vw,
                                              const float* __restrict__ ow) {
    int tid = threadIdx.x;
    if (blockIdx.x == 180) {
        const float PI = 3.14159265358979323846f;
        for (int i = tid; i < 4096; i += 256) {
            int n = i >> 6, xx = i & 63;
            float v = cosf((float)n * ((float)xx + 0.5f) * (PI / 64.0f)) * 0.17677669529663687f;
            if (n == 0) v *= 0.70710678118654752f;
            g_c64[n * 64 + xx] = v;
            g_c64T[xx * 64 + n] = v;
        }
        for (int i = tid; i < 256; i += 256) {
            int n = i >> 4, xx = i & 15;
            float v = cosf((float)n * ((float)xx + 0.5f) * (PI / 16.0f)) * 0.35355339059327373f;
            if (n == 0) v *= 0.70710678118654752f;
            g_c16[n * 16 + xx] = v;
            g_c16T[xx * 16 + n] = v;
        }
        return;
    }
    int i = blockIdx.x * 256 + tid;
    if (i < 18432) {
        int cc = i / 96, k = i - cc * 96;
        g_lwT[k * 192 + cc] = lw[i];
    } else if (i < 27648) {
        int j = i - 18432; int cc = j / 96, k = j - cc * 96;
        g_twT[k * 96 + cc] = tw[j];
    } else if (i < 36864) {
        int j = i - 27648; int cc = j / 96, k = j - cc * 96;
        g_vwT[k * 96 + cc] = vw[j];
    } else if (i < 46080) {
        int j = i - 36864; int cc = j / 96, k = j - cc * 96;
        g_owT[k * 96 + cc] = ow[j];
    }
}

// ------ depthwise 3x3x3 conv, 4 t-planes per block: x -> buf0[B,C,T,H,W] ----
__global__ void __launch_bounds__(256) k_conv(const float* __restrict__ x,
                                              const float* __restrict__ wt,
                                              const float* __restrict__ bs) {
    extern __shared__ float xs[];          // [6][34][66] = 13464
    int htile = blockIdx.x, tg = blockIdx.y, bc = blockIdx.z;
    int c = bc % 96;
    int tid = threadIdx.x;
    int h0 = htile * 32;
    for (int i = tid; i < 6 * 34 * 66; i += 256) {
        int p = i / 2244, rem = i - p * 2244;
        int hh = rem / 66, ww = rem - hh * 66;
        int th = tg * 4 - 1 + p, gh = h0 + hh - 1, gw = ww - 1;
        float v = 0.f;
        if ((unsigned)th < 16u && (unsigned)gh < 64u && (unsigned)gw < 64u)
            v = x[(bc * 16 + th) * 4096 + gh * 64 + gw];
        xs[i] = v;
    }
    float wr[27];
#pragma unroll
    for (int j = 0; j < 27; j++) wr[j] = wt[c * 27 + j];
    float bv = bs[c];
    __syncthreads();
    int wd = tid & 63, ht = tid >> 6;
#pragma unroll
    for (int tt = 0; tt < 4; tt++) {
#pragma unroll
        for (int j = 0; j < 8; j++) {
            int l = ht + j * 4;
            float acc = bv;
#pragma unroll
            for (int dt = 0; dt < 3; dt++)
#pragma unroll
                for (int dh = 0; dh < 3; dh++)
#pragma unroll
                    for (int dw = 0; dw < 3; dw++)
                        acc += wr[dt * 9 + dh * 3 + dw] *
                               xs[(tt + dt) * 2244 + (l + dh) * 66 + wd + dw];
            g_buf0[(bc * 16 + tg * 4 + tt) * 4096 + (h0 + l) * 64 + wd] = acc;
        }
    }
}

// ---- fused linear: z->silu->buf2, xg->bias->DCT_W(sym)->buf1 ---------------
__global__ void __launch_bounds__(512, 2) k_lin(const float* __restrict__ lb) {
    extern __shared__ float sm[];
    float* xs = sm;              // [96][132]=12672; phase3 reused as yx[128][98]
    float* ws = sm + 12672;      // [96][98] = 9408; phase3 reused as cfk[32][68]
    int tid = threadIdx.x;
    int r0 = blockIdx.x * 128;
    int b = r0 >> 16, thw0 = r0 & 65535;
    for (int i = tid; i < 3072; i += 512) {
        int k = i >> 5, r4 = i & 31;
        *(float4*)&xs[k * 132 + r4 * 4] =
            *(const float4*)&g_buf0[(long)(b * 96 + k) * 65536 + thw0 + r4 * 4];
    }
    for (int i = tid; i < 9216; i += 512) {
        int k = i / 96, cc = i - k * 96;
        ws[k * 98 + cc] = g_lwT[k * 192 + 96 + cc];   // z half first
    }
    __syncthreads();
    int ct = tid & 15, rt = tid >> 4;        // rt 0..31
    int rr0 = rt * 4, cc0 = 2 * ct;
    // ---- phase 1: z GEMM + silu ----
    {
        float2 bv[3];
#pragma unroll
        for (int j = 0; j < 3; j++) bv[j] = *(const float2*)&lb[96 + cc0 + 32 * j];
        float2 acc[4][3];
#pragma unroll
        for (int i = 0; i < 4; i++)
#pragma unroll
            for (int j = 0; j < 3; j++) acc[i][j] = make_float2(0.f, 0.f);
#pragma unroll 4
        for (int k = 0; k < 96; k++) {
            float2 wv[3];
#pragma unroll
            for (int j = 0; j < 3; j++) wv[j] = *(const float2*)&ws[k * 98 + cc0 + 32 * j];
            float4 xq = *(const float4*)&xs[k * 132 + rr0];
            float xr[4] = {xq.x, xq.y, xq.z, xq.w};
#pragma unroll
            for (int i = 0; i < 4; i++) {
                float2 xv = make_float2(xr[i], xr[i]);
#pragma unroll
                for (int j = 0; j < 3; j++) acc[i][j] = ffma2(xv, wv[j], acc[i][j]);
            }
        }
#pragma unroll
        for (int i = 0; i < 4; i++)
#pragma unroll
            for (int j = 0; j < 3; j++) {
                float2 v = acc[i][j];
                v.x += bv[j].x; v.y += bv[j].y;
                float2 o;
                o.x = v.x / (1.f + __expf(-v.x));
                o.y = v.y / (1.f + __expf(-v.y));
                *(float2*)&g_buf2[(long)(r0 + rr0 + i) * 96 + cc0 + 32 * j] = o;
            }
    }
    __syncthreads();          // all phase-1 ws reads done
    for (int i = tid; i < 9216; i += 512) {
        int k = i / 96, cc = i - k * 96;
        ws[k * 98 + cc] = g_lwT[k * 192 + cc];        // xg half
    }
    __syncthreads();
    // ---- phase 2: xg GEMM + bias ----
    float2 acc[4][3];
#pragma unroll
    for (int i = 0; i < 4; i++)
#pragma unroll
        for (int j = 0; j < 3; j++) acc[i][j] = make_float2(0.f, 0.f);
#pragma unroll 4
    for (int k = 0; k < 96; k++) {
        float2 wv[3];
#pragma unroll
        for (int j = 0; j < 3; j++) wv[j] = *(const float2*)&ws[k * 98 + cc0 + 32 * j];
        float4 xq = *(const float4*)&xs[k * 132 + rr0];
        float xr[4] = {xq.x, xq.y, xq.z, xq.w};
#pragma unroll
        for (int i = 0; i < 4; i++) {
            float2 xv = make_float2(xr[i], xr[i]);
#pragma unroll
            for (int j = 0; j < 3; j++) acc[i][j] = ffma2(xv, wv[j], acc[i][j]);
        }
    }
    {
        float2 bv[3];
#pragma unroll
        for (int j = 0; j < 3; j++) bv[j] = *(const float2*)&lb[cc0 + 32 * j];
#pragma unroll
        for (int i = 0; i < 4; i++)
#pragma unroll
            for (int j = 0; j < 3; j++) {
                acc[i][j].x += bv[j].x; acc[i][j].y += bv[j].y;
            }
    }
    __syncthreads();          // xs fully read; reuse as yx[row][98]
#pragma unroll
    for (int i = 0; i < 4; i++)
#pragma unroll
        for (int j = 0; j < 3; j++)
            *(float2*)&xs[(rr0 + i) * 98 + cc0 + 32 * j] = acc[i][j];
    for (int i = tid; i < 2048; i += 512)
        ws[(i >> 6) * 68 + (i & 63)] = g_c64T[i];     // cfk[w][n], w<32
    __syncthreads();
    // e/o pre-pass in place: row w := y[w]+y[63-w]; row 63-w := y[w]-y[63-w]
    for (int i = tid; i < 6144; i += 512) {
        int line = i / 3072, rem = i - line * 3072;
        int w = rem / 96, c = rem - w * 96;           // w < 32
        float* p1 = &xs[(line * 64 + w) * 98 + c];
        float* p2 = &xs[(line * 64 + 63 - w) * 98 + c];
        float y1 = *p1, y2 = *p2;
        *p1 = y1 + y2; *p2 = y1 - y2;
    }
    __syncthreads();
    // ---- phase 3: DCT along W (symmetric, 32-long inner loop) ----
    int line = rt >> 4, wl = (rt & 15) * 4;
    float2 a2[4][3];
#pragma unroll
    for (int i = 0; i < 4; i++)
#pragma unroll
        for (int j = 0; j < 3; j++) a2[i][j] = make_float2(0.f, 0.f);
#pragma unroll 4
    for (int w = 0; w < 32; w++) {
        float2 ev[3], ov[3];
#pragma unroll
        for (int j = 0; j < 3; j++) {
            ev[j] = *(const float2*)&xs[(line * 64 + w) * 98 + cc0 + 32 * j];
            ov[j] = *(const float2*)&xs[(line * 64 + 63 - w) * 98 + cc0 + 32 * j];
        }
        float4 q = *(const float4*)&ws[w * 68 + wl];
        float2 c0v = make_float2(q.x, q.x), c1v = make_float2(q.y, q.y);
        float2 c2v = make_float2(q.z, q.z), c3v = make_float2(q.w, q.w);
#pragma unroll
        for (int j = 0; j < 3; j++) {
            a2[0][j] = ffma2(c0v, ev[j], a2[0][j]);   // n=wl   even
            a2[1][j] = ffma2(c1v, ov[j], a2[1][j]);   // n=wl+1 odd
            a2[2][j] = ffma2(c2v, ev[j], a2[2][j]);
            a2[3][j] = ffma2(c3v, ov[j], a2[3][j]);
        }
    }
#pragma unroll
    for (int i = 0; i < 4; i++)
#pragma unroll
        for (int j = 0; j < 3; j++)
            *(float2*)&g_buf1[(long)(r0 + line * 64 + wl + i) * 96 + cc0 + 32 * j] = a2[i][j];
}

// ------- tau field: A, B coefficient fields [THW,96] (128 rows, 8x6) --------
__global__ void __launch_bounds__(256) k_tau(const float* __restrict__ fe,
                                             const float* __restrict__ tb,
                                             const float* __restrict__ cp,
                                             const float* __restrict__ ap) {
    extern __shared__ float sm[];
    float* xs = sm;               // [96][132]
    float* ws = sm + 12672;       // [96][96]
    int tid = threadIdx.x;
    int r0 = blockIdx.x * 128;
    for (int i = tid; i < 12288; i += 256) {
        int r = i / 96, k = i - r * 96;
        xs[k * 132 + r] = fe[(long)(r0 + r) * 96 + k];
    }
    for (int i = tid; i < 9216; i += 256) ws[i] = g_twT[i];
    __syncthreads();
    float c0 = cp[0], al = ap[0];
    int ct = tid & 15, rt = tid >> 4;
    int rr0 = rt * 8, cc0 = 2 * ct;
    float2 acc[8][3];
#pragma unroll
    for (int i = 0; i < 8; i++)
#pragma unroll
        for (int j = 0; j < 3; j++) acc[i][j] = make_float2(0.f, 0.f);
#pragma unroll 4
    for (int k = 0; k < 96; k++) {
        float2 wv[3];
#pragma unroll
        for (int j = 0; j < 3; j++) wv[j] = *(const float2*)&ws[k * 96 + cc0 + 32 * j];
        float4 q0 = *(const float4*)&xs[k * 132 + rr0];
        float4 q1 = *(const float4*)&xs[k * 132 + rr0 + 4];
        float xr[8] = {q0.x, q0.y, q0.z, q0.w, q1.x, q1.y, q1.z, q1.w};
#pragma unroll
        for (int i = 0; i < 8; i++) {
            float2 xv = make_float2(xr[i], xr[i]);
#pragma unroll
            for (int j = 0; j < 3; j++) acc[i][j] = ffma2(xv, wv[j], acc[i][j]);
        }
    }
#pragma unroll
    for (int i = 0; i < 8; i++) {
#pragma unroll
        for (int j = 0; j < 3; j++) {
            int cc = cc0 + 32 * j;
            float2 v = acc[i][j];
            v.x += tb[cc]; v.y += tb[cc + 1];
            float2 Av, Bv;
            {
                float g = 0.5f * v.x * (1.f + erff(v.x * 0.70710678118654752f));
                float si, co; __sincosf(c0 * g, &si, &co);
                float damp = __expf(-0.5f * al * g);
                float so = si / (c0 + 1e-8f);
                Av.x = damp * (co + so * al * 0.5f); Bv.x = damp * so;
            }
            {
                float g = 0.5f * v.y * (1.f + erff(v.y * 0.70710678118654752f));
                float si, co; __sincosf(c0 * g, &si, &co);
                float damp = __expf(-0.5f * al * g);
                float so = si / (c0 + 1e-8f);
                Av.y = damp * (co + so * al * 0.5f); Bv.y = damp * so;
            }
            long idx = (long)(r0 + rr0 + i) * 96 + cc;
            *(float2*)&g_A[idx]  = Av;
            *(float2*)&g_Bc[idx] = Bv;
        }
    }
}

// ---------- forward DCT along H (symmetric): 2 W-columns per block ----------
// e/o butterfly fused into float4 global->smem staging.
__global__ void __launch_bounds__(256) k_dctHf(const float* __restrict__ in,
                                               float* __restrict__ out) {
    extern __shared__ float sm[];
    float* xs  = sm;             // [2][64][100] = 12800 (e/o halves)
    float* cfk = sm + 12800;     // [32][68]: cfk[w][n] = c64[n][w], w<32
    int tid = threadIdx.x;
    for (int i = tid; i < 2048; i += 256) cfk[(i >> 6) * 68 + (i & 63)] = g_c64T[i];
    int outer = blockIdx.x >> 5;
    int wpair = blockIdx.x & 31;
    long obase = (long)outer * TSTR;
    for (int i = tid; i < 1536; i += 256) {
        int s = i / 768, rem = i - s * 768;
        int k = rem / 24, c4 = rem - k * 24;         // k < 32
        long rb = obase + (wpair * 2 + s) * 96 + c4 * 4;
        float4 v1 = *(const float4*)&in[rb + k * 6144];
        float4 v2 = *(const float4*)&in[rb + (63 - k) * 6144];
        float4 e, o;
        e.x = v1.x + v2.x; e.y = v1.y + v2.y; e.z = v1.z + v2.z; e.w = v1.w + v2.w;
        o.x = v1.x - v2.x; o.y = v1.y - v2.y; o.z = v1.z - v2.z; o.w = v1.w - v2.w;
        *(float4*)&xs[(s * 64 + k) * 100 + c4 * 4] = e;
        *(float4*)&xs[(s * 64 + 63 - k) * 100 + c4 * 4] = o;
    }
    __syncthreads();
    int ct = tid & 15, rt = tid >> 4;
    int cc0 = 2 * ct;
    int slab = rt >> 3, n0 = (rt & 7) * 8;
    float2 acc[8][3];
#pragma unroll
    for (int i = 0; i < 8; i++)
#pragma unroll
        for (int j = 0; j < 3; j++) acc[i][j] = make_float2(0.f, 0.f);
#pragma unroll 4
    for (int k = 0; k < 32; k++) {
        float2 ev[3], ov[3];
#pragma unroll
        for (int j = 0; j < 3; j++) {
            ev[j] = *(const float2*)&xs[(slab * 64 + k) * 100 + cc0 + 32 * j];
            ov[j] = *(const float2*)&xs[(slab * 64 + 63 - k) * 100 + cc0 + 32 * j];
        }
        float4 q0 = *(const float4*)&cfk[k * 68 + n0];
        float4 q1 = *(const float4*)&cfk[k * 68 + n0 + 4];
        float cr[8] = {q0.x, q0.y, q0.z, q0.w, q1.x, q1.y, q1.z, q1.w};
#pragma unroll
        for (int i = 0; i < 8; i++) {
            float2 cv = make_float2(cr[i], cr[i]);
            float2* src = (i & 1) ? ov : ev;         // parity of n0+i = parity of i
#pragma unroll
            for (int j = 0; j < 3; j++) acc[i][j] = ffma2(cv, src[j], acc[i][j]);
        }
    }
    long sbase = obase + (wpair * 2 + slab) * 96;
#pragma unroll
    for (int i = 0; i < 8; i++)
#pragma unroll
        for (int j = 0; j < 3; j++)
            *(float2*)&out[sbase + (n0 + i) * 6144 + cc0 + 32 * j] = acc[i][j];
}

// ---------- inverse DCT along H (parity accum): 2 W-columns per block -------
__global__ void __launch_bounds__(256) k_dctHi(const float* __restrict__ in,
                                               float* __restrict__ out) {
    extern __shared__ float sm[];
    float* xs  = sm;             // [2][64][100] = 12800
    float* cik = sm + 12800;     // [64][36]: cik[n][w] = c64[n][w], w<32
    int tid = threadIdx.x;
    for (int i = tid; i < 2048; i += 256) {
        int n = i >> 5, w = i & 31;
        cik[n * 36 + w] = g_c64[n * 64 + w];
    }
    int outer = blockIdx.x >> 5;
    int wpair = blockIdx.x & 31;
    long obase = (long)outer * TSTR;
    for (int i = tid; i < 3072; i += 256) {
        int s = i / 1536, rem = i - s * 1536;
        int k = rem / 24, c4 = rem - k * 24;
        float4 v = *(const float4*)&in[obase + (wpair * 2 + s) * 96 + k * 6144 + c4 * 4];
        *(float4*)&xs[(s * 64 + k) * 100 + c4 * 4] = v;
    }
    __syncthreads();
    int ct = tid & 15, rt = tid >> 4;
    int cc0 = 2 * ct;
    int slab = rt >> 3, wu0 = (rt & 7) * 4;          // 4 w-units -> 8 outputs
    float2 E[4][3], O[4][3];
#pragma unroll
    for (int i = 0; i < 4; i++)
#pragma unroll
        for (int j = 0; j < 3; j++) { E[i][j] = make_float2(0.f, 0.f); O[i][j] = make_float2(0.f, 0.f); }
#pragma unroll 2
    for (int m = 0; m < 32; m++) {
        float2 se[3], so[3];
#pragma unroll
        for (int j = 0; j < 3; j++) {
            se[j] = *(const float2*)&xs[(slab * 64 + 2 * m) * 100 + cc0 + 32 * j];
            so[j] = *(const float2*)&xs[(slab * 64 + 2 * m + 1) * 100 + cc0 + 32 * j];
        }
        float4 qe = *(const float4*)&cik[(2 * m) * 36 + wu0];
        float4 qo = *(const float4*)&cik[(2 * m + 1) * 36 + wu0];
        float ce[4] = {qe.x, qe.y, qe.z, qe.w};
        float co[4] = {qo.x, qo.y, qo.z, qo.w};
#pragma unroll
        for (int i = 0; i < 4; i++) {
            float2 cev = make_float2(ce[i], ce[i]);
            float2 cov = make_float2(co[i], co[i]);
#pragma unroll
            for (int j = 0; j < 3; j++) {
                E[i][j] = ffma2(cev, se[j], E[i][j]);
                O[i][j] = ffma2(cov, so[j], O[i][j]);
            }
        }
    }
    long sbase = obase + (wpair * 2 + slab) * 96;
#pragma unroll
    for (int i = 0; i < 4; i++) {
        int w = wu0 + i;
#pragma unroll
        for (int j = 0; j < 3; j++) {
            float2 a, bq;
            a.x = E[i][j].x + O[i][j].x; a.y = E[i][j].y + O[i][j].y;
            bq.x = E[i][j].x - O[i][j].x; bq.y = E[i][j].y - O[i][j].y;
            *(float2*)&out[sbase + w * 6144 + cc0 + 32 * j] = a;
            *(float2*)&out[sbase + (63 - w) * 6144 + cc0 + 32 * j] = bq;
        }
    }
}

// ---- fused: DCT_T + v0 mix + spectral combine + IDCT_T, 4 hw/block ---------
__global__ void __launch_bounds__(256) k_fusedT(const float* __restrict__ in,
                                                float* __restrict__ out,
                                                const float* __restrict__ vb) {
    extern __shared__ float sm[];
    float* wsm = sm;             // [96][96] = 9216
    float* x16 = sm + 9216;      // [4][16][96] = 6144 (reused as vs)
    float* u0  = x16 + 6144;     // [64][100] = 6400
    float* cA  = u0 + 6400;      // [16][16]: cA[t][n] = c16[n][t]  (fwd)
    float* cC  = cA + 256;       // [16][16]: cC[n][t] = c16[n][t]  (inv)
    int tid = threadIdx.x;
    int b = blockIdx.x >> 10, hw0 = (blockIdx.x & 1023) * 4;
    for (int i = tid; i < 9216; i += 256) wsm[i] = g_vwT[i];
    cA[tid] = g_c16T[tid];
    cC[tid] = g_c16[tid];
    for (int i = tid; i < 1536; i += 256) {
        int s = i / 384, rem = i - s * 384;
        int t = rem / 24, c4 = rem - t * 24;
        *(float4*)&x16[(s * 16 + t) * 96 + c4 * 4] =
            *(const float4*)&in[(long)b * BSTR + (hw0 + s) * 96 + t * TSTR + c4 * 4];
    }
    __syncthreads();
    int ct = tid & 15, rt = tid >> 4;
    int cc0 = 2 * ct;
    int slab = rt >> 2, q4 = (rt & 3) * 4;   // rows within slab
    int hw = hw0 + slab;
    // ---- phase A: forward DCT along T (4 freq rows x 6 ch) ----
    {
        float2 a[4][3];
#pragma unroll
        for (int i = 0; i < 4; i++)
#pragma unroll
            for (int j = 0; j < 3; j++) a[i][j] = make_float2(0.f, 0.f);
#pragma unroll
        for (int t = 0; t < 16; t++) {
            float2 xv[3];
#pragma unroll
            for (int j = 0; j < 3; j++)
                xv[j] = *(const float2*)&x16[(slab * 16 + t) * 96 + cc0 + 32 * j];
            float4 q = *(const float4*)&cA[t * 16 + q4];
            float cr[4] = {q.x, q.y, q.z, q.w};
#pragma unroll
            for (int i = 0; i < 4; i++) {
                float2 cv = make_float2(cr[i], cr[i]);
#pragma unroll
                for (int j = 0; j < 3; j++) a[i][j] = ffma2(cv, xv[j], a[i][j]);
            }
        }
#pragma unroll
        for (int i = 0; i < 4; i++)
#pragma unroll
            for (int j = 0; j < 3; j++)
                *(float2*)&u0[(slab * 16 + q4 + i) * 100 + cc0 + 32 * j] = a[i][j];
    }
    __syncthreads();
    // ---- phase B: v0 mix + spectral combine -> vs (x16 region) ----
    {
        float2 Av[4][3], Bv[4][3];
#pragma unroll
        for (int i = 0; i < 4; i++)
#pragma unroll
            for (int j = 0; j < 3; j++) {
                long gi = ((long)(q4 + i) * 4096 + hw) * 96 + cc0 + 32 * j;
                Av[i][j] = *(const float2*)&g_A[gi];
                Bv[i][j] = *(const float2*)&g_Bc[gi];
            }
        float2 v[4][3];
#pragma unroll
        for (int i = 0; i < 4; i++)
#pragma unroll
            for (int j = 0; j < 3; j++) v[i][j] = make_float2(0.f, 0.f);
#pragma unroll 4
        for (int k = 0; k < 96; k++) {
            float2 wv[3];
#pragma unroll
            for (int j = 0; j < 3; j++) wv[j] = *(const float2*)&wsm[k * 96 + cc0 + 32 * j];
#pragma unroll
            for (int i = 0; i < 4; i++) {
                float u1 = u0[(slab * 16 + q4 + i) * 100 + k];
                float2 uv = make_float2(u1, u1);
#pragma unroll
                for (int j = 0; j < 3; j++) v[i][j] = ffma2(uv, wv[j], v[i][j]);
            }
        }
        if (hw0 == 0 && rt == 0) {   // DC (t=0,h=0,w=0) of constant v0_b field
#pragma unroll
            for (int j = 0; j < 3; j++) {
                v[0][j].x += 256.f * vb[cc0 + 32 * j];
                v[0][j].y += 256.f * vb[cc0 + 32 * j + 1];
            }
        }
        __syncthreads();   // u0 reads done by all; x16 region becomes vs
#pragma unroll
        for (int i = 0; i < 4; i++)
#pragma unroll
            for (int j = 0; j < 3; j++) {
                float2 uu = *(const float2*)&u0[(slab * 16 + q4 + i) * 100 + cc0 + 32 * j];
                float2 r;
                r.x = Av[i][j].x * uu.x + Bv[i][j].x * v[i][j].x;
                r.y = Av[i][j].y * uu.y + Bv[i][j].y * v[i][j].y;
                *(float2*)&x16[(slab * 16 + q4 + i) * 96 + cc0 + 32 * j] = r;
            }
    }
    __syncthreads();
    // ---- phase C: inverse DCT along T (4 time rows x 6 ch) ----
    {
        float2 y[4][3];
#pragma unroll
        for (int i = 0; i < 4; i++)
#pragma unroll
            for (int j = 0; j < 3; j++) y[i][j] = make_float2(0.f, 0.f);
#pragma unroll
        for (int n = 0; n < 16; n++) {
            float2 sv[3];
#pragma unroll
            for (int j = 0; j < 3; j++)
                sv[j] = *(const float2*)&x16[(slab * 16 + n) * 96 + cc0 + 32 * j];
            float4 q = *(const float4*)&cC[n * 16 + q4];
            float cr[4] = {q.x, q.y, q.z, q.w};
#pragma unroll
            for (int i = 0; i < 4; i++) {
                float2 cv = make_float2(cr[i], cr[i]);
#pragma unroll
                for (int j = 0; j < 3; j++) y[i][j] = ffma2(cv, sv[j], y[i][j]);
            }
        }
#pragma unroll
        for (int i = 0; i < 4; i++)
#pragma unroll
            for (int j = 0; j < 3; j++)
                *(float2*)&out[(long)b * BSTR + hw * 96 + (q4 + i) * TSTR + cc0 + 32 * j] = y[i][j];
    }
}

// ---- final: IDCT_W(sym) + LN + gate + out GEMM + transpose store -----------
__global__ void __launch_bounds__(256) k_final(const float* __restrict__ lg,
                                               const float* __restrict__ lbt,
                                               const float* __restrict__ ob,
                                               float* __restrict__ outp) {
    extern __shared__ float sm[];
    float* s   = sm;             // [128][98] = 12544 (freq -> spatial/LN'd -> os)
    float* cik = sm + 12544;     // [64][36]: cik[n][w] = c64[n][w], w<32
    float* ws  = cik + 2304;     // [96][96] = 9216
    float* os  = sm;             // reuse s: [96][130] = 12480
    int tid = threadIdx.x;
    int r0 = blockIdx.x * 128;
    int b = r0 >> 16, thw0 = r0 & 65535;
    for (int i = tid; i < 12288; i += 256) {
        int n = i / 96, c = i - n * 96;
        s[n * 98 + c] = g_buf3[(long)r0 * 96 + i];
    }
    for (int i = tid; i < 2048; i += 256) {
        int n = i >> 5, w = i & 31;
        cik[n * 36 + w] = g_c64[n * 64 + w];
    }
    for (int i = tid; i < 9216; i += 256) ws[i] = g_owT[i];
    __syncthreads();
    int ct = tid & 15, rt = tid >> 4;
    int cc0 = 2 * ct;
    int line = rt >> 3, wu0 = (rt & 7) * 4;
    // IDCT along W (parity accumulation): x[w]=E+O, x[63-w]=E-O
    float2 E[4][3], O[4][3];
#pragma unroll
    for (int i = 0; i < 4; i++)
#pragma unroll
        for (int j = 0; j < 3; j++) { E[i][j] = make_float2(0.f, 0.f); O[i][j] = make_float2(0.f, 0.f); }
#pragma unroll 2
    for (int m = 0; m < 32; m++) {
        float2 se[3], so[3];
#pragma unroll
        for (int j = 0; j < 3; j++) {
            se[j] = *(const float2*)&s[(line * 64 + 2 * m) * 98 + cc0 + 32 * j];
            so[j] = *(const float2*)&s[(line * 64 + 2 * m + 1) * 98 + cc0 + 32 * j];
        }
        float4 qe = *(const float4*)&cik[(2 * m) * 36 + wu0];
        float4 qo = *(const float4*)&cik[(2 * m + 1) * 36 + wu0];
        float ce[4] = {qe.x, qe.y, qe.z, qe.w};
        float co[4] = {qo.x, qo.y, qo.z, qo.w};
#pragma unroll
        for (int i = 0; i < 4; i++) {
            float2 cev = make_float2(ce[i], ce[i]);
            float2 cov = make_float2(co[i], co[i]);
#pragma unroll
            for (int j = 0; j < 3; j++) {
                E[i][j] = ffma2(cev, se[j], E[i][j]);
                O[i][j] = ffma2(cov, so[j], O[i][j]);
            }
        }
    }
    __syncthreads();
#pragma unroll
    for (int i = 0; i < 4; i++) {
        int w = wu0 + i;
#pragma unroll
        for (int j = 0; j < 3; j++) {
            float2 a, bq;
            a.x = E[i][j].x + O[i][j].x; a.y = E[i][j].y + O[i][j].y;
            bq.x = E[i][j].x - O[i][j].x; bq.y = E[i][j].y - O[i][j].y;
            *(float2*)&s[(line * 64 + w) * 98 + cc0 + 32 * j] = a;
            *(float2*)&s[(line * 64 + 63 - w) * 98 + cc0 + 32 * j] = bq;
        }
    }
    __syncthreads();
    // LayerNorm + gate in place; 8 warps x 16 rows
    {
        int wp = tid >> 5, lane = tid & 31;
        float g0 = lg[lane], g1 = lg[lane + 32], g2 = lg[lane + 64];
        float b0 = lbt[lane], b1 = lbt[lane + 32], b2 = lbt[lane + 64];
#pragma unroll
        for (int rr = 0; rr < 16; rr++) {
            int w = wp * 16 + rr;
            float x0 = s[w * 98 + lane], x1 = s[w * 98 + lane + 32], x2 = s[w * 98 + lane + 64];
            float sum = x0 + x1 + x2, q = x0 * x0 + x1 * x1 + x2 * x2;
#pragma unroll
            for (int o = 16; o > 0; o >>= 1) {
                sum += __shfl_xor_sync(0xffffffffu, sum, o);
                q   += __shfl_xor_sync(0xffffffffu, q, o);
            }
            float mean = sum * (1.f / 96.f);
            float var = q * (1.f / 96.f) - mean * mean;
            float rstd = rsqrtf(var + 1e-5f);
            long gr = (long)(r0 + w) * 96;
            s[w * 98 + lane]      = ((x0 - mean) * rstd * g0 + b0) * g_buf2[gr + lane];
            s[w * 98 + lane + 32] = ((x1 - mean) * rstd * g1 + b1) * g_buf2[gr + lane + 32];
            s[w * 98 + lane + 64] = ((x2 - mean) * rstd * g2 + b2) * g_buf2[gr + lane + 64];
        }
    }
    __syncthreads();
    // out GEMM: 8 rows x 6 cols per thread (scalar broadcast row loads)
    int rr0 = rt * 8;
    float2 acc[8][3];
#pragma unroll
    for (int i = 0; i < 8; i++)
#pragma unroll
        for (int j = 0; j < 3; j++) acc[i][j] = make_float2(0.f, 0.f);
#pragma unroll 4
    for (int k = 0; k < 96; k++) {
        float2 wv[3];
#pragma unroll
        for (int j = 0; j < 3; j++) wv[j] = *(const float2*)&ws[k * 96 + cc0 + 32 * j];
#pragma unroll
        for (int i = 0; i < 8; i++) {
            float x1 = s[(rr0 + i) * 98 + k];
            float2 xv = make_float2(x1, x1);
#pragma unroll
            for (int j = 0; j < 3; j++) acc[i][j] = ffma2(xv, wv[j], acc[i][j]);
        }
    }
    float2 obv[3];
#pragma unroll
    for (int j = 0; j < 3; j++) obv[j] = *(const float2*)&ob[cc0 + 32 * j];
    __syncthreads();           // GEMM reads of s done; reuse as os
#pragma unroll
    for (int i = 0; i < 8; i++)
#pragma unroll
        for (int j = 0; j < 3; j++) {
            int cc = cc0 + 32 * j;
            os[cc * 130 + rr0 + i]       = acc[i][j].x + obv[j].x;
            os[(cc + 1) * 130 + rr0 + i] = acc[i][j].y + obv[j].y;
        }
    __syncthreads();
    for (int i = tid; i < 12288; i += 256) {
        int cc = i >> 7, w = i & 127;
        outp[(long)b * BSTR + cc * 65536 + thw0 + w] = os[cc * 130 + w];
    }
}

extern "C" void kernel_launch(void* const* d_in, const int* in_sizes, int n_in,
                              void* d_out, int out_size) {
    const float* x   = (const float*)d_in[0];
    const float* fe  = (const float*)d_in[1];
    const float* dww = (const float*)d_in[2];
    const float* dwb = (const float*)d_in[3];
    const float* lw  = (const float*)d_in[4];
    const float* lb  = (const float*)d_in[5];
    const float* vw  = (const float*)d_in[6];
    const float* vb  = (const float*)d_in[7];
    const float* tw  = (const float*)d_in[8];
    const float* tb  = (const float*)d_in[9];
    const float* cc  = (const float*)d_in[10];
    const float* al  = (const float*)d_in[11];
    const float* lg  = (const float*)d_in[12];
    const float* lbt = (const float*)d_in[13];
    const float* ow  = (const float*)d_in[14];
    const float* ob  = (const float*)d_in[15];
    float* outp = (float*)d_out;

    size_t smCnv = (size_t)(6 * 34 * 66) * 4;           //  53856
    size_t smLin = (size_t)(12672 + 9408) * 4;          //  88320
    size_t smTau = (size_t)(12672 + 9216) * 4;          //  87552
    size_t smHf  = (size_t)(12800 + 2176) * 4;          //  59904
    size_t smHi  = (size_t)(12800 + 2304) * 4;          //  60416
    size_t smFus = (size_t)(9216 + 6144 + 6400 + 512) * 4; // 89088
    size_t smFin = (size_t)(12544 + 2304 + 9216) * 4;   //  96256
    cudaFuncSetAttribute(k_conv,   cudaFuncAttributeMaxDynamicSharedMemorySize, (int)smCnv);
    cudaFuncSetAttribute(k_lin,    cudaFuncAttributeMaxDynamicSharedMemorySize, (int)smLin);
    cudaFuncSetAttribute(k_tau,    cudaFuncAttributeMaxDynamicSharedMemorySize, (int)smTau);
    cudaFuncSetAttribute(k_dctHf,  cudaFuncAttributeMaxDynamicSharedMemorySize, (int)smHf);
    cudaFuncSetAttribute(k_dctHi,  cudaFuncAttributeMaxDynamicSharedMemorySize, (int)smHi);
    cudaFuncSetAttribute(k_fusedT, cudaFuncAttributeMaxDynamicSharedMemorySize, (int)smFus);
    cudaFuncSetAttribute(k_final,  cudaFuncAttributeMaxDynamicSharedMemorySize, (int)smFin);

    float *b1, *b3;
    cudaGetSymbolAddress((void**)&b1, g_buf1);
    cudaGetSymbolAddress((void**)&b3, g_buf3);

    k_init<<<181, 256>>>(lw, tw, vw, ow);
    k_conv<<<dim3(2, 4, 192), 256, smCnv>>>(x, dww, dwb);
    k_lin<<<1024, 512, smLin>>>(lb);                   // z+silu -> buf2; xg+DCT_W -> buf1
    k_tau<<<512, 256, smTau>>>(fe, tb, cc, al);
    k_dctHf<<<1024, 256, smHf>>>(b1, b3);              // DCT along H -> buf3
    k_fusedT<<<2048, 256, smFus>>>(b3, b1, vb);        // DCT_T + mix + IDCT_T -> buf1
    k_dctHi<<<1024, 256, smHi>>>(b1, b3);              // IDCT along H -> buf3
    k_final<<<1024, 256, smFin>>>(lg, lbt, ob, outp);  // IDCT_W + LN + gate + GEMM
}

// round 15
// speedup vs baseline: 1.2344x; 1.0281x over previous
#include <cuda_runtime.h>
#include <math.h>

#define NROW 131072            /* B*T*H*W */
#define BSTR 6291456           /* T*H*W*C */
#define TSTR 393216            /* H*W*C   */

__device__ float g_buf0[NROW * 96];
__device__ float g_buf1[NROW * 96];
__device__ float g_buf2[NROW * 96];
__device__ float g_buf3[NROW * 96];
__device__ float g_A [65536 * 96];
__device__ float g_Bc[65536 * 96];
__device__ float g_c64 [4096];     // [n][x]
__device__ float g_c64T[4096];     // [x][n]
__device__ float g_c16 [256];      // [n][x]
__device__ float g_c16T[256];      // [x][n]
__device__ float g_lwT[96 * 192];
__device__ float g_twT[96 * 96];
__device__ float g_vwT[96 * 96];
__device__ float g_owT[96 * 96];

// packed dual-fp32 FMA (FFMA2) — 2 FMAs per issue slot, exact fp32 rounding
__device__ __forceinline__ float2 ffma2(float2 a, float2 b, float2 c) {
    float2 d;
    asm("fma.rn.f32x2 %0, %1, %2, %3;"
        : "=l"(reinterpret_cast<unsigned long long&>(d))
        : "l"(reinterpret_cast<unsigned long long&>(a)),
          "l"(reinterpret_cast<unsigned long long&>(b)),
          "l"(reinterpret_cast<unsigned long long&>(c)));
    return d;
}

// ------------- merged init: weight transpose (blocks 0..179) + cos (180) ----
__global__ void __launch_bounds__(256) k_init(const float* __restrict__ lw,
                                              const float* __restrict__ tw,
                                              const float* __restrict__ vw,
                                              const float* __restrict__ ow) {
    int tid = threadIdx.x;
    if (blockIdx.x == 180) {
        const float PI = 3.14159265358979323846f;
        for (int i = tid; i < 4096; i += 256) {
            int n = i >> 6, xx = i & 63;
            float v = cosf((float)n * ((float)xx + 0.5f) * (PI / 64.0f)) * 0.17677669529663687f;
            if (n == 0) v *= 0.70710678118654752f;
            g_c64[n * 64 + xx] = v;
            g_c64T[xx * 64 + n] = v;
        }
        for (int i = tid; i < 256; i += 256) {
            int n = i >> 4, xx = i & 15;
            float v = cosf((float)n * ((float)xx + 0.5f) * (PI / 16.0f)) * 0.35355339059327373f;
            if (n == 0) v *= 0.70710678118654752f;
            g_c16[n * 16 + xx] = v;
            g_c16T[xx * 16 + n] = v;
        }
        return;
    }
    int i = blockIdx.x * 256 + tid;
    if (i < 18432) {
        int cc = i / 96, k = i - cc * 96;
        g_lwT[k * 192 + cc] = lw[i];
    } else if (i < 27648) {
        int j = i - 18432; int cc = j / 96, k = j - cc * 96;
        g_twT[k * 96 + cc] = tw[j];
    } else if (i < 36864) {
        int j = i - 27648; int cc = j / 96, k = j - cc * 96;
        g_vwT[k * 96 + cc] = vw[j];
    } else if (i < 46080) {
        int j = i - 36864; int cc = j / 96, k = j - cc * 96;
        g_owT[k * 96 + cc] = ow[j];
    }
}

// ------ depthwise 3x3x3 conv, 4 t-planes per block: x -> buf0[B,C,T,H,W] ----
__global__ void __launch_bounds__(256) k_conv(const float* __restrict__ x,
                                              const float* __restrict__ wt,
                                              const float* __restrict__ bs) {
    extern __shared__ float xs[];          // [6][34][66] = 13464
    int htile = blockIdx.x, tg = blockIdx.y, bc = blockIdx.z;
    int c = bc % 96;
    int tid = threadIdx.x;
    int h0 = htile * 32;
    for (int i = tid; i < 6 * 34 * 66; i += 256) {
        int p = i / 2244, rem = i - p * 2244;
        int hh = rem / 66, ww = rem - hh * 66;
        int th = tg * 4 - 1 + p, gh = h0 + hh - 1, gw = ww - 1;
        float v = 0.f;
        if ((unsigned)th < 16u && (unsigned)gh < 64u && (unsigned)gw < 64u)
            v = x[(bc * 16 + th) * 4096 + gh * 64 + gw];
        xs[i] = v;
    }
    float wr[27];
#pragma unroll
    for (int j = 0; j < 27; j++) wr[j] = wt[c * 27 + j];
    float bv = bs[c];
    __syncthreads();
    int wd = tid & 63, ht = tid >> 6;
#pragma unroll
    for (int tt = 0; tt < 4; tt++) {
#pragma unroll
        for (int j = 0; j < 8; j++) {
            int l = ht + j * 4;
            float acc = bv;
#pragma unroll
            for (int dt = 0; dt < 3; dt++)
#pragma unroll
                for (int dh = 0; dh < 3; dh++)
#pragma unroll
                    for (int dw = 0; dw < 3; dw++)
                        acc += wr[dt * 9 + dh * 3 + dw] *
                               xs[(tt + dt) * 2244 + (l + dh) * 66 + wd + dw];
            g_buf0[(bc * 16 + tg * 4 + tt) * 4096 + (h0 + l) * 64 + wd] = acc;
        }
    }
}

// ---------------- lin block body: z->silu->buf2, xg->bias->DCT_W->buf1 ------
__device__ __forceinline__ void lin_body(int blk, int tid, float* sm,
                                         const float* __restrict__ lb) {
    float* xs = sm;              // [96][132]=12672; phase3 reused as yx[128][98]
    float* ws = sm + 12672;      // [96][98] = 9408; phase3 reused as cfk[32][68]
    int r0 = blk * 128;
    int b = r0 >> 16, thw0 = r0 & 65535;
    for (int i = tid; i < 3072; i += 512) {
        int k = i >> 5, r4 = i & 31;
        *(float4*)&xs[k * 132 + r4 * 4] =
            *(const float4*)&g_buf0[(long)(b * 96 + k) * 65536 + thw0 + r4 * 4];
    }
    for (int i = tid; i < 9216; i += 512) {
        int k = i / 96, cc = i - k * 96;
        ws[k * 98 + cc] = g_lwT[k * 192 + 96 + cc];   // z half first
    }
    __syncthreads();
    int ct = tid & 15, rt = tid >> 4;        // rt 0..31
    int rr0 = rt * 4, cc0 = 2 * ct;
    // ---- phase 1: z GEMM + silu ----
    {
        float2 bv[3];
#pragma unroll
        for (int j = 0; j < 3; j++) bv[j] = *(const float2*)&lb[96 + cc0 + 32 * j];
        float2 acc[4][3];
#pragma unroll
        for (int i = 0; i < 4; i++)
#pragma unroll
            for (int j = 0; j < 3; j++) acc[i][j] = make_float2(0.f, 0.f);
#pragma unroll 4
        for (int k = 0; k < 96; k++) {
            float2 wv[3];
#pragma unroll
            for (int j = 0; j < 3; j++) wv[j] = *(const float2*)&ws[k * 98 + cc0 + 32 * j];
            float4 xq = *(const float4*)&xs[k * 132 + rr0];
            float xr[4] = {xq.x, xq.y, xq.z, xq.w};
#pragma unroll
            for (int i = 0; i < 4; i++) {
                float2 xv = make_float2(xr[i], xr[i]);
#pragma unroll
                for (int j = 0; j < 3; j++) acc[i][j] = ffma2(xv, wv[j], acc[i][j]);
            }
        }
#pragma unroll
        for (int i = 0; i < 4; i++)
#pragma unroll
            for (int j = 0; j < 3; j++) {
                float2 v = acc[i][j];
                v.x += bv[j].x; v.y += bv[j].y;
                float2 o;
                o.x = v.x / (1.f + __expf(-v.x));
                o.y = v.y / (1.f + __expf(-v.y));
                *(float2*)&g_buf2[(long)(r0 + rr0 + i) * 96 + cc0 + 32 * j] = o;
            }
    }
    __syncthreads();          // all phase-1 ws reads done
    for (int i = tid; i < 9216; i += 512) {
        int k = i / 96, cc = i - k * 96;
        ws[k * 98 + cc] = g_lwT[k * 192 + cc];        // xg half
    }
    __syncthreads();
    // ---- phase 2: xg GEMM + bias ----
    float2 acc[4][3];
#pragma unroll
    for (int i = 0; i < 4; i++)
#pragma unroll
        for (int j = 0; j < 3; j++) acc[i][j] = make_float2(0.f, 0.f);
#pragma unroll 4
    for (int k = 0; k < 96; k++) {
        float2 wv[3];
#pragma unroll
        for (int j = 0; j < 3; j++) wv[j] = *(const float2*)&ws[k * 98 + cc0 + 32 * j];
        float4 xq = *(const float4*)&xs[k * 132 + rr0];
        float xr[4] = {xq.x, xq.y, xq.z, xq.w};
#pragma unroll
        for (int i = 0; i < 4; i++) {
            float2 xv = make_float2(xr[i], xr[i]);
#pragma unroll
            for (int j = 0; j < 3; j++) acc[i][j] = ffma2(xv, wv[j], acc[i][j]);
        }
    }
    {
        float2 bv[3];
#pragma unroll
        for (int j = 0; j < 3; j++) bv[j] = *(const float2*)&lb[cc0 + 32 * j];
#pragma unroll
        for (int i = 0; i < 4; i++)
#pragma unroll
            for (int j = 0; j < 3; j++) {
                acc[i][j].x += bv[j].x; acc[i][j].y += bv[j].y;
            }
    }
    __syncthreads();          // xs fully read; reuse as yx[row][98]
#pragma unroll
    for (int i = 0; i < 4; i++)
#pragma unroll
        for (int j = 0; j < 3; j++)
            *(float2*)&xs[(rr0 + i) * 98 + cc0 + 32 * j] = acc[i][j];
    for (int i = tid; i < 2048; i += 512)
        ws[(i >> 6) * 68 + (i & 63)] = g_c64T[i];     // cfk[w][n], w<32
    __syncthreads();
    // e/o pre-pass in place
    for (int i = tid; i < 6144; i += 512) {
        int line = i / 3072, rem = i - line * 3072;
        int w = rem / 96, c = rem - w * 96;           // w < 32
        float* p1 = &xs[(line * 64 + w) * 98 + c];
        float* p2 = &xs[(line * 64 + 63 - w) * 98 + c];
        float y1 = *p1, y2 = *p2;
        *p1 = y1 + y2; *p2 = y1 - y2;
    }
    __syncthreads();
    // ---- phase 3: DCT along W (symmetric) ----
    int line = rt >> 4, wl = (rt & 15) * 4;
    float2 a2[4][3];
#pragma unroll
    for (int i = 0; i < 4; i++)
#pragma unroll
        for (int j = 0; j < 3; j++) a2[i][j] = make_float2(0.f, 0.f);
#pragma unroll 4
    for (int w = 0; w < 32; w++) {
        float2 ev[3], ov[3];
#pragma unroll
        for (int j = 0; j < 3; j++) {
            ev[j] = *(const float2*)&xs[(line * 64 + w) * 98 + cc0 + 32 * j];
            ov[j] = *(const float2*)&xs[(line * 64 + 63 - w) * 98 + cc0 + 32 * j];
        }
        float4 q = *(const float4*)&ws[w * 68 + wl];
        float2 c0v = make_float2(q.x, q.x), c1v = make_float2(q.y, q.y);
        float2 c2v = make_float2(q.z, q.z), c3v = make_float2(q.w, q.w);
#pragma unroll
        for (int j = 0; j < 3; j++) {
            a2[0][j] = ffma2(c0v, ev[j], a2[0][j]);
            a2[1][j] = ffma2(c1v, ov[j], a2[1][j]);
            a2[2][j] = ffma2(c2v, ev[j], a2[2][j]);
            a2[3][j] = ffma2(c3v, ov[j], a2[3][j]);
        }
    }
#pragma unroll
    for (int i = 0; i < 4; i++)
#pragma unroll
        for (int j = 0; j < 3; j++)
            *(float2*)&g_buf1[(long)(r0 + line * 64 + wl + i) * 96 + cc0 + 32 * j] = a2[i][j];
}

// ---------------- tau block body: 128 rows, 4x6 tile @ 512 threads ----------
__device__ __forceinline__ void tau_body(int blk, int tid, float* sm,
                                         const float* __restrict__ fe,
                                         const float* __restrict__ tb,
                                         float c0, float al) {
    float* xs = sm;               // [96][132]
    float* ws = sm + 12672;       // [96][96]
    int r0 = blk * 128;
    for (int i = tid; i < 12288; i += 512) {
        int r = i / 96, k = i - r * 96;
        xs[k * 132 + r] = fe[(long)(r0 + r) * 96 + k];
    }
    for (int i = tid; i < 9216; i += 512) ws[i] = g_twT[i];
    __syncthreads();
    int ct = tid & 15, rt = tid >> 4;
    int rr0 = rt * 4, cc0 = 2 * ct;
    float2 acc[4][3];
#pragma unroll
    for (int i = 0; i < 4; i++)
#pragma unroll
        for (int j = 0; j < 3; j++) acc[i][j] = make_float2(0.f, 0.f);
#pragma unroll 4
    for (int k = 0; k < 96; k++) {
        float2 wv[3];
#pragma unroll
        for (int j = 0; j < 3; j++) wv[j] = *(const float2*)&ws[k * 96 + cc0 + 32 * j];
        float4 q0 = *(const float4*)&xs[k * 132 + rr0];
        float xr[4] = {q0.x, q0.y, q0.z, q0.w};
#pragma unroll
        for (int i = 0; i < 4; i++) {
            float2 xv = make_float2(xr[i], xr[i]);
#pragma unroll
            for (int j = 0; j < 3; j++) acc[i][j] = ffma2(xv, wv[j], acc[i][j]);
        }
    }
#pragma unroll
    for (int i = 0; i < 4; i++) {
#pragma unroll
        for (int j = 0; j < 3; j++) {
            int cc = cc0 + 32 * j;
            float2 v = acc[i][j];
            v.x += tb[cc]; v.y += tb[cc + 1];
            float2 Av, Bv;
            {
                float g = 0.5f * v.x * (1.f + erff(v.x * 0.70710678118654752f));
                float si, co; __sincosf(c0 * g, &si, &co);
                float damp = __expf(-0.5f * al * g);
                float so = si / (c0 + 1e-8f);
                Av.x = damp * (co + so * al * 0.5f); Bv.x = damp * so;
            }
            {
                float g = 0.5f * v.y * (1.f + erff(v.y * 0.70710678118654752f));
                float si, co; __sincosf(c0 * g, &si, &co);
                float damp = __expf(-0.5f * al * g);
                float so = si / (c0 + 1e-8f);
                Av.y = damp * (co + so * al * 0.5f); Bv.y = damp * so;
            }
            long idx = (long)(r0 + rr0 + i) * 96 + cc;
            *(float2*)&g_A[idx]  = Av;
            *(float2*)&g_Bc[idx] = Bv;
        }
    }
}

// ----- combined launch: 1024 lin blocks + 512 tau blocks, interleaved 2:1 ---
__global__ void __launch_bounds__(512, 2) k_lintau(const float* __restrict__ lb,
                                                   const float* __restrict__ fe,
                                                   const float* __restrict__ tbp,
                                                   const float* __restrict__ cp,
                                                   const float* __restrict__ ap) {
    extern __shared__ float sm[];
    int bid = blockIdx.x;            // 0..1535
    int grp = bid / 3, rem = bid - grp * 3;
    int tid = threadIdx.x;
    if (rem < 2) {
        lin_body(grp * 2 + rem, tid, sm, lb);
    } else {
        tau_body(grp, tid, sm, fe, tbp, cp[0], ap[0]);
    }
}

// ---------- forward DCT along H (symmetric): 2 W-columns per block ----------
__global__ void __launch_bounds__(256) k_dctHf(const float* __restrict__ in,
                                               float* __restrict__ out) {
    extern __shared__ float sm[];
    float* xs  = sm;             // [2][64][100] = 12800 (e/o halves)
    float* cfk = sm + 12800;     // [32][68]: cfk[w][n] = c64[n][w], w<32
    int tid = threadIdx.x;
    for (int i = tid; i < 2048; i += 256) cfk[(i >> 6) * 68 + (i & 63)] = g_c64T[i];
    int outer = blockIdx.x >> 5;
    int wpair = blockIdx.x & 31;
    long obase = (long)outer * TSTR;
    for (int i = tid; i < 1536; i += 256) {
        int s = i / 768, rem = i - s * 768;
        int k = rem / 24, c4 = rem - k * 24;         // k < 32
        long rb = obase + (wpair * 2 + s) * 96 + c4 * 4;
        float4 v1 = *(const float4*)&in[rb + k * 6144];
        float4 v2 = *(const float4*)&in[rb + (63 - k) * 6144];
        float4 e, o;
        e.x = v1.x + v2.x; e.y = v1.y + v2.y; e.z = v1.z + v2.z; e.w = v1.w + v2.w;
        o.x = v1.x - v2.x; o.y = v1.y - v2.y; o.z = v1.z - v2.z; o.w = v1.w - v2.w;
        *(float4*)&xs[(s * 64 + k) * 100 + c4 * 4] = e;
        *(float4*)&xs[(s * 64 + 63 - k) * 100 + c4 * 4] = o;
    }
    __syncthreads();
    int ct = tid & 15, rt = tid >> 4;
    int cc0 = 2 * ct;
    int slab = rt >> 3, n0 = (rt & 7) * 8;
    float2 acc[8][3];
#pragma unroll
    for (int i = 0; i < 8; i++)
#pragma unroll
        for (int j = 0; j < 3; j++) acc[i][j] = make_float2(0.f, 0.f);
#pragma unroll 4
    for (int k = 0; k < 32; k++) {
        float2 ev[3], ov[3];
#pragma unroll
        for (int j = 0; j < 3; j++) {
            ev[j] = *(const float2*)&xs[(slab * 64 + k) * 100 + cc0 + 32 * j];
            ov[j] = *(const float2*)&xs[(slab * 64 + 63 - k) * 100 + cc0 + 32 * j];
        }
        float4 q0 = *(const float4*)&cfk[k * 68 + n0];
        float4 q1 = *(const float4*)&cfk[k * 68 + n0 + 4];
        float cr[8] = {q0.x, q0.y, q0.z, q0.w, q1.x, q1.y, q1.z, q1.w};
#pragma unroll
        for (int i = 0; i < 8; i++) {
            float2 cv = make_float2(cr[i], cr[i]);
            float2* src = (i & 1) ? ov : ev;         // parity of n0+i = parity of i
#pragma unroll
            for (int j = 0; j < 3; j++) acc[i][j] = ffma2(cv, src[j], acc[i][j]);
        }
    }
    long sbase = obase + (wpair * 2 + slab) * 96;
#pragma unroll
    for (int i = 0; i < 8; i++)
#pragma unroll
        for (int j = 0; j < 3; j++)
            *(float2*)&out[sbase + (n0 + i) * 6144 + cc0 + 32 * j] = acc[i][j];
}

// ---------- inverse DCT along H (parity accum): 2 W-columns per block -------
__global__ void __launch_bounds__(256) k_dctHi(const float* __restrict__ in,
                                               float* __restrict__ out) {
    extern __shared__ float sm[];
    float* xs  = sm;             // [2][64][100] = 12800
    float* cik = sm + 12800;     // [64][36]: cik[n][w] = c64[n][w], w<32
    int tid = threadIdx.x;
    for (int i = tid; i < 2048; i += 256) {
        int n = i >> 5, w = i & 31;
        cik[n * 36 + w] = g_c64[n * 64 + w];
    }
    int outer = blockIdx.x >> 5;
    int wpair = blockIdx.x & 31;
    long obase = (long)outer * TSTR;
    for (int i = tid; i < 3072; i += 256) {
        int s = i / 1536, rem = i - s * 1536;
        int k = rem / 24, c4 = rem - k * 24;
        float4 v = *(const float4*)&in[obase + (wpair * 2 + s) * 96 + k * 6144 + c4 * 4];
        *(float4*)&xs[(s * 64 + k) * 100 + c4 * 4] = v;
    }
    __syncthreads();
    int ct = tid & 15, rt = tid >> 4;
    int cc0 = 2 * ct;
    int slab = rt >> 3, wu0 = (rt & 7) * 4;          // 4 w-units -> 8 outputs
    float2 E[4][3], O[4][3];
#pragma unroll
    for (int i = 0; i < 4; i++)
#pragma unroll
        for (int j = 0; j < 3; j++) { E[i][j] = make_float2(0.f, 0.f); O[i][j] = make_float2(0.f, 0.f); }
#pragma unroll 2
    for (int m = 0; m < 32; m++) {
        float2 se[3], so[3];
#pragma unroll
        for (int j = 0; j < 3; j++) {
            se[j] = *(const float2*)&xs[(slab * 64 + 2 * m) * 100 + cc0 + 32 * j];
            so[j] = *(const float2*)&xs[(slab * 64 + 2 * m + 1) * 100 + cc0 + 32 * j];
        }
        float4 qe = *(const float4*)&cik[(2 * m) * 36 + wu0];
        float4 qo = *(const float4*)&cik[(2 * m + 1) * 36 + wu0];
        float ce[4] = {qe.x, qe.y, qe.z, qe.w};
        float co[4] = {qo.x, qo.y, qo.z, qo.w};
#pragma unroll
        for (int i = 0; i < 4; i++) {
            float2 cev = make_float2(ce[i], ce[i]);
            float2 cov = make_float2(co[i], co[i]);
#pragma unroll
            for (int j = 0; j < 3; j++) {
                E[i][j] = ffma2(cev, se[j], E[i][j]);
                O[i][j] = ffma2(cov, so[j], O[i][j]);
            }
        }
    }
    long sbase = obase + (wpair * 2 + slab) * 96;
#pragma unroll
    for (int i = 0; i < 4; i++) {
        int w = wu0 + i;
#pragma unroll
        for (int j = 0; j < 3; j++) {
            float2 a, bq;
            a.x = E[i][j].x + O[i][j].x; a.y = E[i][j].y + O[i][j].y;
            bq.x = E[i][j].x - O[i][j].x; bq.y = E[i][j].y - O[i][j].y;
            *(float2*)&out[sbase + w * 6144 + cc0 + 32 * j] = a;
            *(float2*)&out[sbase + (63 - w) * 6144 + cc0 + 32 * j] = bq;
        }
    }
}

// ---- fused: DCT_T + v0 mix + spectral combine + IDCT_T, 4 hw/block ---------
__global__ void __launch_bounds__(256) k_fusedT(const float* __restrict__ in,
                                                float* __restrict__ out,
                                                const float* __restrict__ vb) {
    extern __shared__ float sm[];
    float* wsm = sm;             // [96][96] = 9216
    float* x16 = sm + 9216;      // [4][16][96] = 6144 (reused as vs)
    float* u0  = x16 + 6144;     // [64][100] = 6400
    float* cA  = u0 + 6400;      // [16][16]: cA[t][n] = c16[n][t]  (fwd)
    float* cC  = cA + 256;       // [16][16]: cC[n][t] = c16[n][t]  (inv)
    int tid = threadIdx.x;
    int b = blockIdx.x >> 10, hw0 = (blockIdx.x & 1023) * 4;
    for (int i = tid; i < 9216; i += 256) wsm[i] = g_vwT[i];
    cA[tid] = g_c16T[tid];
    cC[tid] = g_c16[tid];
    for (int i = tid; i < 1536; i += 256) {
        int s = i / 384, rem = i - s * 384;
        int t = rem / 24, c4 = rem - t * 24;
        *(float4*)&x16[(s * 16 + t) * 96 + c4 * 4] =
            *(const float4*)&in[(long)b * BSTR + (hw0 + s) * 96 + t * TSTR + c4 * 4];
    }
    __syncthreads();
    int ct = tid & 15, rt = tid >> 4;
    int cc0 = 2 * ct;
    int slab = rt >> 2, q4 = (rt & 3) * 4;   // rows within slab
    int hw = hw0 + slab;
    // ---- phase A: forward DCT along T (4 freq rows x 6 ch) ----
    {
        float2 a[4][3];
#pragma unroll
        for (int i = 0; i < 4; i++)
#pragma unroll
            for (int j = 0; j < 3; j++) a[i][j] = make_float2(0.f, 0.f);
#pragma unroll
        for (int t = 0; t < 16; t++) {
            float2 xv[3];
#pragma unroll
            for (int j = 0; j < 3; j++)
                xv[j] = *(const float2*)&x16[(slab * 16 + t) * 96 + cc0 + 32 * j];
            float4 q = *(const float4*)&cA[t * 16 + q4];
            float cr[4] = {q.x, q.y, q.z, q.w};
#pragma unroll
            for (int i = 0; i < 4; i++) {
                float2 cv = make_float2(cr[i], cr[i]);
#pragma unroll
                for (int j = 0; j < 3; j++) a[i][j] = ffma2(cv, xv[j], a[i][j]);
            }
        }
#pragma unroll
        for (int i = 0; i < 4; i++)
#pragma unroll
            for (int j = 0; j < 3; j++)
                *(float2*)&u0[(slab * 16 + q4 + i) * 100 + cc0 + 32 * j] = a[i][j];
    }
    __syncthreads();
    // ---- phase B: v0 mix + spectral combine -> vs (x16 region) ----
    {
        float2 Av[4][3], Bv[4][3];
#pragma unroll
        for (int i = 0; i < 4; i++)
#pragma unroll
            for (int j = 0; j < 3; j++) {
                long gi = ((long)(q4 + i) * 4096 + hw) * 96 + cc0 + 32 * j;
                Av[i][j] = *(const float2*)&g_A[gi];
                Bv[i][j] = *(const float2*)&g_Bc[gi];
            }
        float2 v[4][3];
#pragma unroll
        for (int i = 0; i < 4; i++)
#pragma unroll
            for (int j = 0; j < 3; j++) v[i][j] = make_float2(0.f, 0.f);
#pragma unroll 4
        for (int k = 0; k < 96; k++) {
            float2 wv[3];
#pragma unroll
            for (int j = 0; j < 3; j++) wv[j] = *(const float2*)&wsm[k * 96 + cc0 + 32 * j];
#pragma unroll
            for (int i = 0; i < 4; i++) {
                float u1 = u0[(slab * 16 + q4 + i) * 100 + k];
                float2 uv = make_float2(u1, u1);
#pragma unroll
                for (int j = 0; j < 3; j++) v[i][j] = ffma2(uv, wv[j], v[i][j]);
            }
        }
        if (hw0 == 0 && rt == 0) {   // DC (t=0,h=0,w=0) of constant v0_b field
#pragma unroll
            for (int j = 0; j < 3; j++) {
                v[0][j].x += 256.f * vb[cc0 + 32 * j];
                v[0][j].y += 256.f * vb[cc0 + 32 * j + 1];
            }
        }
        __syncthreads();   // u0 reads done by all; x16 region becomes vs
#pragma unroll
        for (int i = 0; i < 4; i++)
#pragma unroll
            for (int j = 0; j < 3; j++) {
                float2 uu = *(const float2*)&u0[(slab * 16 + q4 + i) * 100 + cc0 + 32 * j];
                float2 r;
                r.x = Av[i][j].x * uu.x + Bv[i][j].x * v[i][j].x;
                r.y = Av[i][j].y * uu.y + Bv[i][j].y * v[i][j].y;
                *(float2*)&x16[(slab * 16 + q4 + i) * 96 + cc0 + 32 * j] = r;
            }
    }
    __syncthreads();
    // ---- phase C: inverse DCT along T (4 time rows x 6 ch) ----
    {
        float2 y[4][3];
#pragma unroll
        for (int i = 0; i < 4; i++)
#pragma unroll
            for (int j = 0; j < 3; j++) y[i][j] = make_float2(0.f, 0.f);
#pragma unroll
        for (int n = 0; n < 16; n++) {
            float2 sv[3];
#pragma unroll
            for (int j = 0; j < 3; j++)
                sv[j] = *(const float2*)&x16[(slab * 16 + n) * 96 + cc0 + 32 * j];
            float4 q = *(const float4*)&cC[n * 16 + q4];
            float cr[4] = {q.x, q.y, q.z, q.w};
#pragma unroll
            for (int i = 0; i < 4; i++) {
                float2 cv = make_float2(cr[i], cr[i]);
#pragma unroll
                for (int j = 0; j < 3; j++) y[i][j] = ffma2(cv, sv[j], y[i][j]);
            }
        }
#pragma unroll
        for (int i = 0; i < 4; i++)
#pragma unroll
            for (int j = 0; j < 3; j++)
                *(float2*)&out[(long)b * BSTR + hw * 96 + (q4 + i) * TSTR + cc0 + 32 * j] = y[i][j];
    }
}

// ---- final: IDCT_W(sym) + LN + gate + out GEMM + transpose store -----------
__global__ void __launch_bounds__(256) k_final(const float* __restrict__ lg,
                                               const float* __restrict__ lbt,
                                               const float* __restrict__ ob,
                                               float* __restrict__ outp) {
    extern __shared__ float sm[];
    float* s   = sm;             // [128][98] = 12544 (freq -> spatial/LN'd -> os)
    float* cik = sm + 12544;     // [64][36]: cik[n][w] = c64[n][w], w<32
    float* ws  = cik + 2304;     // [96][96] = 9216
    float* os  = sm;             // reuse s: [96][130] = 12480
    int tid = threadIdx.x;
    int r0 = blockIdx.x * 128;
    int b = r0 >> 16, thw0 = r0 & 65535;
    for (int i = tid; i < 12288; i += 256) {
        int n = i / 96, c = i - n * 96;
        s[n * 98 + c] = g_buf3[(long)r0 * 96 + i];
    }
    for (int i = tid; i < 2048; i += 256) {
        int n = i >> 5, w = i & 31;
        cik[n * 36 + w] = g_c64[n * 64 + w];
    }
    for (int i = tid; i < 9216; i += 256) ws[i] = g_owT[i];
    __syncthreads();
    int ct = tid & 15, rt = tid >> 4;
    int cc0 = 2 * ct;
    int line = rt >> 3, wu0 = (rt & 7) * 4;
    // IDCT along W (parity accumulation): x[w]=E+O, x[63-w]=E-O
    float2 E[4][3], O[4][3];
#pragma unroll
    for (int i = 0; i < 4; i++)
#pragma unroll
        for (int j = 0; j < 3; j++) { E[i][j] = make_float2(0.f, 0.f); O[i][j] = make_float2(0.f, 0.f); }
#pragma unroll 2
    for (int m = 0; m < 32; m++) {
        float2 se[3], so[3];
#pragma unroll
        for (int j = 0; j < 3; j++) {
            se[j] = *(const float2*)&s[(line * 64 + 2 * m) * 98 + cc0 + 32 * j];
            so[j] = *(const float2*)&s[(line * 64 + 2 * m + 1) * 98 + cc0 + 32 * j];
        }
        float4 qe = *(const float4*)&cik[(2 * m) * 36 + wu0];
        float4 qo = *(const float4*)&cik[(2 * m + 1) * 36 + wu0];
        float ce[4] = {qe.x, qe.y, qe.z, qe.w};
        float co[4] = {qo.x, qo.y, qo.z, qo.w};
#pragma unroll
        for (int i = 0; i < 4; i++) {
            float2 cev = make_float2(ce[i], ce[i]);
            float2 cov = make_float2(co[i], co[i]);
#pragma unroll
            for (int j = 0; j < 3; j++) {
                E[i][j] = ffma2(cev, se[j], E[i][j]);
                O[i][j] = ffma2(cov, so[j], O[i][j]);
            }
        }
    }
    __syncthreads();
#pragma unroll
    for (int i = 0; i < 4; i++) {
        int w = wu0 + i;
#pragma unroll
        for (int j = 0; j < 3; j++) {
            float2 a, bq;
            a.x = E[i][j].x + O[i][j].x; a.y = E[i][j].y + O[i][j].y;
            bq.x = E[i][j].x - O[i][j].x; bq.y = E[i][j].y - O[i][j].y;
            *(float2*)&s[(line * 64 + w) * 98 + cc0 + 32 * j] = a;
            *(float2*)&s[(line * 64 + 63 - w) * 98 + cc0 + 32 * j] = bq;
        }
    }
    __syncthreads();
    // LayerNorm + gate in place; 8 warps x 16 rows
    {
        int wp = tid >> 5, lane = tid & 31;
        float g0 = lg[lane], g1 = lg[lane + 32], g2 = lg[lane + 64];
        float b0 = lbt[lane], b1 = lbt[lane + 32], b2 = lbt[lane + 64];
#pragma unroll
        for (int rr = 0; rr < 16; rr++) {
            int w = wp * 16 + rr;
            float x0 = s[w * 98 + lane], x1 = s[w * 98 + lane + 32], x2 = s[w * 98 + lane + 64];
            float sum = x0 + x1 + x2, q = x0 * x0 + x1 * x1 + x2 * x2;
#pragma unroll
            for (int o = 16; o > 0; o >>= 1) {
                sum += __shfl_xor_sync(0xffffffffu, sum, o);
                q   += __shfl_xor_sync(0xffffffffu, q, o);
            }
            float mean = sum * (1.f / 96.f);
            float var = q * (1.f / 96.f) - mean * mean;
            float rstd = rsqrtf(var + 1e-5f);
            long gr = (long)(r0 + w) * 96;
            s[w * 98 + lane]      = ((x0 - mean) * rstd * g0 + b0) * g_buf2[gr + lane];
            s[w * 98 + lane + 32] = ((x1 - mean) * rstd * g1 + b1) * g_buf2[gr + lane + 32];
            s[w * 98 + lane + 64] = ((x2 - mean) * rstd * g2 + b2) * g_buf2[gr + lane + 64];
        }
    }
    __syncthreads();
    // out GEMM: 8 rows x 6 cols per thread (scalar broadcast row loads)
    int rr0 = rt * 8;
    float2 acc[8][3];
#pragma unroll
    for (int i = 0; i < 8; i++)
#pragma unroll
        for (int j = 0; j < 3; j++) acc[i][j] = make_float2(0.f, 0.f);
#pragma unroll 4
    for (int k = 0; k < 96; k++) {
        float2 wv[3];
#pragma unroll
        for (int j = 0; j < 3; j++) wv[j] = *(const float2*)&ws[k * 96 + cc0 + 32 * j];
#pragma unroll
        for (int i = 0; i < 8; i++) {
            float x1 = s[(rr0 + i) * 98 + k];
            float2 xv = make_float2(x1, x1);
#pragma unroll
            for (int j = 0; j < 3; j++) acc[i][j] = ffma2(xv, wv[j], acc[i][j]);
        }
    }
    float2 obv[3];
#pragma unroll
    for (int j = 0; j < 3; j++) obv[j] = *(const float2*)&ob[cc0 + 32 * j];
    __syncthreads();           // GEMM reads of s done; reuse as os
#pragma unroll
    for (int i = 0; i < 8; i++)
#pragma unroll
        for (int j = 0; j < 3; j++) {
            int cc = cc0 + 32 * j;
            os[cc * 130 + rr0 + i]       = acc[i][j].x + obv[j].x;
            os[(cc + 1) * 130 + rr0 + i] = acc[i][j].y + obv[j].y;
        }
    __syncthreads();
    for (int i = tid; i < 12288; i += 256) {
        int cc = i >> 7, w = i & 127;
        outp[(long)b * BSTR + cc * 65536 + thw0 + w] = os[cc * 130 + w];
    }
}

extern "C" void kernel_launch(void* const* d_in, const int* in_sizes, int n_in,
                              void* d_out, int out_size) {
    const float* x   = (const float*)d_in[0];
    const float* fe  = (const float*)d_in[1];
    const float* dww = (const float*)d_in[2];
    const float* dwb = (const float*)d_in[3];
    const float* lw  = (const float*)d_in[4];
    const float* lb  = (const float*)d_in[5];
    const float* vw  = (const float*)d_in[6];
    const float* vb  = (const float*)d_in[7];
    const float* tw  = (const float*)d_in[8];
    const float* tb  = (const float*)d_in[9];
    const float* cc  = (const float*)d_in[10];
    const float* al  = (const float*)d_in[11];
    const float* lg  = (const float*)d_in[12];
    const float* lbt = (const float*)d_in[13];
    const float* ow  = (const float*)d_in[14];
    const float* ob  = (const float*)d_in[15];
    float* outp = (float*)d_out;

    size_t smCnv = (size_t)(6 * 34 * 66) * 4;           //  53856
    size_t smLT  = (size_t)(12672 + 9408) * 4;          //  88320 (max of lin/tau)
    size_t smHf  = (size_t)(12800 + 2176) * 4;          //  59904
    size_t smHi  = (size_t)(12800 + 2304) * 4;          //  60416
    size_t smFus = (size_t)(9216 + 6144 + 6400 + 512) * 4; // 89088
    size_t smFin = (size_t)(12544 + 2304 + 9216) * 4;   //  96256
    cudaFuncSetAttribute(k_conv,   cudaFuncAttributeMaxDynamicSharedMemorySize, (int)smCnv);
    cudaFuncSetAttribute(k_lintau, cudaFuncAttributeMaxDynamicSharedMemorySize, (int)smLT);
    cudaFuncSetAttribute(k_dctHf,  cudaFuncAttributeMaxDynamicSharedMemorySize, (int)smHf);
    cudaFuncSetAttribute(k_dctHi,  cudaFuncAttributeMaxDynamicSharedMemorySize, (int)smHi);
    cudaFuncSetAttribute(k_fusedT, cudaFuncAttributeMaxDynamicSharedMemorySize, (int)smFus);
    cudaFuncSetAttribute(k_final,  cudaFuncAttributeMaxDynamicSharedMemorySize, (int)smFin);

    float *b1, *b3;
    cudaGetSymbolAddress((void**)&b1, g_buf1);
    cudaGetSymbolAddress((void**)&b3, g_buf3);

    k_init<<<181, 256>>>(lw, tw, vw, ow);
    k_conv<<<dim3(2, 4, 192), 256, smCnv>>>(x, dww, dwb);
    k_lintau<<<1536, 512, smLT>>>(lb, fe, tb, cc, al); // lin + tau concurrent
    k_dctHf<<<1024, 256, smHf>>>(b1, b3);              // DCT along H -> buf3
    k_fusedT<<<2048, 256, smFus>>>(b3, b1, vb);        // DCT_T + mix + IDCT_T -> buf1
    k_dctHi<<<1024, 256, smHi>>>(b1, b3);              // IDCT along H -> buf3
    k_final<<<1024, 256, smFin>>>(lg, lbt, ob, outp);  // IDCT_W + LN + gate + GEMM
}

// round 16
// speedup vs baseline: 1.2807x; 1.0375x over previous
#include <cuda_runtime.h>
#include <math.h>

#define NROW 131072            /* B*T*H*W */
#define BSTR 6291456           /* T*H*W*C */
#define TSTR 393216            /* H*W*C   */

__device__ float g_buf0[NROW * 96];
__device__ float g_buf1[NROW * 96];
__device__ float g_buf2[NROW * 96];
__device__ float g_buf3[NROW * 96];
__device__ float g_A [65536 * 96];
__device__ float g_Bc[65536 * 96];
__device__ float g_c64 [4096];     // [n][x]
__device__ float g_c64T[4096];     // [x][n]
__device__ float g_c16 [256];      // [n][x]
__device__ float g_c16T[256];      // [x][n]
__device__ float g_lwT[96 * 192];
__device__ float g_twT[96 * 96];
__device__ float g_vwT[96 * 96];
__device__ float g_owT[96 * 96];

// packed dual-fp32 FMA (FFMA2) — 2 FMAs per issue slot, exact fp32 rounding
__device__ __forceinline__ float2 ffma2(float2 a, float2 b, float2 c) {
    float2 d;
    asm("fma.rn.f32x2 %0, %1, %2, %3;"
        : "=l"(reinterpret_cast<unsigned long long&>(d))
        : "l"(reinterpret_cast<unsigned long long&>(a)),
          "l"(reinterpret_cast<unsigned long long&>(b)),
          "l"(reinterpret_cast<unsigned long long&>(c)));
    return d;
}

// ------------- merged init: weight transpose (blocks 0..179) + cos (180) ----
__global__ void __launch_bounds__(256) k_init(const float* __restrict__ lw,
                                              const float* __restrict__ tw,
                                              const float* __restrict__ vw,
                                              const float* __restrict__ ow) {
    int tid = threadIdx.x;
    if (blockIdx.x == 180) {
        const float PI = 3.14159265358979323846f;
        for (int i = tid; i < 4096; i += 256) {
            int n = i >> 6, xx = i & 63;
            float v = cosf((float)n * ((float)xx + 0.5f) * (PI / 64.0f)) * 0.17677669529663687f;
            if (n == 0) v *= 0.70710678118654752f;
            g_c64[n * 64 + xx] = v;
            g_c64T[xx * 64 + n] = v;
        }
        for (int i = tid; i < 256; i += 256) {
            int n = i >> 4, xx = i & 15;
            float v = cosf((float)n * ((float)xx + 0.5f) * (PI / 16.0f)) * 0.35355339059327373f;
            if (n == 0) v *= 0.70710678118654752f;
            g_c16[n * 16 + xx] = v;
            g_c16T[xx * 16 + n] = v;
        }
        return;
    }
    int i = blockIdx.x * 256 + tid;
    if (i < 18432) {
        int cc = i / 96, k = i - cc * 96;
        g_lwT[k * 192 + cc] = lw[i];
    } else if (i < 27648) {
        int j = i - 18432; int cc = j / 96, k = j - cc * 96;
        g_twT[k * 96 + cc] = tw[j];
    } else if (i < 36864) {
        int j = i - 27648; int cc = j / 96, k = j - cc * 96;
        g_vwT[k * 96 + cc] = vw[j];
    } else if (i < 46080) {
        int j = i - 36864; int cc = j / 96, k = j - cc * 96;
        g_owT[k * 96 + cc] = ow[j];
    }
}

// ------ depthwise 3x3x3 conv, 4 t-planes per block: x -> buf0[B,C,T,H,W] ----
__global__ void __launch_bounds__(256) k_conv(const float* __restrict__ x,
                                              const float* __restrict__ wt,
                                              const float* __restrict__ bs) {
    extern __shared__ float xs[];          // [6][34][66] = 13464
    int htile = blockIdx.x, tg = blockIdx.y, bc = blockIdx.z;
    int c = bc % 96;
    int tid = threadIdx.x;
    int h0 = htile * 32;
    for (int i = tid; i < 6 * 34 * 66; i += 256) {
        int p = i / 2244, rem = i - p * 2244;
        int hh = rem / 66, ww = rem - hh * 66;
        int th = tg * 4 - 1 + p, gh = h0 + hh - 1, gw = ww - 1;
        float v = 0.f;
        if ((unsigned)th < 16u && (unsigned)gh < 64u && (unsigned)gw < 64u)
            v = x[(bc * 16 + th) * 4096 + gh * 64 + gw];
        xs[i] = v;
    }
    float wr[27];
#pragma unroll
    for (int j = 0; j < 27; j++) wr[j] = wt[c * 27 + j];
    float bv = bs[c];
    __syncthreads();
    int wd = tid & 63, ht = tid >> 6;
#pragma unroll
    for (int tt = 0; tt < 4; tt++) {
#pragma unroll
        for (int j = 0; j < 8; j++) {
            int l = ht + j * 4;
            float acc = bv;
#pragma unroll
            for (int dt = 0; dt < 3; dt++)
#pragma unroll
                for (int dh = 0; dh < 3; dh++)
#pragma unroll
                    for (int dw = 0; dw < 3; dw++)
                        acc += wr[dt * 9 + dh * 3 + dw] *
                               xs[(tt + dt) * 2244 + (l + dh) * 66 + wd + dw];
            g_buf0[(bc * 16 + tg * 4 + tt) * 4096 + (h0 + l) * 64 + wd] = acc;
        }
    }
}

// ---------------- lin block body: z->silu->buf2, xg->bias->DCT_W->buf1 ------
__device__ __forceinline__ void lin_body(int blk, int tid, float* sm,
                                         const float* __restrict__ lb) {
    float* xs = sm;              // [96][132]=12672; phase3 reused as yx[128][98]
    float* ws = sm + 12672;      // [96][100] = 9600; phase3 reused as cfk[32][68]
    int r0 = blk * 128;
    int b = r0 >> 16, thw0 = r0 & 65535;
    for (int i = tid; i < 3072; i += 512) {
        int k = i >> 5, r4 = i & 31;
        *(float4*)&xs[k * 132 + r4 * 4] =
            *(const float4*)&g_buf0[(long)(b * 96 + k) * 65536 + thw0 + r4 * 4];
    }
    for (int i = tid; i < 2304; i += 512) {
        int k = i / 24, c4 = i - k * 24;
        *(float4*)&ws[k * 100 + c4 * 4] =
            *(const float4*)&g_lwT[k * 192 + 96 + c4 * 4];   // z half first
    }
    __syncthreads();
    int ct = tid & 15, rt = tid >> 4;        // rt 0..31
    int rr0 = rt * 4, cc0 = 2 * ct;
    // ---- phase 1: z GEMM + silu ----
    {
        float2 bv[3];
#pragma unroll
        for (int j = 0; j < 3; j++) bv[j] = *(const float2*)&lb[96 + cc0 + 32 * j];
        float2 acc[4][3];
#pragma unroll
        for (int i = 0; i < 4; i++)
#pragma unroll
            for (int j = 0; j < 3; j++) acc[i][j] = make_float2(0.f, 0.f);
#pragma unroll 4
        for (int k = 0; k < 96; k++) {
            float2 wv[3];
#pragma unroll
            for (int j = 0; j < 3; j++) wv[j] = *(const float2*)&ws[k * 100 + cc0 + 32 * j];
            float4 xq = *(const float4*)&xs[k * 132 + rr0];
            float xr[4] = {xq.x, xq.y, xq.z, xq.w};
#pragma unroll
            for (int i = 0; i < 4; i++) {
                float2 xv = make_float2(xr[i], xr[i]);
#pragma unroll
                for (int j = 0; j < 3; j++) acc[i][j] = ffma2(xv, wv[j], acc[i][j]);
            }
        }
#pragma unroll
        for (int i = 0; i < 4; i++)
#pragma unroll
            for (int j = 0; j < 3; j++) {
                float2 v = acc[i][j];
                v.x += bv[j].x; v.y += bv[j].y;
                float2 o;
                o.x = v.x / (1.f + __expf(-v.x));
                o.y = v.y / (1.f + __expf(-v.y));
                *(float2*)&g_buf2[(long)(r0 + rr0 + i) * 96 + cc0 + 32 * j] = o;
            }
    }
    __syncthreads();          // all phase-1 ws reads done
    for (int i = tid; i < 2304; i += 512) {
        int k = i / 24, c4 = i - k * 24;
        *(float4*)&ws[k * 100 + c4 * 4] =
            *(const float4*)&g_lwT[k * 192 + c4 * 4];        // xg half
    }
    __syncthreads();
    // ---- phase 2: xg GEMM + bias ----
    float2 acc[4][3];
#pragma unroll
    for (int i = 0; i < 4; i++)
#pragma unroll
        for (int j = 0; j < 3; j++) acc[i][j] = make_float2(0.f, 0.f);
#pragma unroll 4
    for (int k = 0; k < 96; k++) {
        float2 wv[3];
#pragma unroll
        for (int j = 0; j < 3; j++) wv[j] = *(const float2*)&ws[k * 100 + cc0 + 32 * j];
        float4 xq = *(const float4*)&xs[k * 132 + rr0];
        float xr[4] = {xq.x, xq.y, xq.z, xq.w};
#pragma unroll
        for (int i = 0; i < 4; i++) {
            float2 xv = make_float2(xr[i], xr[i]);
#pragma unroll
            for (int j = 0; j < 3; j++) acc[i][j] = ffma2(xv, wv[j], acc[i][j]);
        }
    }
    {
        float2 bv[3];
#pragma unroll
        for (int j = 0; j < 3; j++) bv[j] = *(const float2*)&lb[cc0 + 32 * j];
#pragma unroll
        for (int i = 0; i < 4; i++)
#pragma unroll
            for (int j = 0; j < 3; j++) {
                acc[i][j].x += bv[j].x; acc[i][j].y += bv[j].y;
            }
    }
    __syncthreads();          // xs fully read; reuse as yx[row][98]
#pragma unroll
    for (int i = 0; i < 4; i++)
#pragma unroll
        for (int j = 0; j < 3; j++)
            *(float2*)&xs[(rr0 + i) * 98 + cc0 + 32 * j] = acc[i][j];
    for (int i = tid; i < 2048; i += 512)
        ws[(i >> 6) * 68 + (i & 63)] = g_c64T[i];     // cfk[w][n], w<32
    __syncthreads();
    // e/o pre-pass in place
    for (int i = tid; i < 6144; i += 512) {
        int line = i / 3072, rem = i - line * 3072;
        int w = rem / 96, c = rem - w * 96;           // w < 32
        float* p1 = &xs[(line * 64 + w) * 98 + c];
        float* p2 = &xs[(line * 64 + 63 - w) * 98 + c];
        float y1 = *p1, y2 = *p2;
        *p1 = y1 + y2; *p2 = y1 - y2;
    }
    __syncthreads();
    // ---- phase 3: DCT along W (symmetric) ----
    int line = rt >> 4, wl = (rt & 15) * 4;
    float2 a2[4][3];
#pragma unroll
    for (int i = 0; i < 4; i++)
#pragma unroll
        for (int j = 0; j < 3; j++) a2[i][j] = make_float2(0.f, 0.f);
#pragma unroll 4
    for (int w = 0; w < 32; w++) {
        float2 ev[3], ov[3];
#pragma unroll
        for (int j = 0; j < 3; j++) {
            ev[j] = *(const float2*)&xs[(line * 64 + w) * 98 + cc0 + 32 * j];
            ov[j] = *(const float2*)&xs[(line * 64 + 63 - w) * 98 + cc0 + 32 * j];
        }
        float4 q = *(const float4*)&ws[w * 68 + wl];
        float2 c0v = make_float2(q.x, q.x), c1v = make_float2(q.y, q.y);
        float2 c2v = make_float2(q.z, q.z), c3v = make_float2(q.w, q.w);
#pragma unroll
        for (int j = 0; j < 3; j++) {
            a2[0][j] = ffma2(c0v, ev[j], a2[0][j]);
            a2[1][j] = ffma2(c1v, ov[j], a2[1][j]);
            a2[2][j] = ffma2(c2v, ev[j], a2[2][j]);
            a2[3][j] = ffma2(c3v, ov[j], a2[3][j]);
        }
    }
#pragma unroll
    for (int i = 0; i < 4; i++)
#pragma unroll
        for (int j = 0; j < 3; j++)
            *(float2*)&g_buf1[(long)(r0 + line * 64 + wl + i) * 96 + cc0 + 32 * j] = a2[i][j];
}

// ---------------- tau block body: 128 rows, 4x6 tile @ 512 threads ----------
__device__ __forceinline__ void tau_body(int blk, int tid, float* sm,
                                         const float* __restrict__ fe,
                                         const float* __restrict__ tb,
                                         float c0, float al) {
    float* xs = sm;               // [96][132]
    float* ws = sm + 12672;       // [96][96]
    int r0 = blk * 128;
    for (int i = tid; i < 12288; i += 512) {
        int r = i / 96, k = i - r * 96;
        xs[k * 132 + r] = fe[(long)(r0 + r) * 96 + k];
    }
    for (int i = tid; i < 2304; i += 512)
        *(float4*)&ws[i * 4] = *(const float4*)&g_twT[i * 4];
    __syncthreads();
    int ct = tid & 15, rt = tid >> 4;
    int rr0 = rt * 4, cc0 = 2 * ct;
    float2 acc[4][3];
#pragma unroll
    for (int i = 0; i < 4; i++)
#pragma unroll
        for (int j = 0; j < 3; j++) acc[i][j] = make_float2(0.f, 0.f);
#pragma unroll 4
    for (int k = 0; k < 96; k++) {
        float2 wv[3];
#pragma unroll
        for (int j = 0; j < 3; j++) wv[j] = *(const float2*)&ws[k * 96 + cc0 + 32 * j];
        float4 q0 = *(const float4*)&xs[k * 132 + rr0];
        float xr[4] = {q0.x, q0.y, q0.z, q0.w};
#pragma unroll
        for (int i = 0; i < 4; i++) {
            float2 xv = make_float2(xr[i], xr[i]);
#pragma unroll
            for (int j = 0; j < 3; j++) acc[i][j] = ffma2(xv, wv[j], acc[i][j]);
        }
    }
#pragma unroll
    for (int i = 0; i < 4; i++) {
#pragma unroll
        for (int j = 0; j < 3; j++) {
            int cc = cc0 + 32 * j;
            float2 v = acc[i][j];
            v.x += tb[cc]; v.y += tb[cc + 1];
            float2 Av, Bv;
            {
                float g = 0.5f * v.x * (1.f + erff(v.x * 0.70710678118654752f));
                float si, co; __sincosf(c0 * g, &si, &co);
                float damp = __expf(-0.5f * al * g);
                float so = si / (c0 + 1e-8f);
                Av.x = damp * (co + so * al * 0.5f); Bv.x = damp * so;
            }
            {
                float g = 0.5f * v.y * (1.f + erff(v.y * 0.70710678118654752f));
                float si, co; __sincosf(c0 * g, &si, &co);
                float damp = __expf(-0.5f * al * g);
                float so = si / (c0 + 1e-8f);
                Av.y = damp * (co + so * al * 0.5f); Bv.y = damp * so;
            }
            long idx = (long)(r0 + rr0 + i) * 96 + cc;
            *(float2*)&g_A[idx]  = Av;
            *(float2*)&g_Bc[idx] = Bv;
        }
    }
}

// ----- combined launch: 1024 lin blocks + 512 tau blocks, interleaved 2:1 ---
__global__ void __launch_bounds__(512, 2) k_lintau(const float* __restrict__ lb,
                                                   const float* __restrict__ fe,
                                                   const float* __restrict__ tbp,
                                                   const float* __restrict__ cp,
                                                   const float* __restrict__ ap) {
    extern __shared__ float sm[];
    int bid = blockIdx.x;            // 0..1535
    int grp = bid / 3, rem = bid - grp * 3;
    int tid = threadIdx.x;
    if (rem < 2) {
        lin_body(grp * 2 + rem, tid, sm, lb);
    } else {
        tau_body(grp, tid, sm, fe, tbp, cp[0], ap[0]);
    }
}

// ---------- forward DCT along H (symmetric): 2 W-columns per block ----------
__global__ void __launch_bounds__(256) k_dctHf(const float* __restrict__ in,
                                               float* __restrict__ out) {
    extern __shared__ float sm[];
    float* xs  = sm;             // [2][64][100] = 12800 (e/o halves)
    float* cfk = sm + 12800;     // [32][68]: cfk[w][n] = c64[n][w], w<32
    int tid = threadIdx.x;
    for (int i = tid; i < 2048; i += 256) cfk[(i >> 6) * 68 + (i & 63)] = g_c64T[i];
    int outer = blockIdx.x >> 5;
    int wpair = blockIdx.x & 31;
    long obase = (long)outer * TSTR;
    for (int i = tid; i < 1536; i += 256) {
        int s = i / 768, rem = i - s * 768;
        int k = rem / 24, c4 = rem - k * 24;         // k < 32
        long rb = obase + (wpair * 2 + s) * 96 + c4 * 4;
        float4 v1 = *(const float4*)&in[rb + k * 6144];
        float4 v2 = *(const float4*)&in[rb + (63 - k) * 6144];
        float4 e, o;
        e.x = v1.x + v2.x; e.y = v1.y + v2.y; e.z = v1.z + v2.z; e.w = v1.w + v2.w;
        o.x = v1.x - v2.x; o.y = v1.y - v2.y; o.z = v1.z - v2.z; o.w = v1.w - v2.w;
        *(float4*)&xs[(s * 64 + k) * 100 + c4 * 4] = e;
        *(float4*)&xs[(s * 64 + 63 - k) * 100 + c4 * 4] = o;
    }
    __syncthreads();
    int ct = tid & 15, rt = tid >> 4;
    int cc0 = 2 * ct;
    int slab = rt >> 3, n0 = (rt & 7) * 8;
    float2 acc[8][3];
#pragma unroll
    for (int i = 0; i < 8; i++)
#pragma unroll
        for (int j = 0; j < 3; j++) acc[i][j] = make_float2(0.f, 0.f);
#pragma unroll 4
    for (int k = 0; k < 32; k++) {
        float2 ev[3], ov[3];
#pragma unroll
        for (int j = 0; j < 3; j++) {
            ev[j] = *(const float2*)&xs[(slab * 64 + k) * 100 + cc0 + 32 * j];
            ov[j] = *(const float2*)&xs[(slab * 64 + 63 - k) * 100 + cc0 + 32 * j];
        }
        float4 q0 = *(const float4*)&cfk[k * 68 + n0];
        float4 q1 = *(const float4*)&cfk[k * 68 + n0 + 4];
        float cr[8] = {q0.x, q0.y, q0.z, q0.w, q1.x, q1.y, q1.z, q1.w};
#pragma unroll
        for (int i = 0; i < 8; i++) {
            float2 cv = make_float2(cr[i], cr[i]);
            float2* src = (i & 1) ? ov : ev;         // parity of n0+i = parity of i
#pragma unroll
            for (int j = 0; j < 3; j++) acc[i][j] = ffma2(cv, src[j], acc[i][j]);
        }
    }
    long sbase = obase + (wpair * 2 + slab) * 96;
#pragma unroll
    for (int i = 0; i < 8; i++)
#pragma unroll
        for (int j = 0; j < 3; j++)
            *(float2*)&out[sbase + (n0 + i) * 6144 + cc0 + 32 * j] = acc[i][j];
}

// ---------- inverse DCT along H (parity accum): 2 W-columns per block -------
__global__ void __launch_bounds__(256) k_dctHi(const float* __restrict__ in,
                                               float* __restrict__ out) {
    extern __shared__ float sm[];
    float* xs  = sm;             // [2][64][100] = 12800
    float* cik = sm + 12800;     // [64][36]: cik[n][w] = c64[n][w], w<32
    int tid = threadIdx.x;
    for (int i = tid; i < 2048; i += 256) {
        int n = i >> 5, w = i & 31;
        cik[n * 36 + w] = g_c64[n * 64 + w];
    }
    int outer = blockIdx.x >> 5;
    int wpair = blockIdx.x & 31;
    long obase = (long)outer * TSTR;
    for (int i = tid; i < 3072; i += 256) {
        int s = i / 1536, rem = i - s * 1536;
        int k = rem / 24, c4 = rem - k * 24;
        float4 v = *(const float4*)&in[obase + (wpair * 2 + s) * 96 + k * 6144 + c4 * 4];
        *(float4*)&xs[(s * 64 + k) * 100 + c4 * 4] = v;
    }
    __syncthreads();
    int ct = tid & 15, rt = tid >> 4;
    int cc0 = 2 * ct;
    int slab = rt >> 3, wu0 = (rt & 7) * 4;          // 4 w-units -> 8 outputs
    float2 E[4][3], O[4][3];
#pragma unroll
    for (int i = 0; i < 4; i++)
#pragma unroll
        for (int j = 0; j < 3; j++) { E[i][j] = make_float2(0.f, 0.f); O[i][j] = make_float2(0.f, 0.f); }
#pragma unroll 2
    for (int m = 0; m < 32; m++) {
        float2 se[3], so[3];
#pragma unroll
        for (int j = 0; j < 3; j++) {
            se[j] = *(const float2*)&xs[(slab * 64 + 2 * m) * 100 + cc0 + 32 * j];
            so[j] = *(const float2*)&xs[(slab * 64 + 2 * m + 1) * 100 + cc0 + 32 * j];
        }
        float4 qe = *(const float4*)&cik[(2 * m) * 36 + wu0];
        float4 qo = *(const float4*)&cik[(2 * m + 1) * 36 + wu0];
        float ce[4] = {qe.x, qe.y, qe.z, qe.w};
        float co[4] = {qo.x, qo.y, qo.z, qo.w};
#pragma unroll
        for (int i = 0; i < 4; i++) {
            float2 cev = make_float2(ce[i], ce[i]);
            float2 cov = make_float2(co[i], co[i]);
#pragma unroll
            for (int j = 0; j < 3; j++) {
                E[i][j] = ffma2(cev, se[j], E[i][j]);
                O[i][j] = ffma2(cov, so[j], O[i][j]);
            }
        }
    }
    long sbase = obase + (wpair * 2 + slab) * 96;
#pragma unroll
    for (int i = 0; i < 4; i++) {
        int w = wu0 + i;
#pragma unroll
        for (int j = 0; j < 3; j++) {
            float2 a, bq;
            a.x = E[i][j].x + O[i][j].x; a.y = E[i][j].y + O[i][j].y;
            bq.x = E[i][j].x - O[i][j].x; bq.y = E[i][j].y - O[i][j].y;
            *(float2*)&out[sbase + w * 6144 + cc0 + 32 * j] = a;
            *(float2*)&out[sbase + (63 - w) * 6144 + cc0 + 32 * j] = bq;
        }
    }
}

// ---- fused: DCT_T + v0 mix + spectral combine + IDCT_T, 4 hw/block ---------
__global__ void __launch_bounds__(256) k_fusedT(const float* __restrict__ in,
                                                float* __restrict__ out,
                                                const float* __restrict__ vb) {
    extern __shared__ float sm[];
    float* wsm = sm;             // [96][96] = 9216
    float* x16 = sm + 9216;      // [4][16][96] = 6144 (reused as vs)
    float* u0  = x16 + 6144;     // [64][100] = 6400
    float* cA  = u0 + 6400;      // [16][16]: cA[t][n] = c16[n][t]  (fwd)
    float* cC  = cA + 256;       // [16][16]: cC[n][t] = c16[n][t]  (inv)
    int tid = threadIdx.x;
    int b = blockIdx.x >> 10, hw0 = (blockIdx.x & 1023) * 4;
    for (int i = tid; i < 2304; i += 256)
        *(float4*)&wsm[i * 4] = *(const float4*)&g_vwT[i * 4];
    cA[tid] = g_c16T[tid];
    cC[tid] = g_c16[tid];
    for (int i = tid; i < 1536; i += 256) {
        int s = i / 384, rem = i - s * 384;
        int t = rem / 24, c4 = rem - t * 24;
        *(float4*)&x16[(s * 16 + t) * 96 + c4 * 4] =
            *(const float4*)&in[(long)b * BSTR + (hw0 + s) * 96 + t * TSTR + c4 * 4];
    }
    __syncthreads();
    int ct = tid & 15, rt = tid >> 4;
    int cc0 = 2 * ct;
    int slab = rt >> 2, q4 = (rt & 3) * 4;   // rows within slab
    int hw = hw0 + slab;
    // ---- phase A: forward DCT along T (4 freq rows x 6 ch) ----
    {
        float2 a[4][3];
#pragma unroll
        for (int i = 0; i < 4; i++)
#pragma unroll
            for (int j = 0; j < 3; j++) a[i][j] = make_float2(0.f, 0.f);
#pragma unroll
        for (int t = 0; t < 16; t++) {
            float2 xv[3];
#pragma unroll
            for (int j = 0; j < 3; j++)
                xv[j] = *(const float2*)&x16[(slab * 16 + t) * 96 + cc0 + 32 * j];
            float4 q = *(const float4*)&cA[t * 16 + q4];
            float cr[4] = {q.x, q.y, q.z, q.w};
#pragma unroll
            for (int i = 0; i < 4; i++) {
                float2 cv = make_float2(cr[i], cr[i]);
#pragma unroll
                for (int j = 0; j < 3; j++) a[i][j] = ffma2(cv, xv[j], a[i][j]);
            }
        }
#pragma unroll
        for (int i = 0; i < 4; i++)
#pragma unroll
            for (int j = 0; j < 3; j++)
                *(float2*)&u0[(slab * 16 + q4 + i) * 100 + cc0 + 32 * j] = a[i][j];
    }
    __syncthreads();
    // ---- phase B: v0 mix + spectral combine -> vs (x16 region) ----
    {
        float2 Av[4][3], Bv[4][3];
#pragma unroll
        for (int i = 0; i < 4; i++)
#pragma unroll
            for (int j = 0; j < 3; j++) {
                long gi = ((long)(q4 + i) * 4096 + hw) * 96 + cc0 + 32 * j;
                Av[i][j] = *(const float2*)&g_A[gi];
                Bv[i][j] = *(const float2*)&g_Bc[gi];
            }
        float2 v[4][3];
#pragma unroll
        for (int i = 0; i < 4; i++)
#pragma unroll
            for (int j = 0; j < 3; j++) v[i][j] = make_float2(0.f, 0.f);
#pragma unroll 4
        for (int k = 0; k < 96; k++) {
            float2 wv[3];
#pragma unroll
            for (int j = 0; j < 3; j++) wv[j] = *(const float2*)&wsm[k * 96 + cc0 + 32 * j];
#pragma unroll
            for (int i = 0; i < 4; i++) {
                float u1 = u0[(slab * 16 + q4 + i) * 100 + k];
                float2 uv = make_float2(u1, u1);
#pragma unroll
                for (int j = 0; j < 3; j++) v[i][j] = ffma2(uv, wv[j], v[i][j]);
            }
        }
        if (hw0 == 0 && rt == 0) {   // DC (t=0,h=0,w=0) of constant v0_b field
#pragma unroll
            for (int j = 0; j < 3; j++) {
                v[0][j].x += 256.f * vb[cc0 + 32 * j];
                v[0][j].y += 256.f * vb[cc0 + 32 * j + 1];
            }
        }
        __syncthreads();   // u0 reads done by all; x16 region becomes vs
#pragma unroll
        for (int i = 0; i < 4; i++)
#pragma unroll
            for (int j = 0; j < 3; j++) {
                float2 uu = *(const float2*)&u0[(slab * 16 + q4 + i) * 100 + cc0 + 32 * j];
                float2 r;
                r.x = Av[i][j].x * uu.x + Bv[i][j].x * v[i][j].x;
                r.y = Av[i][j].y * uu.y + Bv[i][j].y * v[i][j].y;
                *(float2*)&x16[(slab * 16 + q4 + i) * 96 + cc0 + 32 * j] = r;
            }
    }
    __syncthreads();
    // ---- phase C: inverse DCT along T (4 time rows x 6 ch) ----
    {
        float2 y[4][3];
#pragma unroll
        for (int i = 0; i < 4; i++)
#pragma unroll
            for (int j = 0; j < 3; j++) y[i][j] = make_float2(0.f, 0.f);
#pragma unroll
        for (int n = 0; n < 16; n++) {
            float2 sv[3];
#pragma unroll
            for (int j = 0; j < 3; j++)
                sv[j] = *(const float2*)&x16[(slab * 16 + n) * 96 + cc0 + 32 * j];
            float4 q = *(const float4*)&cC[n * 16 + q4];
            float cr[4] = {q.x, q.y, q.z, q.w};
#pragma unroll
            for (int i = 0; i < 4; i++) {
                float2 cv = make_float2(cr[i], cr[i]);
#pragma unroll
                for (int j = 0; j < 3; j++) y[i][j] = ffma2(cv, sv[j], y[i][j]);
            }
        }
#pragma unroll
        for (int i = 0; i < 4; i++)
#pragma unroll
            for (int j = 0; j < 3; j++)
                *(float2*)&out[(long)b * BSTR + hw * 96 + (q4 + i) * TSTR + cc0 + 32 * j] = y[i][j];
    }
}

// ---- final: IDCT_W(sym) + LN + gate + out GEMM + transpose store -----------
__global__ void __launch_bounds__(256) k_final(const float* __restrict__ lg,
                                               const float* __restrict__ lbt,
                                               const float* __restrict__ ob,
                                               float* __restrict__ outp) {
    extern __shared__ float sm[];
    float* s   = sm;             // [128][100] = 12800 (freq -> spatial/LN'd -> os)
    float* cik = sm + 12800;     // [64][36]: cik[n][w] = c64[n][w], w<32
    float* ws  = cik + 2304;     // [96][96] = 9216
    float* os  = sm;             // reuse s: [96][130] = 12480
    int tid = threadIdx.x;
    int r0 = blockIdx.x * 128;
    int b = r0 >> 16, thw0 = r0 & 65535;
    for (int i = tid; i < 3072; i += 256) {
        int n = i / 24, c4 = i - n * 24;
        *(float4*)&s[n * 100 + c4 * 4] =
            *(const float4*)&g_buf3[(long)r0 * 96 + n * 96 + c4 * 4];
    }
    for (int i = tid; i < 2048; i += 256) {
        int n = i >> 5, w = i & 31;
        cik[n * 36 + w] = g_c64[n * 64 + w];
    }
    for (int i = tid; i < 2304; i += 256)
        *(float4*)&ws[i * 4] = *(const float4*)&g_owT[i * 4];
    __syncthreads();
    int ct = tid & 15, rt = tid >> 4;
    int cc0 = 2 * ct;
    int line = rt >> 3, wu0 = (rt & 7) * 4;
    // IDCT along W (parity accumulation): x[w]=E+O, x[63-w]=E-O
    float2 E[4][3], O[4][3];
#pragma unroll
    for (int i = 0; i < 4; i++)
#pragma unroll
        for (int j = 0; j < 3; j++) { E[i][j] = make_float2(0.f, 0.f); O[i][j] = make_float2(0.f, 0.f); }
#pragma unroll 2
    for (int m = 0; m < 32; m++) {
        float2 se[3], so[3];
#pragma unroll
        for (int j = 0; j < 3; j++) {
            se[j] = *(const float2*)&s[(line * 64 + 2 * m) * 100 + cc0 + 32 * j];
            so[j] = *(const float2*)&s[(line * 64 + 2 * m + 1) * 100 + cc0 + 32 * j];
        }
        float4 qe = *(const float4*)&cik[(2 * m) * 36 + wu0];
        float4 qo = *(const float4*)&cik[(2 * m + 1) * 36 + wu0];
        float ce[4] = {qe.x, qe.y, qe.z, qe.w};
        float co[4] = {qo.x, qo.y, qo.z, qo.w};
#pragma unroll
        for (int i = 0; i < 4; i++) {
            float2 cev = make_float2(ce[i], ce[i]);
            float2 cov = make_float2(co[i], co[i]);
#pragma unroll
            for (int j = 0; j < 3; j++) {
                E[i][j] = ffma2(cev, se[j], E[i][j]);
                O[i][j] = ffma2(cov, so[j], O[i][j]);
            }
        }
    }
    __syncthreads();
#pragma unroll
    for (int i = 0; i < 4; i++) {
        int w = wu0 + i;
#pragma unroll
        for (int j = 0; j < 3; j++) {
            float2 a, bq;
            a.x = E[i][j].x + O[i][j].x; a.y = E[i][j].y + O[i][j].y;
            bq.x = E[i][j].x - O[i][j].x; bq.y = E[i][j].y - O[i][j].y;
            *(float2*)&s[(line * 64 + w) * 100 + cc0 + 32 * j] = a;
            *(float2*)&s[(line * 64 + 63 - w) * 100 + cc0 + 32 * j] = bq;
        }
    }
    __syncthreads();
    // LayerNorm + gate in place; 8 warps x 16 rows
    {
        int wp = tid >> 5, lane = tid & 31;
        float g0 = lg[lane], g1 = lg[lane + 32], g2 = lg[lane + 64];
        float b0 = lbt[lane], b1 = lbt[lane + 32], b2 = lbt[lane + 64];
#pragma unroll
        for (int rr = 0; rr < 16; rr++) {
            int w = wp * 16 + rr;
            float x0 = s[w * 100 + lane], x1 = s[w * 100 + lane + 32], x2 = s[w * 100 + lane + 64];
            float sum = x0 + x1 + x2, q = x0 * x0 + x1 * x1 + x2 * x2;
#pragma unroll
            for (int o = 16; o > 0; o >>= 1) {
                sum += __shfl_xor_sync(0xffffffffu, sum, o);
                q   += __shfl_xor_sync(0xffffffffu, q, o);
            }
            float mean = sum * (1.f / 96.f);
            float var = q * (1.f / 96.f) - mean * mean;
            float rstd = rsqrtf(var + 1e-5f);
            long gr = (long)(r0 + w) * 96;
            s[w * 100 + lane]      = ((x0 - mean) * rstd * g0 + b0) * g_buf2[gr + lane];
            s[w * 100 + lane + 32] = ((x1 - mean) * rstd * g1 + b1) * g_buf2[gr + lane + 32];
            s[w * 100 + lane + 64] = ((x2 - mean) * rstd * g2 + b2) * g_buf2[gr + lane + 64];
        }
    }
    __syncthreads();
    // out GEMM: 8 rows x 6 cols per thread (scalar broadcast row loads)
    int rr0 = rt * 8;
    float2 acc[8][3];
#pragma unroll
    for (int i = 0; i < 8; i++)
#pragma unroll
        for (int j = 0; j < 3; j++) acc[i][j] = make_float2(0.f, 0.f);
#pragma unroll 4
    for (int k = 0; k < 96; k++) {
        float2 wv[3];
#pragma unroll
        for (int j = 0; j < 3; j++) wv[j] = *(const float2*)&ws[k * 96 + cc0 + 32 * j];
#pragma unroll
        for (int i = 0; i < 8; i++) {
            float x1 = s[(rr0 + i) * 100 + k];
            float2 xv = make_float2(x1, x1);
#pragma unroll
            for (int j = 0; j < 3; j++) acc[i][j] = ffma2(xv, wv[j], acc[i][j]);
        }
    }
    float2 obv[3];
#pragma unroll
    for (int j = 0; j < 3; j++) obv[j] = *(const float2*)&ob[cc0 + 32 * j];
    __syncthreads();           // GEMM reads of s done; reuse as os
#pragma unroll
    for (int i = 0; i < 8; i++)
#pragma unroll
        for (int j = 0; j < 3; j++) {
            int cc = cc0 + 32 * j;
            os[cc * 130 + rr0 + i]       = acc[i][j].x + obv[j].x;
            os[(cc + 1) * 130 + rr0 + i] = acc[i][j].y + obv[j].y;
        }
    __syncthreads();
    for (int i = tid; i < 12288; i += 256) {
        int cc = i >> 7, w = i & 127;
        outp[(long)b * BSTR + cc * 65536 + thw0 + w] = os[cc * 130 + w];
    }
}

extern "C" void kernel_launch(void* const* d_in, const int* in_sizes, int n_in,
                              void* d_out, int out_size) {
    const float* x   = (const float*)d_in[0];
    const float* fe  = (const float*)d_in[1];
    const float* dww = (const float*)d_in[2];
    const float* dwb = (const float*)d_in[3];
    const float* lw  = (const float*)d_in[4];
    const float* lb  = (const float*)d_in[5];
    const float* vw  = (const float*)d_in[6];
    const float* vb  = (const float*)d_in[7];
    const float* tw  = (const float*)d_in[8];
    const float* tb  = (const float*)d_in[9];
    const float* cc  = (const float*)d_in[10];
    const float* al  = (const float*)d_in[11];
    const float* lg  = (const float*)d_in[12];
    const float* lbt = (const float*)d_in[13];
    const float* ow  = (const float*)d_in[14];
    const float* ob  = (const float*)d_in[15];
    float* outp = (float*)d_out;

    size_t smCnv = (size_t)(6 * 34 * 66) * 4;           //  53856
    size_t smLT  = (size_t)(12672 + 9600) * 4;          //  89088 (max of lin/tau)
    size_t smHf  = (size_t)(12800 + 2176) * 4;          //  59904
    size_t smHi  = (size_t)(12800 + 2304) * 4;          //  60416
    size_t smFus = (size_t)(9216 + 6144 + 6400 + 512) * 4; // 89088
    size_t smFin = (size_t)(12800 + 2304 + 9216) * 4;   //  97280
    cudaFuncSetAttribute(k_conv,   cudaFuncAttributeMaxDynamicSharedMemorySize, (int)smCnv);
    cudaFuncSetAttribute(k_lintau, cudaFuncAttributeMaxDynamicSharedMemorySize, (int)smLT);
    cudaFuncSetAttribute(k_dctHf,  cudaFuncAttributeMaxDynamicSharedMemorySize, (int)smHf);
    cudaFuncSetAttribute(k_dctHi,  cudaFuncAttributeMaxDynamicSharedMemorySize, (int)smHi);
    cudaFuncSetAttribute(k_fusedT, cudaFuncAttributeMaxDynamicSharedMemorySize, (int)smFus);
    cudaFuncSetAttribute(k_final,  cudaFuncAttributeMaxDynamicSharedMemorySize, (int)smFin);

    float *b1, *b3;
    cudaGetSymbolAddress((void**)&b1, g_buf1);
    cudaGetSymbolAddress((void**)&b3, g_buf3);

    k_init<<<181, 256>>>(lw, tw, vw, ow);
    k_conv<<<dim3(2, 4, 192), 256, smCnv>>>(x, dww, dwb);
    k_lintau<<<1536, 512, smLT>>>(lb, fe, tb, cc, al); // lin + tau concurrent
    k_dctHf<<<1024, 256, smHf>>>(b1, b3);              // DCT along H -> buf3
    k_fusedT<<<2048, 256, smFus>>>(b3, b1, vb);        // DCT_T + mix + IDCT_T -> buf1
    k_dctHi<<<1024, 256, smHi>>>(b1, b3);              // IDCT along H -> buf3
    k_final<<<1024, 256, smFin>>>(lg, lbt, ob, outp);  // IDCT_W + LN + gate + GEMM
}